// round 1
// baseline (speedup 1.0000x reference)
#include <cuda_runtime.h>
#include <math.h>

// Problem constants (fixed shapes for this problem)
#define BATCH 32
#define NN    1024
#define DD    128
#define ROWS  (BATCH * NN)   // 32768

// Scratch (device globals — no allocation allowed)
__device__ float g_t [ROWS * DD];   // tangent vectors
__device__ float g_m [ROWS * DD];   // message m
__device__ float g_m2[ROWS * DD];   // m @ W_agg  (reassociated)

// ---------------------------------------------------------------------------
// Composite per-row scale: logmap0( proj( expmap0(h) ) ) = s(||h||) * h
// Faithfully follows the reference clipping order (EPS=1e-7, MAX_NORM=1-1e-5, c=1)
// ---------------------------------------------------------------------------
__device__ __forceinline__ float hyp_scale(float n) {
    const float EPS  = 1e-7f;
    const float MAXN = 1.0f - 1e-5f;
    float n1 = fmaxf(n, EPS);
    float r  = tanhf(n1) / n1;          // expmap0:  x = r * h
    float xn = r * n;                   // ||x||
    float n2 = fmaxf(xn, EPS);
    float s2 = (n2 > MAXN) ? (MAXN / n2) : 1.0f;   // proj: x' = s2 * x
    float x2 = s2 * xn;                 // ||x'||
    float n3 = fmaxf(x2, EPS);
    float z  = fminf(n3, 1.0f - EPS);   // _artanh clip (n3 > 0 already)
    float lg = atanhf(z) / n3;          // logmap0: t = lg * x'
    return r * s2 * lg;
}

// ---------------------------------------------------------------------------
// Small GEMM:  out[r, j] = sum_k X[r,k] * W(k,j) (+ bias[j]), 128x128 weights.
//   TRANSW=true  -> W stored [j,k]  (X @ W^T)
//   TRANSW=false -> W stored [k,j]  (X @ W)
//   EPI: 0 = store, 1 = hyperbolic row rescale, 2 = multiply by mask[r]
// Tiling: BM=64, BN=128 (full width), BK=8; 256 threads (32x8); TM=8, TN=4.
// ---------------------------------------------------------------------------
template<bool TRANSW, int EPI>
__global__ void __launch_bounds__(256) gemm_small(
    const float* __restrict__ X, const float* __restrict__ W,
    const float* __restrict__ bias, const float* __restrict__ mask,
    float* __restrict__ out)
{
    __shared__ float Xs[8][64];
    __shared__ float Ws[8][128];

    const int tid  = threadIdx.x;
    const int tx   = tid & 31;          // 32 column groups x 4 cols
    const int ty   = tid >> 5;          // 8  row groups   x 8 rows
    const int row0 = blockIdx.x * 64;

    float acc[8][4];
    #pragma unroll
    for (int i = 0; i < 8; i++)
        #pragma unroll
        for (int j = 0; j < 4; j++) acc[i][j] = 0.f;

    for (int k0 = 0; k0 < DD; k0 += 8) {
        // X tile: 64 x 8 = 512 floats -> one float2 per thread
        {
            int m  = tid >> 2;
            int kk = (tid & 3) * 2;
            float2 v = *(const float2*)&X[(size_t)(row0 + m) * DD + k0 + kk];
            Xs[kk    ][m] = v.x;
            Xs[kk + 1][m] = v.y;
        }
        // W tile: 8 x 128 = 1024 floats -> 4 scalars per thread
        #pragma unroll
        for (int i = 0; i < 4; i++) {
            int idx = tid + i * 256;
            if (TRANSW) {
                int n = idx >> 3, kk = idx & 7;
                Ws[kk][n] = W[(size_t)n * DD + k0 + kk];
            } else {
                int kk = idx >> 7, n = idx & 127;
                Ws[kk][n] = W[(size_t)(k0 + kk) * DD + n];
            }
        }
        __syncthreads();
        #pragma unroll
        for (int kk = 0; kk < 8; kk++) {
            float4 x0 = *(const float4*)&Xs[kk][ty * 8];
            float4 x1 = *(const float4*)&Xs[kk][ty * 8 + 4];
            float4 w0 = *(const float4*)&Ws[kk][tx * 4];
            float xr[8] = {x0.x, x0.y, x0.z, x0.w, x1.x, x1.y, x1.z, x1.w};
            float wc[4] = {w0.x, w0.y, w0.z, w0.w};
            #pragma unroll
            for (int i = 0; i < 8; i++)
                #pragma unroll
                for (int j = 0; j < 4; j++)
                    acc[i][j] = fmaf(xr[i], wc[j], acc[i][j]);
        }
        __syncthreads();
    }

    float bv[4] = {0.f, 0.f, 0.f, 0.f};
    if (bias) {
        float4 b4 = *(const float4*)&bias[tx * 4];
        bv[0] = b4.x; bv[1] = b4.y; bv[2] = b4.z; bv[3] = b4.w;
    }

    #pragma unroll
    for (int i = 0; i < 8; i++) {
        int r = row0 + ty * 8 + i;
        float v[4];
        #pragma unroll
        for (int j = 0; j < 4; j++) v[j] = acc[i][j] + bv[j];

        if (EPI == 1) {
            // full row (128 cols) lives in this warp: 32 lanes x 4 cols
            float ss = v[0]*v[0] + v[1]*v[1] + v[2]*v[2] + v[3]*v[3];
            #pragma unroll
            for (int o = 16; o > 0; o >>= 1)
                ss += __shfl_xor_sync(0xffffffffu, ss, o);
            float s = hyp_scale(sqrtf(ss));
            #pragma unroll
            for (int j = 0; j < 4; j++) v[j] *= s;
        } else if (EPI == 2) {
            float s = mask[r];
            #pragma unroll
            for (int j = 0; j < 4; j++) v[j] *= s;
        }
        *(float4*)&out[(size_t)r * DD + tx * 4] = make_float4(v[0], v[1], v[2], v[3]);
    }
}

// ---------------------------------------------------------------------------
// Big GEMM (dominant): per batch b,
//   raw  = A_b[1024,1024] @ M2_b[1024,128]
//   t    = relu(M_b + raw + b_agg)
//   T_b  = hyp_rows(t)                      (fused proj/expmap0/logmap0)
// Tiling: BM=128, BN=128 (full width), BK=16; 256 threads (16x16); TM=TN=8.
// ---------------------------------------------------------------------------
__global__ void __launch_bounds__(256) agg_gemm(
    const float* __restrict__ A, const float* __restrict__ M2,
    const float* __restrict__ M, const float* __restrict__ bagg,
    float* __restrict__ T)
{
    __shared__ float As[16][128];   // A tile transposed: [k][m]
    __shared__ float Bs[16][128];   // M2 tile:           [k][n]

    const int tid  = threadIdx.x;
    const int tx   = tid & 15;      // 16 col groups x 8 cols
    const int ty   = tid >> 4;      // 16 row groups x 8 rows
    const int b    = blockIdx.y;
    const int row0 = blockIdx.x * 128;

    const float* Ab  = A  + (size_t)b * NN * NN;
    const float* M2b = M2 + (size_t)b * NN * DD;
    const float* Mb  = M  + (size_t)b * NN * DD;
    float*       Tb  = T  + (size_t)b * NN * DD;

    float acc[8][8];
    #pragma unroll
    for (int i = 0; i < 8; i++)
        #pragma unroll
        for (int j = 0; j < 8; j++) acc[i][j] = 0.f;

    for (int k0 = 0; k0 < NN; k0 += 16) {
        // A tile: 128 rows x 16 k = 512 float4 -> 2 per thread (store transposed)
        #pragma unroll
        for (int i = 0; i < 2; i++) {
            int idx = tid + i * 256;
            int m   = idx >> 2;
            int kq  = (idx & 3) * 4;
            float4 v = *(const float4*)&Ab[(size_t)(row0 + m) * NN + k0 + kq];
            As[kq    ][m] = v.x;
            As[kq + 1][m] = v.y;
            As[kq + 2][m] = v.z;
            As[kq + 3][m] = v.w;
        }
        // M2 tile: 16 k x 128 n = 512 float4 -> 2 per thread (coalesced)
        #pragma unroll
        for (int i = 0; i < 2; i++) {
            int idx = tid + i * 256;
            int kk  = idx >> 5;
            int nq  = (idx & 31) * 4;
            *(float4*)&Bs[kk][nq] = *(const float4*)&M2b[(size_t)(k0 + kk) * DD + nq];
        }
        __syncthreads();
        #pragma unroll
        for (int kk = 0; kk < 16; kk++) {
            float ar[8], br[8];
            *(float4*)&ar[0] = *(const float4*)&As[kk][ty * 8];
            *(float4*)&ar[4] = *(const float4*)&As[kk][ty * 8 + 4];
            *(float4*)&br[0] = *(const float4*)&Bs[kk][tx * 8];
            *(float4*)&br[4] = *(const float4*)&Bs[kk][tx * 8 + 4];
            #pragma unroll
            for (int i = 0; i < 8; i++)
                #pragma unroll
                for (int j = 0; j < 8; j++)
                    acc[i][j] = fmaf(ar[i], br[j], acc[i][j]);
        }
        __syncthreads();
    }

    // Epilogue: t = relu(m + raw + b_agg); hyperbolic rescale per row.
    float bv[8];
    {
        float4 b0 = *(const float4*)&bagg[tx * 8];
        float4 b1 = *(const float4*)&bagg[tx * 8 + 4];
        bv[0]=b0.x; bv[1]=b0.y; bv[2]=b0.z; bv[3]=b0.w;
        bv[4]=b1.x; bv[5]=b1.y; bv[6]=b1.z; bv[7]=b1.w;
    }
    #pragma unroll
    for (int i = 0; i < 8; i++) {
        int r = row0 + ty * 8 + i;
        float mv[8];
        float4 m0 = *(const float4*)&Mb[(size_t)r * DD + tx * 8];
        float4 m1 = *(const float4*)&Mb[(size_t)r * DD + tx * 8 + 4];
        mv[0]=m0.x; mv[1]=m0.y; mv[2]=m0.z; mv[3]=m0.w;
        mv[4]=m1.x; mv[5]=m1.y; mv[6]=m1.z; mv[7]=m1.w;

        float ss = 0.f;
        #pragma unroll
        for (int j = 0; j < 8; j++) {
            float v = fmaxf(acc[i][j] + mv[j] + bv[j], 0.f);
            acc[i][j] = v;
            ss = fmaf(v, v, ss);
        }
        // row spread across 16 lanes (tx) within a half-warp
        #pragma unroll
        for (int o = 8; o > 0; o >>= 1)
            ss += __shfl_xor_sync(0xffffffffu, ss, o);

        float s = hyp_scale(sqrtf(ss));
        #pragma unroll
        for (int j = 0; j < 8; j++) acc[i][j] *= s;

        *(float4*)&Tb[(size_t)r * DD + tx * 8] =
            make_float4(acc[i][0], acc[i][1], acc[i][2], acc[i][3]);
        *(float4*)&Tb[(size_t)r * DD + tx * 8 + 4] =
            make_float4(acc[i][4], acc[i][5], acc[i][6], acc[i][7]);
    }
}

// ---------------------------------------------------------------------------
// Launch: embed -> 2 x (msg, m@W_agg, big agg GEMM) -> final projection
// ---------------------------------------------------------------------------
extern "C" void kernel_launch(void* const* d_in, const int* in_sizes, int n_in,
                              void* d_out, int out_size)
{
    const float* nf    = (const float*)d_in[0];  // [32,1024,128]
    const float* adj   = (const float*)d_in[1];  // [32,1024,1024]
    const float* mask  = (const float*)d_in[2];  // [32,1024,1]
    const float* Wemb  = (const float*)d_in[3];  // [128,128] (h,d)
    const float* Wmsg  = (const float*)d_in[4];  // [2,128,128]
    const float* bmsg  = (const float*)d_in[5];  // [2,128]
    const float* Wagg  = (const float*)d_in[6];  // [2,128,128]
    const float* bagg  = (const float*)d_in[7];  // [2,128]
    const float* Wproj = (const float*)d_in[8];  // [128,128]
    const float* bproj = (const float*)d_in[9];  // [128]
    float* out = (float*)d_out;

    float *t, *m, *m2;
    cudaGetSymbolAddress((void**)&t,  g_t);
    cudaGetSymbolAddress((void**)&m,  g_m);
    cudaGetSymbolAddress((void**)&m2, g_m2);

    dim3 gsmall(ROWS / 64);           // 512 blocks
    dim3 gbig(NN / 128, BATCH);       // 8 x 32 blocks

    // embed: h = nf @ Wemb^T; t = logmap0(proj(expmap0(h)))
    gemm_small<true, 1><<<gsmall, 256>>>(nf, Wemb, nullptr, nullptr, t);

    for (int l = 0; l < 2; l++) {
        // m = t @ Wmsg[l] + bmsg[l]
        gemm_small<false, 0><<<gsmall, 256>>>(t, Wmsg + l * DD * DD,
                                              bmsg + l * DD, nullptr, m);
        // m2 = m @ Wagg[l]          (reassociation: (A@m)@Wagg = A@(m@Wagg))
        gemm_small<false, 0><<<gsmall, 256>>>(m, Wagg + l * DD * DD,
                                              nullptr, nullptr, m2);
        // t = hyp_rows(relu(m + A@m2 + bagg[l]))
        agg_gemm<<<gbig, 256>>>(adj, m2, m, bagg + l * DD, t);
    }

    // out = (t @ Wproj^T + bproj) * mask
    gemm_small<true, 2><<<gsmall, 256>>>(t, Wproj, bproj, mask, out);
}

// round 3
// speedup vs baseline: 1.4284x; 1.4284x over previous
#include <cuda_runtime.h>
#include <math.h>
#include <stdint.h>

// Problem constants
#define BATCH 32
#define NN    1024
#define DD    128
#define ROWS  (BATCH * NN)   // 32768

// Scratch (device globals — no allocation allowed)
__device__ float g_t[ROWS * DD];
__device__ float g_m[ROWS * DD];
__device__ __align__(16) uint16_t g_ah[(size_t)BATCH * NN * NN];   // adj bf16 hi (64MB)
__device__ __align__(16) uint16_t g_al[(size_t)BATCH * NN * NN];   // adj bf16 lo (64MB)
__device__ __align__(16) uint16_t g_m2h[(size_t)BATCH * DD * NN];  // m2^T bf16 hi [b][n][k]
__device__ __align__(16) uint16_t g_m2l[(size_t)BATCH * DD * NN];  // m2^T bf16 lo

// ---------------------------------------------------------------------------
// Helpers
// ---------------------------------------------------------------------------
__device__ __forceinline__ uint32_t smem_u32(const void* p) {
    uint32_t a;
    asm("{ .reg .u64 t; cvta.to.shared.u64 t, %1; cvt.u32.u64 %0, t; }" : "=r"(a) : "l"(p));
    return a;
}
__device__ __forceinline__ uint32_t lds_u32(uint32_t addr) {
    uint32_t v;
    asm volatile("ld.shared.b32 %0, [%1];" : "=r"(v) : "r"(addr));
    return v;
}
// pack {lo=bf16(v0), hi=bf16(v1)}
__device__ __forceinline__ uint32_t pack_bf16x2(float v0, float v1) {
    uint32_t r;
    asm("cvt.rn.bf16x2.f32 %0, %1, %2;" : "=r"(r) : "f"(v1), "f"(v0));
    return r;
}
// split two floats into bf16x2 hi + bf16x2 residual
__device__ __forceinline__ void split2(float v0, float v1, uint32_t& h, uint32_t& l) {
    h = pack_bf16x2(v0, v1);
    float r0 = v0 - __uint_as_float(h << 16);
    float r1 = v1 - __uint_as_float(h & 0xffff0000u);
    l = pack_bf16x2(r0, r1);
}
#define CP16(dst, src) \
    asm volatile("cp.async.cg.shared.global [%0], [%1], 16;" :: "r"(dst), "l"(src) : "memory")

__device__ __forceinline__ void mma_bf16(float d[4], const uint32_t a[4],
                                         uint32_t b0, uint32_t b1) {
    asm volatile(
        "mma.sync.aligned.m16n8k16.row.col.f32.bf16.bf16.f32 "
        "{%0,%1,%2,%3}, {%4,%5,%6,%7}, {%8,%9}, {%0,%1,%2,%3};"
        : "+f"(d[0]), "+f"(d[1]), "+f"(d[2]), "+f"(d[3])
        : "r"(a[0]), "r"(a[1]), "r"(a[2]), "r"(a[3]), "r"(b0), "r"(b1));
}

// Composite per-row scale: logmap0(proj(expmap0(h))) = s(||h||) * h
__device__ __forceinline__ float hyp_scale(float n) {
    const float EPS  = 1e-7f;
    const float MAXN = 1.0f - 1e-5f;
    float n1 = fmaxf(n, EPS);
    float r  = tanhf(n1) / n1;
    float xn = r * n;
    float n2 = fmaxf(xn, EPS);
    float s2 = (n2 > MAXN) ? (MAXN / n2) : 1.0f;
    float x2 = s2 * xn;
    float n3 = fmaxf(x2, EPS);
    float z  = fminf(n3, 1.0f - EPS);
    float lg = atanhf(z) / n3;
    return r * s2 * lg;
}

// ---------------------------------------------------------------------------
// One-time adjacency split: fp32 -> bf16 hi/lo
// ---------------------------------------------------------------------------
__global__ void __launch_bounds__(256) split_adj(const float4* __restrict__ a,
                                                 uint2* __restrict__ h,
                                                 uint2* __restrict__ l) {
    int i = blockIdx.x * 256 + threadIdx.x;
    float4 v = a[i];
    uint32_t h0, l0, h1, l1;
    split2(v.x, v.y, h0, l0);
    split2(v.z, v.w, h1, l1);
    h[i] = make_uint2(h0, h1);
    l[i] = make_uint2(l0, l1);
}

// ---------------------------------------------------------------------------
// Small GEMM (SIMT):  out[r, j] = sum_k X[r,k] * W(k,j) (+ bias[j])
//   EPI: 0 = store, 1 = hyperbolic rescale, 2 = mask, 3 = m2^T bf16-split
// ---------------------------------------------------------------------------
template<bool TRANSW, int EPI>
__global__ void __launch_bounds__(256) gemm_small(
    const float* __restrict__ X, const float* __restrict__ W,
    const float* __restrict__ bias, const float* __restrict__ mask,
    float* __restrict__ out, float* __restrict__ out2)
{
    __shared__ float Xs[8][64];
    __shared__ float Ws[8][128];

    const int tid  = threadIdx.x;
    const int tx   = tid & 31;
    const int ty   = tid >> 5;
    const int row0 = blockIdx.x * 64;

    float acc[8][4];
    #pragma unroll
    for (int i = 0; i < 8; i++)
        #pragma unroll
        for (int j = 0; j < 4; j++) acc[i][j] = 0.f;

    for (int k0 = 0; k0 < DD; k0 += 8) {
        {
            int m  = tid >> 2;
            int kk = (tid & 3) * 2;
            float2 v = *(const float2*)&X[(size_t)(row0 + m) * DD + k0 + kk];
            Xs[kk][m] = v.x;
            Xs[kk + 1][m] = v.y;
        }
        #pragma unroll
        for (int i = 0; i < 4; i++) {
            int idx = tid + i * 256;
            if (TRANSW) {
                int n = idx >> 3, kk = idx & 7;
                Ws[kk][n] = W[(size_t)n * DD + k0 + kk];
            } else {
                int kk = idx >> 7, n = idx & 127;
                Ws[kk][n] = W[(size_t)(k0 + kk) * DD + n];
            }
        }
        __syncthreads();
        #pragma unroll
        for (int kk = 0; kk < 8; kk++) {
            float4 x0 = *(const float4*)&Xs[kk][ty * 8];
            float4 x1 = *(const float4*)&Xs[kk][ty * 8 + 4];
            float4 w0 = *(const float4*)&Ws[kk][tx * 4];
            float xr[8] = {x0.x, x0.y, x0.z, x0.w, x1.x, x1.y, x1.z, x1.w};
            float wc[4] = {w0.x, w0.y, w0.z, w0.w};
            #pragma unroll
            for (int i = 0; i < 8; i++)
                #pragma unroll
                for (int j = 0; j < 4; j++)
                    acc[i][j] = fmaf(xr[i], wc[j], acc[i][j]);
        }
        __syncthreads();
    }

    if constexpr (EPI == 3) {
        // Stage fp32, then write m2^T [b][n][k] as bf16 hi/lo.
        __shared__ float stg[64 * 129];
        const int bb = row0 >> 10;
        const int k0 = row0 & 1023;
        #pragma unroll
        for (int i = 0; i < 8; i++)
            #pragma unroll
            for (int j = 0; j < 4; j++)
                stg[(ty * 8 + i) * 129 + tx * 4 + j] = acc[i][j];
        __syncthreads();
        uint16_t* oh = (uint16_t*)out;
        uint16_t* ol = (uint16_t*)out2;
        #pragma unroll
        for (int it = 0; it < 4; it++) {
            int idx = tid + it * 256;
            int n   = idx >> 3;
            int kq  = (idx & 7) * 8;
            float v[8];
            #pragma unroll
            for (int q = 0; q < 8; q++) v[q] = stg[(kq + q) * 129 + n];
            uint32_t H[4], L[4];
            #pragma unroll
            for (int p = 0; p < 4; p++) split2(v[2*p], v[2*p+1], H[p], L[p]);
            size_t off = (((size_t)bb * DD + n) << 10) + k0 + kq;
            *(uint4*)(oh + off) = *(uint4*)H;
            *(uint4*)(ol + off) = *(uint4*)L;
        }
        return;
    }

    float bv[4] = {0.f, 0.f, 0.f, 0.f};
    if (bias) {
        float4 b4 = *(const float4*)&bias[tx * 4];
        bv[0] = b4.x; bv[1] = b4.y; bv[2] = b4.z; bv[3] = b4.w;
    }

    #pragma unroll
    for (int i = 0; i < 8; i++) {
        int r = row0 + ty * 8 + i;
        float v[4];
        #pragma unroll
        for (int j = 0; j < 4; j++) v[j] = acc[i][j] + bv[j];

        if (EPI == 1) {
            float ss = v[0]*v[0] + v[1]*v[1] + v[2]*v[2] + v[3]*v[3];
            #pragma unroll
            for (int o = 16; o > 0; o >>= 1)
                ss += __shfl_xor_sync(0xffffffffu, ss, o);
            float s = hyp_scale(sqrtf(ss));
            #pragma unroll
            for (int j = 0; j < 4; j++) v[j] *= s;
        } else if (EPI == 2) {
            float s = mask[r];
            #pragma unroll
            for (int j = 0; j < 4; j++) v[j] *= s;
        }
        *(float4*)&out[(size_t)r * DD + tx * 4] = make_float4(v[0], v[1], v[2], v[3]);
    }
}

// ---------------------------------------------------------------------------
// Big GEMM via mma.sync bf16 x3 (error-compensated):
//   D = A[128,1024] @ m2[1024,128], A & B split hi/lo bf16.
//   epilogue: t = hyp_rows(relu(m + D + b_agg))
// BM=128, BN=128, BK=32; 8 warps (2x4), warp tile 64x32; cp.async double buffer.
// ---------------------------------------------------------------------------
#define PA    80       // bytes per smem tile row (40 bf16, conflict-free pitch)
#define TILE  10240    // 128 * PA
#define AGG_SMEM (8 * TILE)  // 81920 B (also covers 128x132 f32 epilogue staging)

__global__ void __launch_bounds__(256, 2) agg_mma(
    const uint16_t* __restrict__ AH, const uint16_t* __restrict__ AL,
    const uint16_t* __restrict__ BH, const uint16_t* __restrict__ BL,
    const float* __restrict__ M, const float* __restrict__ bagg,
    float* __restrict__ T)
{
    extern __shared__ char smem[];
    const uint32_t sb = smem_u32(smem);
    const int tid  = threadIdx.x;
    const int lane = tid & 31;
    const int wid  = tid >> 5;
    const int b    = blockIdx.y;
    const int row0 = blockIdx.x * 128;
    const int wm   = wid & 1;     // warp m (x64)
    const int wn   = wid >> 1;    // warp n (x32)

    const char* gAh = (const char*)(AH + (size_t)(b * NN + row0) * NN);
    const char* gAl = (const char*)(AL + (size_t)(b * NN + row0) * NN);
    const char* gBh = (const char*)(BH + (size_t)b * DD * NN);
    const char* gBl = (const char*)(BL + (size_t)b * DD * NN);

    const int r_ld = tid >> 2;           // 0..63 (+64 second round)
    const int chb  = (tid & 3) * 16;     // 16B chunk within 64B row-slice

    float d[4][4][4];
    #pragma unroll
    for (int mi = 0; mi < 4; mi++)
        #pragma unroll
        for (int ni = 0; ni < 4; ni++)
            #pragma unroll
            for (int q = 0; q < 4; q++) d[mi][ni][q] = 0.f;

    // ---- issue one k-chunk (32 cols) of all 4 tiles into stage s ----
    auto issue = [&](int c, int s) {
        #pragma unroll
        for (int j = 0; j < 2; j++) {
            int r = r_ld + j * 64;
            uint32_t doff = (uint32_t)(r * PA + chb);
            size_t   soff = (size_t)r * 2048 + (size_t)c * 64 + chb;
            CP16(sb + (uint32_t)(0 * TILE) + (uint32_t)s * TILE + doff, gAh + soff);
            CP16(sb + (uint32_t)(2 * TILE) + (uint32_t)s * TILE + doff, gAl + soff);
            CP16(sb + (uint32_t)(4 * TILE) + (uint32_t)s * TILE + doff, gBh + soff);
            CP16(sb + (uint32_t)(6 * TILE) + (uint32_t)s * TILE + doff, gBl + soff);
        }
        asm volatile("cp.async.commit_group;" ::: "memory");
    };

    issue(0, 0);

    const uint32_t aoff = (uint32_t)((wm * 64 + (lane >> 2)) * PA + (lane & 3) * 4);
    const uint32_t boff = (uint32_t)((wn * 32 + (lane >> 2)) * PA + (lane & 3) * 4);

    for (int c = 0; c < 32; c++) {
        int s = c & 1;
        if (c + 1 < 32) {
            issue(c + 1, s ^ 1);
            asm volatile("cp.async.wait_group 1;" ::: "memory");
        } else {
            asm volatile("cp.async.wait_group 0;" ::: "memory");
        }
        __syncthreads();

        uint32_t sAh = sb + (uint32_t)s * TILE + aoff;
        uint32_t sAl = sb + 2 * TILE + (uint32_t)s * TILE + aoff;
        uint32_t sBh = sb + 4 * TILE + (uint32_t)s * TILE + boff;
        uint32_t sBl = sb + 6 * TILE + (uint32_t)s * TILE + boff;

        #pragma unroll
        for (int ks = 0; ks < 2; ks++) {
            uint32_t kb = ks * 32;   // byte offset of k16 group
            uint32_t bh[4][2], bl[4][2];
            #pragma unroll
            for (int ni = 0; ni < 4; ni++) {
                uint32_t a0 = sBh + ni * 8 * PA + kb;
                bh[ni][0] = lds_u32(a0);
                bh[ni][1] = lds_u32(a0 + 16);
                uint32_t a1 = sBl + ni * 8 * PA + kb;
                bl[ni][0] = lds_u32(a1);
                bl[ni][1] = lds_u32(a1 + 16);
            }
            #pragma unroll
            for (int mi = 0; mi < 4; mi++) {
                uint32_t p0 = sAh + mi * 16 * PA + kb;
                uint32_t ah[4] = { lds_u32(p0),      lds_u32(p0 + 8 * PA),
                                   lds_u32(p0 + 16), lds_u32(p0 + 8 * PA + 16) };
                uint32_t p1 = sAl + mi * 16 * PA + kb;
                uint32_t al[4] = { lds_u32(p1),      lds_u32(p1 + 8 * PA),
                                   lds_u32(p1 + 16), lds_u32(p1 + 8 * PA + 16) };
                #pragma unroll
                for (int ni = 0; ni < 4; ni++) {
                    mma_bf16(d[mi][ni], ah, bh[ni][0], bh[ni][1]);
                    mma_bf16(d[mi][ni], ah, bl[ni][0], bl[ni][1]);
                    mma_bf16(d[mi][ni], al, bh[ni][0], bh[ni][1]);
                }
            }
        }
        __syncthreads();
    }

    // ---- stage D to smem (f32, pitch 132) ----
    float* stg = (float*)smem;
    #pragma unroll
    for (int mi = 0; mi < 4; mi++) {
        int R = wm * 64 + mi * 16 + (lane >> 2);
        #pragma unroll
        for (int ni = 0; ni < 4; ni++) {
            int C = wn * 32 + ni * 8 + (lane & 3) * 2;
            *(float2*)&stg[R * 132 + C]       = make_float2(d[mi][ni][0], d[mi][ni][1]);
            *(float2*)&stg[(R + 8) * 132 + C] = make_float2(d[mi][ni][2], d[mi][ni][3]);
        }
    }
    __syncthreads();

    // ---- fused row epilogue: relu(m + D + bias) then hyperbolic rescale ----
    const float* Mb = M + ((size_t)b * NN + row0) * DD;
    float*       Tb = T + ((size_t)b * NN + row0) * DD;
    float4 bg = *(const float4*)&bagg[lane * 4];
    #pragma unroll
    for (int i = 0; i < 16; i++) {
        int rr = wid * 16 + i;
        float4 raw = *(const float4*)&stg[rr * 132 + lane * 4];
        float4 mm  = *(const float4*)&Mb[(size_t)rr * DD + lane * 4];
        float v0 = fmaxf(raw.x + mm.x + bg.x, 0.f);
        float v1 = fmaxf(raw.y + mm.y + bg.y, 0.f);
        float v2 = fmaxf(raw.z + mm.z + bg.z, 0.f);
        float v3 = fmaxf(raw.w + mm.w + bg.w, 0.f);
        float ss = v0*v0 + v1*v1 + v2*v2 + v3*v3;
        #pragma unroll
        for (int o = 16; o > 0; o >>= 1)
            ss += __shfl_xor_sync(0xffffffffu, ss, o);
        float s = hyp_scale(sqrtf(ss));
        *(float4*)&Tb[(size_t)rr * DD + lane * 4] =
            make_float4(v0 * s, v1 * s, v2 * s, v3 * s);
    }
}

// ---------------------------------------------------------------------------
// Host launch
// ---------------------------------------------------------------------------
extern "C" void kernel_launch(void* const* d_in, const int* in_sizes, int n_in,
                              void* d_out, int out_size)
{
    const float* nf    = (const float*)d_in[0];
    const float* adj   = (const float*)d_in[1];
    const float* mask  = (const float*)d_in[2];
    const float* Wemb  = (const float*)d_in[3];
    const float* Wmsg  = (const float*)d_in[4];
    const float* bmsg  = (const float*)d_in[5];
    const float* Wagg  = (const float*)d_in[6];
    const float* bagg  = (const float*)d_in[7];
    const float* Wproj = (const float*)d_in[8];
    const float* bproj = (const float*)d_in[9];
    float* out = (float*)d_out;

    float *t, *m;
    uint16_t *ah, *al, *m2h, *m2l;
    cudaGetSymbolAddress((void**)&t,   g_t);
    cudaGetSymbolAddress((void**)&m,   g_m);
    cudaGetSymbolAddress((void**)&ah,  g_ah);
    cudaGetSymbolAddress((void**)&al,  g_al);
    cudaGetSymbolAddress((void**)&m2h, g_m2h);
    cudaGetSymbolAddress((void**)&m2l, g_m2l);

    static bool attr_set = false;
    if (!attr_set) {
        cudaFuncSetAttribute(agg_mma, cudaFuncAttributeMaxDynamicSharedMemorySize,
                             AGG_SMEM);
        attr_set = true;
    }

    dim3 gsmall(ROWS / 64);        // 512
    dim3 gbig(NN / 128, BATCH);    // 8 x 32

    // one-time adjacency split (per launch; deterministic)
    split_adj<<<(BATCH * NN * NN / 4) / 256, 256>>>((const float4*)adj,
                                                    (uint2*)ah, (uint2*)al);

    // embed: t = hyp_rows(nf @ Wemb^T)
    gemm_small<true, 1><<<gsmall, 256>>>(nf, Wemb, nullptr, nullptr, t, nullptr);

    for (int l = 0; l < 2; l++) {
        // m = t @ Wmsg[l] + bmsg[l]
        gemm_small<false, 0><<<gsmall, 256>>>(t, Wmsg + l * DD * DD,
                                              bmsg + l * DD, nullptr, m, nullptr);
        // m2^T (bf16 hi/lo, [b][n][k]) = (m @ Wagg[l])^T
        gemm_small<false, 3><<<gsmall, 256>>>(m, Wagg + l * DD * DD,
                                              nullptr, nullptr,
                                              (float*)m2h, (float*)m2l);
        // t = hyp_rows(relu(m + A@m2 + bagg[l]))
        agg_mma<<<gbig, 256, AGG_SMEM>>>(ah, al, m2h, m2l, m, bagg + l * DD, t);
    }

    // out = (t @ Wproj^T + bproj) * mask
    gemm_small<true, 2><<<gsmall, 256>>>(t, Wproj, bproj, mask, out, nullptr);
}

// round 4
// speedup vs baseline: 1.7417x; 1.2193x over previous
#include <cuda_runtime.h>
#include <math.h>
#include <stdint.h>

// Problem constants
#define BATCH 32
#define NN    1024
#define DD    128
#define ROWS  (BATCH * NN)   // 32768

// Scratch (device globals — no allocation allowed)
__device__ float g_t[ROWS * DD];
__device__ float g_m[ROWS * DD];
__device__ __align__(16) uint16_t g_ah[(size_t)BATCH * NN * NN];   // adj bf16 hi
__device__ __align__(16) uint16_t g_al[(size_t)BATCH * NN * NN];   // adj bf16 lo
__device__ __align__(16) uint16_t g_m2h[(size_t)BATCH * DD * NN];  // m2^T hi [b][n][k]
__device__ __align__(16) uint16_t g_m2l[(size_t)BATCH * DD * NN];  // m2^T lo

// ---------------------------------------------------------------------------
// Helpers
// ---------------------------------------------------------------------------
__device__ __forceinline__ uint32_t smem_u32(const void* p) {
    uint32_t a;
    asm("{ .reg .u64 t; cvta.to.shared.u64 t, %1; cvt.u32.u64 %0, t; }" : "=r"(a) : "l"(p));
    return a;
}
__device__ __forceinline__ uint32_t lds_u32(uint32_t addr) {
    uint32_t v;
    asm volatile("ld.shared.b32 %0, [%1];" : "=r"(v) : "r"(addr));
    return v;
}
__device__ __forceinline__ uint32_t pack_bf16x2(float v0, float v1) {
    uint32_t r;
    asm("cvt.rn.bf16x2.f32 %0, %1, %2;" : "=r"(r) : "f"(v1), "f"(v0));
    return r;
}
__device__ __forceinline__ void split2(float v0, float v1, uint32_t& h, uint32_t& l) {
    h = pack_bf16x2(v0, v1);
    float r0 = v0 - __uint_as_float(h << 16);
    float r1 = v1 - __uint_as_float(h & 0xffff0000u);
    l = pack_bf16x2(r0, r1);
}
#define CP16(dst, src) \
    asm volatile("cp.async.cg.shared.global [%0], [%1], 16;" :: "r"(dst), "l"(src) : "memory")

__device__ __forceinline__ void mma_bf16(float d[4], const uint32_t a[4],
                                         uint32_t b0, uint32_t b1) {
    asm volatile(
        "mma.sync.aligned.m16n8k16.row.col.f32.bf16.bf16.f32 "
        "{%0,%1,%2,%3}, {%4,%5,%6,%7}, {%8,%9}, {%0,%1,%2,%3};"
        : "+f"(d[0]), "+f"(d[1]), "+f"(d[2]), "+f"(d[3])
        : "r"(a[0]), "r"(a[1]), "r"(a[2]), "r"(a[3]), "r"(b0), "r"(b1));
}

// Composite per-row scale: logmap0(proj(expmap0(h))) = s(||h||) * h
__device__ __forceinline__ float hyp_scale(float n) {
    const float EPS  = 1e-7f;
    const float MAXN = 1.0f - 1e-5f;
    float n1 = fmaxf(n, EPS);
    float r  = tanhf(n1) / n1;
    float xn = r * n;
    float n2 = fmaxf(xn, EPS);
    float s2 = (n2 > MAXN) ? (MAXN / n2) : 1.0f;
    float x2 = s2 * xn;
    float n3 = fmaxf(x2, EPS);
    float z  = fminf(n3, 1.0f - EPS);
    float lg = atanhf(z) / n3;
    return r * s2 * lg;
}

// ---------------------------------------------------------------------------
// One-time adjacency split: fp32 -> bf16 hi/lo
// ---------------------------------------------------------------------------
__global__ void __launch_bounds__(256) split_adj(const float4* __restrict__ a,
                                                 uint2* __restrict__ h,
                                                 uint2* __restrict__ l) {
    int i = blockIdx.x * 256 + threadIdx.x;
    float4 v = a[i];
    uint32_t h0, l0, h1, l1;
    split2(v.x, v.y, h0, l0);
    split2(v.z, v.w, h1, l1);
    h[i] = make_uint2(h0, h1);
    l[i] = make_uint2(l0, l1);
}

// ---------------------------------------------------------------------------
// Shared-memory layout for the fused linear kernels (128-row CTAs, 8 warps)
//   bf16 tile buffers: [128 rows][128 bf16], pitch PX=272 bytes (bank-clean)
// ---------------------------------------------------------------------------
#define PX 272
#define OFF_XH 0
#define OFF_XL 34816
#define OFF_WH 69632
#define OFF_WL 104448
#define OFF_STG 139264                 // 64 x 129 f32 transpose staging
#define LIN_SMEM  172288
#define PROJ_SMEM 139264

// Load [128][128] f32 (row stride ldg) -> split bf16 hi/lo smem tiles
__device__ __forceinline__ void load_split_128(const float* __restrict__ g, int ldg,
                                               char* xh, char* xl, int tid) {
    int row = tid >> 1;
    int c0  = (tid & 1) * 64;
    const float* gp = g + (size_t)row * ldg + c0;
    char* ph = xh + row * PX + c0 * 2;
    char* pl = xl + row * PX + c0 * 2;
    #pragma unroll
    for (int i = 0; i < 16; i++) {
        float4 v = *(const float4*)(gp + i * 4);
        uint32_t h0, l0, h1, l1;
        split2(v.x, v.y, h0, l0);
        split2(v.z, v.w, h1, l1);
        *(uint2*)(ph + i * 8) = make_uint2(h0, h1);
        *(uint2*)(pl + i * 8) = make_uint2(l0, l1);
    }
}

// Load W [k=128][n=128] f32 from gmem, transpose to smem [n][k] bf16 hi/lo.
// Uses stg as f32 staging; contains internal __syncthreads (full block).
__device__ __forceinline__ void load_w_trans(const float* __restrict__ gW, float* stg,
                                             char* wh, char* wl, int tid) {
    for (int kk0 = 0; kk0 < 128; kk0 += 64) {
        int r = tid >> 2, c = (tid & 3) * 32;
        const float* gp = gW + (size_t)(kk0 + r) * 128 + c;
        #pragma unroll
        for (int i = 0; i < 8; i++) {
            float4 v = *(const float4*)(gp + i * 4);
            float* s = &stg[r * 129 + c + i * 4];
            s[0] = v.x; s[1] = v.y; s[2] = v.z; s[3] = v.w;
        }
        __syncthreads();
        int n = tid >> 1, ks = (tid & 1) * 32;
        char* ph = wh + n * PX + (kk0 + ks) * 2;
        char* pl = wl + n * PX + (kk0 + ks) * 2;
        #pragma unroll
        for (int j = 0; j < 32; j += 2) {
            float v0 = stg[(ks + j) * 129 + n];
            float v1 = stg[(ks + j + 1) * 129 + n];
            uint32_t h, l;
            split2(v0, v1, h, l);
            *(uint32_t*)(ph + j * 2) = h;
            *(uint32_t*)(pl + j * 2) = l;
        }
        __syncthreads();
    }
}

// Full-K (128) mma block: D[i][j] += sum_k A[i][k]*B[j][k], 3-product hi/lo.
// A smem [i][k] at Ah/Al, B smem [j][k] at Bh/Bl (both pitch PX).
__device__ __forceinline__ void mma_K128(uint32_t Ah, uint32_t Al,
                                         uint32_t Bh, uint32_t Bl,
                                         int wm, int wn, int lane,
                                         float (&d)[4][4][4]) {
    const uint32_t aoff = (uint32_t)((wm * 64 + (lane >> 2)) * PX + (lane & 3) * 4);
    const uint32_t boff = (uint32_t)((wn * 32 + (lane >> 2)) * PX + (lane & 3) * 4);
    const uint32_t sAh = Ah + aoff, sAl = Al + aoff;
    const uint32_t sBh = Bh + boff, sBl = Bl + boff;
    for (int ks = 0; ks < 8; ks++) {
        uint32_t kb = ks * 32;
        uint32_t bh[4][2], bl[4][2];
        #pragma unroll
        for (int ni = 0; ni < 4; ni++) {
            uint32_t a0 = sBh + ni * 8 * PX + kb;
            bh[ni][0] = lds_u32(a0);
            bh[ni][1] = lds_u32(a0 + 16);
            uint32_t a1 = sBl + ni * 8 * PX + kb;
            bl[ni][0] = lds_u32(a1);
            bl[ni][1] = lds_u32(a1 + 16);
        }
        #pragma unroll
        for (int mi = 0; mi < 4; mi++) {
            uint32_t p0 = sAh + mi * 16 * PX + kb;
            uint32_t ah[4] = { lds_u32(p0),      lds_u32(p0 + 8 * PX),
                               lds_u32(p0 + 16), lds_u32(p0 + 8 * PX + 16) };
            uint32_t p1 = sAl + mi * 16 * PX + kb;
            uint32_t al[4] = { lds_u32(p1),      lds_u32(p1 + 8 * PX),
                               lds_u32(p1 + 16), lds_u32(p1 + 8 * PX + 16) };
            #pragma unroll
            for (int ni = 0; ni < 4; ni++) {
                mma_bf16(d[mi][ni], ah, bh[ni][0], bh[ni][1]);
                mma_bf16(d[mi][ni], ah, bl[ni][0], bl[ni][1]);
                mma_bf16(d[mi][ni], al, bh[ni][0], bh[ni][1]);
            }
        }
    }
}
#define ZERO_D(d) { _Pragma("unroll") for (int _i = 0; _i < 4; _i++) \
    _Pragma("unroll") for (int _j = 0; _j < 4; _j++) \
    _Pragma("unroll") for (int _q = 0; _q < 4; _q++) d[_i][_j][_q] = 0.f; }

// ---------------------------------------------------------------------------
// Fused front/chain kernel.
//   FIRST=1: h = X@Wemb^T -> t = hyp_rows(h)   (t kept in smem only)
//   FIRST=0: t = X (read from gmem)
//   then: m = t@W1 + b1 (write gmem), m2T = W2^T @ m^T -> split bf16 write.
// ---------------------------------------------------------------------------
template<bool FIRST>
__global__ void __launch_bounds__(256, 1) chain_kernel(
    const float* __restrict__ X, const float* __restrict__ Wemb,
    const float* __restrict__ W1, const float* __restrict__ bias1,
    const float* __restrict__ W2,
    float* __restrict__ Mout,
    uint16_t* __restrict__ M2H, uint16_t* __restrict__ M2L)
{
    extern __shared__ char smem[];
    const uint32_t sb = smem_u32(smem);
    const int tid = threadIdx.x, lane = tid & 31, wid = tid >> 5;
    const int wm = wid & 1, wn = wid >> 1;
    const int row0 = blockIdx.x * 128;

    char* XH = smem + OFF_XH;
    char* XL = smem + OFF_XL;
    char* WH = smem + OFF_WH;
    char* WL = smem + OFF_WL;
    float* STG = (float*)(smem + OFF_STG);

    float d[4][4][4];

    if (FIRST) {
        // GEMM0: h = nf @ Wemb^T
        load_split_128(X + (size_t)row0 * DD, DD, XH, XL, tid);
        load_split_128(Wemb, DD, WH, WL, tid);
        __syncthreads();
        ZERO_D(d);
        mma_K128(sb + OFF_XH, sb + OFF_XL, sb + OFF_WH, sb + OFF_WL, wm, wn, lane, d);
        __syncthreads();                       // all reads of WH done
        // stage h into W region (f32, pitch 132)
        float* stgD = (float*)(smem + OFF_WH);
        #pragma unroll
        for (int mi = 0; mi < 4; mi++) {
            int R = wm * 64 + mi * 16 + (lane >> 2);
            #pragma unroll
            for (int ni = 0; ni < 4; ni++) {
                int C = wn * 32 + ni * 8 + (lane & 3) * 2;
                stgD[R * 132 + C]           = d[mi][ni][0];
                stgD[R * 132 + C + 1]       = d[mi][ni][1];
                stgD[(R + 8) * 132 + C]     = d[mi][ni][2];
                stgD[(R + 8) * 132 + C + 1] = d[mi][ni][3];
            }
        }
        __syncthreads();
        // hyp rows -> t split into XH/XL (no gmem write needed)
        #pragma unroll
        for (int i = 0; i < 16; i++) {
            int rr = wid * 16 + i;
            float4 v = *(float4*)&stgD[rr * 132 + lane * 4];
            float ss = v.x * v.x + v.y * v.y + v.z * v.z + v.w * v.w;
            #pragma unroll
            for (int o = 16; o > 0; o >>= 1)
                ss += __shfl_xor_sync(0xffffffffu, ss, o);
            float s = hyp_scale(sqrtf(ss));
            v.x *= s; v.y *= s; v.z *= s; v.w *= s;
            uint32_t h0, l0, h1, l1;
            split2(v.x, v.y, h0, l0);
            split2(v.z, v.w, h1, l1);
            *(uint2*)(XH + rr * PX + lane * 8) = make_uint2(h0, h1);
            *(uint2*)(XL + rr * PX + lane * 8) = make_uint2(l0, l1);
        }
        __syncthreads();                       // stgD consumed; XH/XL = t
    } else {
        load_split_128(X + (size_t)row0 * DD, DD, XH, XL, tid);
        // visibility handled by load_w_trans' internal barrier
    }

    // GEMM1: m = t @ W1 + b1   (W1 gmem [k][n] -> smem [n][k])
    load_w_trans(W1, STG, WH, WL, tid);
    ZERO_D(d);
    mma_K128(sb + OFF_XH, sb + OFF_XL, sb + OFF_WH, sb + OFF_WL, wm, wn, lane, d);
    __syncthreads();                           // all reads of XH (t) done

    // write m (fp32 gmem) + split m into XH/XL directly from registers
    #pragma unroll
    for (int mi = 0; mi < 4; mi++) {
        int R = wm * 64 + mi * 16 + (lane >> 2);
        #pragma unroll
        for (int ni = 0; ni < 4; ni++) {
            int C = wn * 32 + ni * 8 + (lane & 3) * 2;
            float b0 = bias1[C], b1 = bias1[C + 1];
            float v0 = d[mi][ni][0] + b0, v1 = d[mi][ni][1] + b1;
            float v2 = d[mi][ni][2] + b0, v3 = d[mi][ni][3] + b1;
            *(float2*)&Mout[(size_t)(row0 + R) * DD + C]     = make_float2(v0, v1);
            *(float2*)&Mout[(size_t)(row0 + R + 8) * DD + C] = make_float2(v2, v3);
            uint32_t h, l;
            split2(v0, v1, h, l);
            *(uint32_t*)(XH + R * PX + C * 2) = h;
            *(uint32_t*)(XL + R * PX + C * 2) = l;
            split2(v2, v3, h, l);
            *(uint32_t*)(XH + (R + 8) * PX + C * 2) = h;
            *(uint32_t*)(XL + (R + 8) * PX + C * 2) = l;
        }
    }

    // GEMM2: m2T[n][r] = sum_k W2[k][n] * m[r][k]  (A = W2^T smem, B = m smem)
    load_w_trans(W2, STG, WH, WL, tid);        // internal barriers fence m-split
    ZERO_D(d);
    mma_K128(sb + OFF_WH, sb + OFF_WL, sb + OFF_XH, sb + OFF_XL, wm, wn, lane, d);

    // write m2T split bf16 directly: rows = n, cols = r (k-contiguous in gmem)
    const int bb = row0 >> 10;
    const int rb = row0 & 1023;
    #pragma unroll
    for (int mi = 0; mi < 4; mi++) {
        int Rn = wm * 64 + mi * 16 + (lane >> 2);
        #pragma unroll
        for (int ni = 0; ni < 4; ni++) {
            int Cr = wn * 32 + ni * 8 + (lane & 3) * 2;
            uint32_t h, l;
            split2(d[mi][ni][0], d[mi][ni][1], h, l);
            size_t o = (((size_t)bb * DD + Rn) << 10) + rb + Cr;
            *(uint32_t*)(M2H + o) = h;
            *(uint32_t*)(M2L + o) = l;
            split2(d[mi][ni][2], d[mi][ni][3], h, l);
            size_t o2 = (((size_t)bb * DD + Rn + 8) << 10) + rb + Cr;
            *(uint32_t*)(M2H + o2) = h;
            *(uint32_t*)(M2L + o2) = l;
        }
    }
}

// ---------------------------------------------------------------------------
// Final projection: out = (t @ Wproj^T + bproj) * mask   (Wproj gmem [n][k])
// ---------------------------------------------------------------------------
__global__ void __launch_bounds__(256, 1) proj_kernel(
    const float* __restrict__ X, const float* __restrict__ Wp,
    const float* __restrict__ bp, const float* __restrict__ mask,
    float* __restrict__ out)
{
    extern __shared__ char smem[];
    const uint32_t sb = smem_u32(smem);
    const int tid = threadIdx.x, lane = tid & 31, wid = tid >> 5;
    const int wm = wid & 1, wn = wid >> 1;
    const int row0 = blockIdx.x * 128;

    load_split_128(X + (size_t)row0 * DD, DD, smem + OFF_XH, smem + OFF_XL, tid);
    load_split_128(Wp, DD, smem + OFF_WH, smem + OFF_WL, tid);
    __syncthreads();

    float d[4][4][4];
    ZERO_D(d);
    mma_K128(sb + OFF_XH, sb + OFF_XL, sb + OFF_WH, sb + OFF_WL, wm, wn, lane, d);

    #pragma unroll
    for (int mi = 0; mi < 4; mi++) {
        int R = wm * 64 + mi * 16 + (lane >> 2);
        float mk0 = mask[row0 + R];
        float mk1 = mask[row0 + R + 8];
        #pragma unroll
        for (int ni = 0; ni < 4; ni++) {
            int C = wn * 32 + ni * 8 + (lane & 3) * 2;
            float b0 = bp[C], b1 = bp[C + 1];
            *(float2*)&out[(size_t)(row0 + R) * DD + C] =
                make_float2((d[mi][ni][0] + b0) * mk0, (d[mi][ni][1] + b1) * mk0);
            *(float2*)&out[(size_t)(row0 + R + 8) * DD + C] =
                make_float2((d[mi][ni][2] + b0) * mk1, (d[mi][ni][3] + b1) * mk1);
        }
    }
}

// ---------------------------------------------------------------------------
// Big GEMM via mma.sync bf16 x3 (unchanged from R3, validated)
// ---------------------------------------------------------------------------
#define PA    80
#define TILE  10240
#define AGG_SMEM (8 * TILE)

__global__ void __launch_bounds__(256, 2) agg_mma(
    const uint16_t* __restrict__ AH, const uint16_t* __restrict__ AL,
    const uint16_t* __restrict__ BH, const uint16_t* __restrict__ BL,
    const float* __restrict__ M, const float* __restrict__ bagg,
    float* __restrict__ T)
{
    extern __shared__ char smem[];
    const uint32_t sb = smem_u32(smem);
    const int tid  = threadIdx.x;
    const int lane = tid & 31;
    const int wid  = tid >> 5;
    const int b    = blockIdx.y;
    const int row0 = blockIdx.x * 128;
    const int wm   = wid & 1;
    const int wn   = wid >> 1;

    const char* gAh = (const char*)(AH + (size_t)(b * NN + row0) * NN);
    const char* gAl = (const char*)(AL + (size_t)(b * NN + row0) * NN);
    const char* gBh = (const char*)(BH + (size_t)b * DD * NN);
    const char* gBl = (const char*)(BL + (size_t)b * DD * NN);

    const int r_ld = tid >> 2;
    const int chb  = (tid & 3) * 16;

    float d[4][4][4];
    ZERO_D(d);

    auto issue = [&](int c, int s) {
        #pragma unroll
        for (int j = 0; j < 2; j++) {
            int r = r_ld + j * 64;
            uint32_t doff = (uint32_t)(r * PA + chb);
            size_t   soff = (size_t)r * 2048 + (size_t)c * 64 + chb;
            CP16(sb + (uint32_t)s * TILE + doff,            gAh + soff);
            CP16(sb + 2 * TILE + (uint32_t)s * TILE + doff, gAl + soff);
            CP16(sb + 4 * TILE + (uint32_t)s * TILE + doff, gBh + soff);
            CP16(sb + 6 * TILE + (uint32_t)s * TILE + doff, gBl + soff);
        }
        asm volatile("cp.async.commit_group;" ::: "memory");
    };

    issue(0, 0);

    const uint32_t aoff = (uint32_t)((wm * 64 + (lane >> 2)) * PA + (lane & 3) * 4);
    const uint32_t boff = (uint32_t)((wn * 32 + (lane >> 2)) * PA + (lane & 3) * 4);

    for (int c = 0; c < 32; c++) {
        int s = c & 1;
        if (c + 1 < 32) {
            issue(c + 1, s ^ 1);
            asm volatile("cp.async.wait_group 1;" ::: "memory");
        } else {
            asm volatile("cp.async.wait_group 0;" ::: "memory");
        }
        __syncthreads();

        uint32_t sAh = sb + (uint32_t)s * TILE + aoff;
        uint32_t sAl = sb + 2 * TILE + (uint32_t)s * TILE + aoff;
        uint32_t sBh = sb + 4 * TILE + (uint32_t)s * TILE + boff;
        uint32_t sBl = sb + 6 * TILE + (uint32_t)s * TILE + boff;

        #pragma unroll
        for (int ks = 0; ks < 2; ks++) {
            uint32_t kb = ks * 32;
            uint32_t bh[4][2], bl[4][2];
            #pragma unroll
            for (int ni = 0; ni < 4; ni++) {
                uint32_t a0 = sBh + ni * 8 * PA + kb;
                bh[ni][0] = lds_u32(a0);
                bh[ni][1] = lds_u32(a0 + 16);
                uint32_t a1 = sBl + ni * 8 * PA + kb;
                bl[ni][0] = lds_u32(a1);
                bl[ni][1] = lds_u32(a1 + 16);
            }
            #pragma unroll
            for (int mi = 0; mi < 4; mi++) {
                uint32_t p0 = sAh + mi * 16 * PA + kb;
                uint32_t ah[4] = { lds_u32(p0),      lds_u32(p0 + 8 * PA),
                                   lds_u32(p0 + 16), lds_u32(p0 + 8 * PA + 16) };
                uint32_t p1 = sAl + mi * 16 * PA + kb;
                uint32_t al[4] = { lds_u32(p1),      lds_u32(p1 + 8 * PA),
                                   lds_u32(p1 + 16), lds_u32(p1 + 8 * PA + 16) };
                #pragma unroll
                for (int ni = 0; ni < 4; ni++) {
                    mma_bf16(d[mi][ni], ah, bh[ni][0], bh[ni][1]);
                    mma_bf16(d[mi][ni], ah, bl[ni][0], bl[ni][1]);
                    mma_bf16(d[mi][ni], al, bh[ni][0], bh[ni][1]);
                }
            }
        }
        __syncthreads();
    }

    float* stg = (float*)smem;
    #pragma unroll
    for (int mi = 0; mi < 4; mi++) {
        int R = wm * 64 + mi * 16 + (lane >> 2);
        #pragma unroll
        for (int ni = 0; ni < 4; ni++) {
            int C = wn * 32 + ni * 8 + (lane & 3) * 2;
            *(float2*)&stg[R * 132 + C]       = make_float2(d[mi][ni][0], d[mi][ni][1]);
            *(float2*)&stg[(R + 8) * 132 + C] = make_float2(d[mi][ni][2], d[mi][ni][3]);
        }
    }
    __syncthreads();

    const float* Mb = M + ((size_t)b * NN + row0) * DD;
    float*       Tb = T + ((size_t)b * NN + row0) * DD;
    float4 bg = *(const float4*)&bagg[lane * 4];
    #pragma unroll
    for (int i = 0; i < 16; i++) {
        int rr = wid * 16 + i;
        float4 raw = *(const float4*)&stg[rr * 132 + lane * 4];
        float4 mm  = *(const float4*)&Mb[(size_t)rr * DD + lane * 4];
        float v0 = fmaxf(raw.x + mm.x + bg.x, 0.f);
        float v1 = fmaxf(raw.y + mm.y + bg.y, 0.f);
        float v2 = fmaxf(raw.z + mm.z + bg.z, 0.f);
        float v3 = fmaxf(raw.w + mm.w + bg.w, 0.f);
        float ss = v0*v0 + v1*v1 + v2*v2 + v3*v3;
        #pragma unroll
        for (int o = 16; o > 0; o >>= 1)
            ss += __shfl_xor_sync(0xffffffffu, ss, o);
        float s = hyp_scale(sqrtf(ss));
        *(float4*)&Tb[(size_t)rr * DD + lane * 4] =
            make_float4(v0 * s, v1 * s, v2 * s, v3 * s);
    }
}

// ---------------------------------------------------------------------------
// Host launch
// ---------------------------------------------------------------------------
extern "C" void kernel_launch(void* const* d_in, const int* in_sizes, int n_in,
                              void* d_out, int out_size)
{
    const float* nf    = (const float*)d_in[0];
    const float* adj   = (const float*)d_in[1];
    const float* mask  = (const float*)d_in[2];
    const float* Wemb  = (const float*)d_in[3];
    const float* Wmsg  = (const float*)d_in[4];
    const float* bmsg  = (const float*)d_in[5];
    const float* Wagg  = (const float*)d_in[6];
    const float* bagg  = (const float*)d_in[7];
    const float* Wproj = (const float*)d_in[8];
    const float* bproj = (const float*)d_in[9];
    float* out = (float*)d_out;

    float *t, *m;
    uint16_t *ah, *al, *m2h, *m2l;
    cudaGetSymbolAddress((void**)&t,   g_t);
    cudaGetSymbolAddress((void**)&m,   g_m);
    cudaGetSymbolAddress((void**)&ah,  g_ah);
    cudaGetSymbolAddress((void**)&al,  g_al);
    cudaGetSymbolAddress((void**)&m2h, g_m2h);
    cudaGetSymbolAddress((void**)&m2l, g_m2l);

    cudaFuncSetAttribute(agg_mma, cudaFuncAttributeMaxDynamicSharedMemorySize, AGG_SMEM);
    cudaFuncSetAttribute(chain_kernel<true>,  cudaFuncAttributeMaxDynamicSharedMemorySize, LIN_SMEM);
    cudaFuncSetAttribute(chain_kernel<false>, cudaFuncAttributeMaxDynamicSharedMemorySize, LIN_SMEM);
    cudaFuncSetAttribute(proj_kernel, cudaFuncAttributeMaxDynamicSharedMemorySize, PROJ_SMEM);

    dim3 glin(ROWS / 128);         // 256
    dim3 gbig(NN / 128, BATCH);    // 8 x 32

    split_adj<<<(BATCH * NN * NN / 4) / 256, 256>>>((const float4*)adj,
                                                    (uint2*)ah, (uint2*)al);

    // layer 0: embed + hyp + msg + m2 fused
    chain_kernel<true><<<glin, 256, LIN_SMEM>>>(nf, Wemb, Wmsg, bmsg, Wagg,
                                                m, m2h, m2l);
    agg_mma<<<gbig, 256, AGG_SMEM>>>(ah, al, m2h, m2l, m, bagg, t);

    // layer 1: msg + m2 fused
    chain_kernel<false><<<glin, 256, LIN_SMEM>>>(t, nullptr,
                                                 Wmsg + DD * DD, bmsg + DD,
                                                 Wagg + DD * DD, m, m2h, m2l);
    agg_mma<<<gbig, 256, AGG_SMEM>>>(ah, al, m2h, m2l, m, bagg + DD, t);

    // out = (t @ Wproj^T + bproj) * mask
    proj_kernel<<<glin, 256, PROJ_SMEM>>>(t, Wproj, bproj, mask, out);
}

// round 6
// speedup vs baseline: 1.7757x; 1.0195x over previous
#include <cuda_runtime.h>
#include <math.h>
#include <stdint.h>

// Problem constants
#define BATCH 32
#define NN    1024
#define DD    128
#define ROWS  (BATCH * NN)   // 32768

// Scratch (device globals — no allocation allowed)
__device__ float g_t[ROWS * DD];
__device__ float g_m[ROWS * DD];
__device__ __align__(16) uint16_t g_ah[(size_t)BATCH * NN * NN];   // adj bf16 hi
__device__ __align__(16) uint16_t g_al[(size_t)BATCH * NN * NN];   // adj bf16 lo
__device__ __align__(16) uint16_t g_m2h[(size_t)BATCH * DD * NN];  // m2^T hi [b][n][k]
__device__ __align__(16) uint16_t g_m2l[(size_t)BATCH * DD * NN];  // m2^T lo
__device__ __align__(16) uint16_t g_wh[6 * DD * DD];               // weights hi [n][k]
__device__ __align__(16) uint16_t g_wl[6 * DD * DD];               // weights lo

// ---------------------------------------------------------------------------
// Helpers
// ---------------------------------------------------------------------------
__device__ __forceinline__ uint32_t smem_u32(const void* p) {
    uint32_t a;
    asm("{ .reg .u64 t; cvta.to.shared.u64 t, %1; cvt.u32.u64 %0, t; }" : "=r"(a) : "l"(p));
    return a;
}
__device__ __forceinline__ uint32_t lds_u32(uint32_t addr) {
    uint32_t v;
    asm volatile("ld.shared.b32 %0, [%1];" : "=r"(v) : "r"(addr));
    return v;
}
__device__ __forceinline__ uint32_t pack_bf16x2(float v0, float v1) {
    uint32_t r;
    asm("cvt.rn.bf16x2.f32 %0, %1, %2;" : "=r"(r) : "f"(v1), "f"(v0));
    return r;
}
__device__ __forceinline__ void split2(float v0, float v1, uint32_t& h, uint32_t& l) {
    h = pack_bf16x2(v0, v1);
    float r0 = v0 - __uint_as_float(h << 16);
    float r1 = v1 - __uint_as_float(h & 0xffff0000u);
    l = pack_bf16x2(r0, r1);
}
#define CP16(dst, src) \
    asm volatile("cp.async.cg.shared.global [%0], [%1], 16;" :: "r"(dst), "l"(src) : "memory")
#define CP_COMMIT() asm volatile("cp.async.commit_group;" ::: "memory")
#define CPWAIT(n)   asm volatile("cp.async.wait_group %0;" :: "n"(n) : "memory")

__device__ __forceinline__ void mma_bf16(float d[4], const uint32_t a[4],
                                         uint32_t b0, uint32_t b1) {
    asm volatile(
        "mma.sync.aligned.m16n8k16.row.col.f32.bf16.bf16.f32 "
        "{%0,%1,%2,%3}, {%4,%5,%6,%7}, {%8,%9}, {%0,%1,%2,%3};"
        : "+f"(d[0]), "+f"(d[1]), "+f"(d[2]), "+f"(d[3])
        : "r"(a[0]), "r"(a[1]), "r"(a[2]), "r"(a[3]), "r"(b0), "r"(b1));
}

// Composite per-row scale: logmap0(proj(expmap0(h))) = s(||h||) * h
__device__ __forceinline__ float hyp_scale(float n) {
    const float EPS  = 1e-7f;
    const float MAXN = 1.0f - 1e-5f;
    float n1 = fmaxf(n, EPS);
    float r  = tanhf(n1) / n1;
    float xn = r * n;
    float n2 = fmaxf(xn, EPS);
    float s2 = (n2 > MAXN) ? (MAXN / n2) : 1.0f;
    float x2 = s2 * xn;
    float n3 = fmaxf(x2, EPS);
    float z  = fminf(n3, 1.0f - EPS);
    float lg = atanhf(z) / n3;
    return r * s2 * lg;
}

// ---------------------------------------------------------------------------
// Generic warp-tile MMA block over merged hi/lo smem tiles.
// ---------------------------------------------------------------------------
template<int PITCH, int LOOFF, int NKS, int MI>
__device__ __forceinline__ void mma_blk(uint32_t Ab, uint32_t Bb,
                                        int wma, int wnb, int lane,
                                        float (&d)[MI][4][4]) {
    const uint32_t aoff = (uint32_t)((wma * (MI * 16) + (lane >> 2)) * PITCH + (lane & 3) * 4);
    const uint32_t boff = (uint32_t)((wnb * 32 + (lane >> 2)) * PITCH + (lane & 3) * 4);
    const uint32_t sA = Ab + aoff, sB = Bb + boff;
    #pragma unroll
    for (int ks = 0; ks < NKS; ks++) {
        uint32_t kb = (uint32_t)ks * 32;
        uint32_t bh[4][2], bl[4][2];
        #pragma unroll
        for (int ni = 0; ni < 4; ni++) {
            uint32_t a0 = sB + ni * 8 * PITCH + kb;
            bh[ni][0] = lds_u32(a0);
            bh[ni][1] = lds_u32(a0 + 16);
            bl[ni][0] = lds_u32(a0 + LOOFF);
            bl[ni][1] = lds_u32(a0 + LOOFF + 16);
        }
        #pragma unroll
        for (int mi = 0; mi < MI; mi++) {
            uint32_t p0 = sA + mi * 16 * PITCH + kb;
            uint32_t ah[4] = { lds_u32(p0),      lds_u32(p0 + 8 * PITCH),
                               lds_u32(p0 + 16), lds_u32(p0 + 8 * PITCH + 16) };
            uint32_t al[4] = { lds_u32(p0 + LOOFF),      lds_u32(p0 + 8 * PITCH + LOOFF),
                               lds_u32(p0 + LOOFF + 16), lds_u32(p0 + 8 * PITCH + LOOFF + 16) };
            #pragma unroll
            for (int ni = 0; ni < 4; ni++) {
                mma_bf16(d[mi][ni], ah, bh[ni][0], bh[ni][1]);
                mma_bf16(d[mi][ni], ah, bl[ni][0], bl[ni][1]);
                mma_bf16(d[mi][ni], al, bh[ni][0], bh[ni][1]);
            }
        }
    }
}

// ---------------------------------------------------------------------------
// One-time adjacency split: fp32 -> bf16 hi/lo
// ---------------------------------------------------------------------------
__global__ void __launch_bounds__(256) split_adj(const float4* __restrict__ a,
                                                 uint2* __restrict__ h,
                                                 uint2* __restrict__ l) {
    int i = blockIdx.x * 256 + threadIdx.x;
    float4 v = a[i];
    uint32_t h0, l0, h1, l1;
    split2(v.x, v.y, h0, l0);
    split2(v.z, v.w, h1, l1);
    h[i] = make_uint2(h0, h1);
    l[i] = make_uint2(l0, l1);
}

// ---------------------------------------------------------------------------
// One-time weight split into [n][k] bf16 hi/lo. mats: 0=emb,1=msg0,2=agg0,
// 3=msg1,4=agg1,5=proj. emb/proj stored [n][k] already; msg/agg are [k][n].
// ---------------------------------------------------------------------------
__global__ void __launch_bounds__(256) split_weights(
    const float* __restrict__ Wemb, const float* __restrict__ Wmsg,
    const float* __restrict__ Wagg, const float* __restrict__ Wproj,
    uint16_t* __restrict__ WH, uint16_t* __restrict__ WL)
{
    int mat = blockIdx.x;
    const float* src;
    bool trans;
    switch (mat) {
        case 0:  src = Wemb;            trans = false; break;
        case 1:  src = Wmsg;            trans = true;  break;
        case 2:  src = Wagg;            trans = true;  break;
        case 3:  src = Wmsg + DD * DD;  trans = true;  break;
        case 4:  src = Wagg + DD * DD;  trans = true;  break;
        default: src = Wproj;           trans = false; break;
    }
    for (int idx = threadIdx.x; idx < DD * DD; idx += 256) {
        int n = idx >> 7, k = idx & 127;
        float v = trans ? src[k * DD + n] : src[idx];
        uint32_t p = pack_bf16x2(v, 0.f);
        uint16_t hh = (uint16_t)(p & 0xffffu);
        float r = v - __uint_as_float((uint32_t)hh << 16);
        uint32_t pl = pack_bf16x2(r, 0.f);
        WH[mat * DD * DD + idx] = hh;
        WL[mat * DD * DD + idx] = (uint16_t)(pl & 0xffffu);
    }
}

// ---------------------------------------------------------------------------
// Chain / proj smem layout: merged hi||lo rows, pitch 528 (bank = 4r+c).
// ---------------------------------------------------------------------------
#define PW 528
#define XBYTES (64 * PW)
#define WBYTES (128 * PW)
#define LIN_SMEM (XBYTES + WBYTES)    // 101376 -> 2 CTAs/SM

// LDG 64x128 fp32 rows (stride 128) -> split bf16 hi/lo into X tile
__device__ __forceinline__ void ldgsplit_X64(const float* __restrict__ g,
                                             char* X, int tid) {
    int row = tid >> 2;
    int c0  = (tid & 3) * 32;
    const float* gp = g + (size_t)row * DD + c0;
    char* ph = X + row * PW + c0 * 2;
    char* pl = ph + 256;
    #pragma unroll
    for (int i = 0; i < 8; i++) {
        float4 v = *(const float4*)(gp + i * 4);
        uint32_t h0, l0, h1, l1;
        split2(v.x, v.y, h0, l0);
        split2(v.z, v.w, h1, l1);
        *(uint2*)(ph + i * 8) = make_uint2(h0, h1);
        *(uint2*)(pl + i * 8) = make_uint2(l0, l1);
    }
}

// cp.async a pre-split weight matrix (mat) into W tile
__device__ __forceinline__ void cpw(const uint16_t* __restrict__ WHg,
                                    const uint16_t* __restrict__ WLg,
                                    int mat, uint32_t wbase, int tid) {
    int n = tid >> 1, half = tid & 1;
    const char* src = (const char*)((half ? WLg : WHg) + (size_t)mat * DD * DD + n * DD);
    uint32_t dst = wbase + (uint32_t)(n * PW + half * 256);
    #pragma unroll
    for (int q = 0; q < 16; q++)
        CP16(dst + q * 16, src + q * 16);
}

// ---------------------------------------------------------------------------
// Fused chain kernel (64-row tiles, 512 CTAs, 2 CTA/SM)
// ---------------------------------------------------------------------------
template<bool FIRST>
__global__ void __launch_bounds__(256, 2) chain_kernel(
    const float* __restrict__ X,
    const uint16_t* __restrict__ WHg, const uint16_t* __restrict__ WLg,
    int emb_mat, int w1_mat, int w2_mat,
    const float* __restrict__ bias1,
    float* __restrict__ Mout,
    uint16_t* __restrict__ M2H, uint16_t* __restrict__ M2L)
{
    extern __shared__ char smem[];
    const uint32_t sX = smem_u32(smem);
    const uint32_t sW = sX + XBYTES;
    char* Xp = smem;

    const int tid = threadIdx.x, lane = tid & 31, wid = tid >> 5;
    const int wm = wid & 1, wn = wid >> 1;      // GEMM0/1: M=64,N=128
    const int wm2 = wid & 3, wn2 = wid >> 2;    // GEMM2:   M=128,N=64
    const int row0 = blockIdx.x * 64;
    const int bb = row0 >> 10;
    const int rb = row0 & 1023;

    float d[2][4][4];

    if (FIRST) {
        cpw(WHg, WLg, emb_mat, sW, tid);
        CP_COMMIT();
        ldgsplit_X64(X + (size_t)row0 * DD, Xp, tid);
        CPWAIT(0);
        __syncthreads();

        #pragma unroll
        for (int i = 0; i < 2; i++)
            #pragma unroll
            for (int j = 0; j < 4; j++)
                #pragma unroll
                for (int q = 0; q < 4; q++) d[i][j][q] = 0.f;
        mma_blk<PW, 256, 8, 2>(sX, sW, wm, wn, lane, d);
        __syncthreads();                         // X & W reads done

        cpw(WHg, WLg, w1_mat, sW, tid);          // prefetch W1
        CP_COMMIT();

        // stage h f32 into X region (pitch 132 floats)
        float* stg = (float*)Xp;
        #pragma unroll
        for (int mi = 0; mi < 2; mi++) {
            int R = wm * 32 + mi * 16 + (lane >> 2);
            #pragma unroll
            for (int ni = 0; ni < 4; ni++) {
                int C = wn * 32 + ni * 8 + (lane & 3) * 2;
                stg[R * 132 + C]           = d[mi][ni][0];
                stg[R * 132 + C + 1]       = d[mi][ni][1];
                stg[(R + 8) * 132 + C]     = d[mi][ni][2];
                stg[(R + 8) * 132 + C + 1] = d[mi][ni][3];
            }
        }
        __syncthreads();

        // hyp rows (8 rows per warp), resplit into X tile in place
        #pragma unroll
        for (int i = 0; i < 8; i++) {
            int rr = wid * 8 + i;
            float4 v = *(float4*)&stg[rr * 132 + lane * 4];
            float ss = v.x * v.x + v.y * v.y + v.z * v.z + v.w * v.w;
            #pragma unroll
            for (int o = 16; o > 0; o >>= 1)
                ss += __shfl_xor_sync(0xffffffffu, ss, o);
            float s = hyp_scale(sqrtf(ss));
            v.x *= s; v.y *= s; v.z *= s; v.w *= s;
            __syncwarp();
            uint32_t h0, l0, h1, l1;
            split2(v.x, v.y, h0, l0);
            split2(v.z, v.w, h1, l1);
            *(uint2*)(Xp + rr * PW + lane * 8)       = make_uint2(h0, h1);
            *(uint2*)(Xp + rr * PW + 256 + lane * 8) = make_uint2(l0, l1);
        }
        CPWAIT(0);
        __syncthreads();
    } else {
        cpw(WHg, WLg, w1_mat, sW, tid);
        CP_COMMIT();
        ldgsplit_X64(X + (size_t)row0 * DD, Xp, tid);
        CPWAIT(0);
        __syncthreads();
    }

    // GEMM1: m = t @ W1 + b1
    #pragma unroll
    for (int i = 0; i < 2; i++)
        #pragma unroll
        for (int j = 0; j < 4; j++)
            #pragma unroll
            for (int q = 0; q < 4; q++) d[i][j][q] = 0.f;
    mma_blk<PW, 256, 8, 2>(sX, sW, wm, wn, lane, d);
    __syncthreads();                             // X & W reads done

    cpw(WHg, WLg, w2_mat, sW, tid);              // prefetch W2
    CP_COMMIT();

    // write m (gmem fp32) + resplit m into X tile
    #pragma unroll
    for (int mi = 0; mi < 2; mi++) {
        int R = wm * 32 + mi * 16 + (lane >> 2);
        #pragma unroll
        for (int ni = 0; ni < 4; ni++) {
            int C = wn * 32 + ni * 8 + (lane & 3) * 2;
            float b0 = bias1[C], b1 = bias1[C + 1];
            float v0 = d[mi][ni][0] + b0, v1 = d[mi][ni][1] + b1;
            float v2 = d[mi][ni][2] + b0, v3 = d[mi][ni][3] + b1;
            *(float2*)&Mout[(size_t)(row0 + R) * DD + C]     = make_float2(v0, v1);
            *(float2*)&Mout[(size_t)(row0 + R + 8) * DD + C] = make_float2(v2, v3);
            uint32_t h, l;
            split2(v0, v1, h, l);
            *(uint32_t*)(Xp + R * PW + C * 2)       = h;
            *(uint32_t*)(Xp + R * PW + 256 + C * 2) = l;
            split2(v2, v3, h, l);
            *(uint32_t*)(Xp + (R + 8) * PW + C * 2)       = h;
            *(uint32_t*)(Xp + (R + 8) * PW + 256 + C * 2) = l;
        }
    }
    CPWAIT(0);
    __syncthreads();

    // GEMM2: m2T[n][r] = sum_k W2n[n][k] * m[r][k]
    float e[2][4][4];
    #pragma unroll
    for (int i = 0; i < 2; i++)
        #pragma unroll
        for (int j = 0; j < 4; j++)
            #pragma unroll
            for (int q = 0; q < 4; q++) e[i][j][q] = 0.f;
    mma_blk<PW, 256, 8, 2>(sW, sX, wm2, wn2, lane, e);

    #pragma unroll
    for (int mi = 0; mi < 2; mi++) {
        int Rn = wm2 * 32 + mi * 16 + (lane >> 2);
        #pragma unroll
        for (int ni = 0; ni < 4; ni++) {
            int Cr = wn2 * 32 + ni * 8 + (lane & 3) * 2;
            uint32_t h, l;
            split2(e[mi][ni][0], e[mi][ni][1], h, l);
            size_t o = (((size_t)(bb * DD + Rn)) << 10) + rb + Cr;
            *(uint32_t*)(M2H + o) = h;
            *(uint32_t*)(M2L + o) = l;
            split2(e[mi][ni][2], e[mi][ni][3], h, l);
            size_t o2 = (((size_t)(bb * DD + Rn + 8)) << 10) + rb + Cr;
            *(uint32_t*)(M2H + o2) = h;
            *(uint32_t*)(M2L + o2) = l;
        }
    }
}

// ---------------------------------------------------------------------------
// Final projection: out = (t @ WprojT + bp) * mask
// ---------------------------------------------------------------------------
__global__ void __launch_bounds__(256, 2) proj_kernel(
    const float* __restrict__ X,
    const uint16_t* __restrict__ WHg, const uint16_t* __restrict__ WLg,
    const float* __restrict__ bp, const float* __restrict__ mask,
    float* __restrict__ out)
{
    extern __shared__ char smem[];
    const uint32_t sX = smem_u32(smem);
    const uint32_t sW = sX + XBYTES;
    const int tid = threadIdx.x, lane = tid & 31, wid = tid >> 5;
    const int wm = wid & 1, wn = wid >> 1;
    const int row0 = blockIdx.x * 64;

    cpw(WHg, WLg, 5, sW, tid);
    CP_COMMIT();
    ldgsplit_X64(X + (size_t)row0 * DD, smem, tid);
    CPWAIT(0);
    __syncthreads();

    float d[2][4][4];
    #pragma unroll
    for (int i = 0; i < 2; i++)
        #pragma unroll
        for (int j = 0; j < 4; j++)
            #pragma unroll
            for (int q = 0; q < 4; q++) d[i][j][q] = 0.f;
    mma_blk<PW, 256, 8, 2>(sX, sW, wm, wn, lane, d);

    #pragma unroll
    for (int mi = 0; mi < 2; mi++) {
        int R = wm * 32 + mi * 16 + (lane >> 2);
        float mk0 = mask[row0 + R];
        float mk1 = mask[row0 + R + 8];
        #pragma unroll
        for (int ni = 0; ni < 4; ni++) {
            int C = wn * 32 + ni * 8 + (lane & 3) * 2;
            float b0 = bp[C], b1 = bp[C + 1];
            *(float2*)&out[(size_t)(row0 + R) * DD + C] =
                make_float2((d[mi][ni][0] + b0) * mk0, (d[mi][ni][1] + b1) * mk0);
            *(float2*)&out[(size_t)(row0 + R + 8) * DD + C] =
                make_float2((d[mi][ni][2] + b0) * mk1, (d[mi][ni][3] + b1) * mk1);
        }
    }
}

// ---------------------------------------------------------------------------
// Big GEMM: 3-stage cp.async pipeline, merged hi||lo tiles (pitch 144).
// RACE-FIX ordering per chunk: wait(c) -> syncthreads -> issue(c+2) -> mma(c).
// The barrier both publishes chunk c and retires iteration c-1's readers,
// making the write into stage (c-1)%3 legal.
// ---------------------------------------------------------------------------
#define PAG    144
#define TILEA  18432                   // 128 * 144
#define STG_SZ (2 * TILEA)             // A + B per stage
#define AGG_SMEM (3 * STG_SZ)          // 110592 -> 2 CTAs/SM

__global__ void __launch_bounds__(256, 2) agg_mma(
    const uint16_t* __restrict__ AH, const uint16_t* __restrict__ AL,
    const uint16_t* __restrict__ BH, const uint16_t* __restrict__ BL,
    const float* __restrict__ M, const float* __restrict__ bagg,
    float* __restrict__ T)
{
    extern __shared__ char smem[];
    const uint32_t sb = smem_u32(smem);
    const int tid  = threadIdx.x;
    const int lane = tid & 31;
    const int wid  = tid >> 5;
    const int b    = blockIdx.y;
    const int row0 = blockIdx.x * 128;
    const int wm   = wid & 1;
    const int wn   = wid >> 1;

    const char* gAh = (const char*)(AH + (size_t)(b * NN + row0) * NN);
    const char* gAl = (const char*)(AL + (size_t)(b * NN + row0) * NN);
    const char* gBh = (const char*)(BH + (size_t)b * DD * NN);
    const char* gBl = (const char*)(BL + (size_t)b * DD * NN);

    const int r_ld = tid >> 2;          // 0..63
    const int q16  = (tid & 3) * 16;    // 16B chunk in 64B half-row

    float d[4][4][4];
    #pragma unroll
    for (int i = 0; i < 4; i++)
        #pragma unroll
        for (int j = 0; j < 4; j++)
            #pragma unroll
            for (int qq = 0; qq < 4; qq++) d[i][j][qq] = 0.f;

    auto issue = [&](int c, int s) {
        uint32_t base = sb + (uint32_t)s * STG_SZ;
        #pragma unroll
        for (int j = 0; j < 2; j++) {
            int r = r_ld + j * 64;
            uint32_t drow = (uint32_t)(r * PAG) + q16;
            size_t   soff = (size_t)r * 2048 + (size_t)c * 64 + q16;
            CP16(base + drow,              gAh + soff);
            CP16(base + drow + 64,         gAl + soff);
            CP16(base + TILEA + drow,      gBh + soff);
            CP16(base + TILEA + drow + 64, gBl + soff);
        }
        CP_COMMIT();
    };

    issue(0, 0);
    issue(1, 1);

    for (int c = 0; c < 32; c++) {
        // wait for chunk c data (per-thread), then publish + retire prior readers
        if (c < 31) { CPWAIT(1); } else { CPWAIT(0); }
        __syncthreads();
        // now safe: stage (c+2)%3 == (c-1)%3 has no remaining readers
        if (c + 2 < 32) issue(c + 2, (c + 2) % 3);
        uint32_t base = sb + (uint32_t)(c % 3) * STG_SZ;
        mma_blk<PAG, 64, 2, 4>(base, base + TILEA, wm, wn, lane, d);
    }
    __syncthreads();                    // drain readers of last stage

    // stage D to smem (f32, pitch 132)
    float* stg = (float*)smem;
    #pragma unroll
    for (int mi = 0; mi < 4; mi++) {
        int R = wm * 64 + mi * 16 + (lane >> 2);
        #pragma unroll
        for (int ni = 0; ni < 4; ni++) {
            int C = wn * 32 + ni * 8 + (lane & 3) * 2;
            *(float2*)&stg[R * 132 + C]       = make_float2(d[mi][ni][0], d[mi][ni][1]);
            *(float2*)&stg[(R + 8) * 132 + C] = make_float2(d[mi][ni][2], d[mi][ni][3]);
        }
    }
    __syncthreads();

    const float* Mb = M + ((size_t)b * NN + row0) * DD;
    float*       Tb = T + ((size_t)b * NN + row0) * DD;
    float4 bg = *(const float4*)&bagg[lane * 4];
    #pragma unroll
    for (int i = 0; i < 16; i++) {
        int rr = wid * 16 + i;
        float4 raw = *(const float4*)&stg[rr * 132 + lane * 4];
        float4 mm  = *(const float4*)&Mb[(size_t)rr * DD + lane * 4];
        float v0 = fmaxf(raw.x + mm.x + bg.x, 0.f);
        float v1 = fmaxf(raw.y + mm.y + bg.y, 0.f);
        float v2 = fmaxf(raw.z + mm.z + bg.z, 0.f);
        float v3 = fmaxf(raw.w + mm.w + bg.w, 0.f);
        float ss = v0*v0 + v1*v1 + v2*v2 + v3*v3;
        #pragma unroll
        for (int o = 16; o > 0; o >>= 1)
            ss += __shfl_xor_sync(0xffffffffu, ss, o);
        float s = hyp_scale(sqrtf(ss));
        *(float4*)&Tb[(size_t)rr * DD + lane * 4] =
            make_float4(v0 * s, v1 * s, v2 * s, v3 * s);
    }
}

// ---------------------------------------------------------------------------
// Host launch
// ---------------------------------------------------------------------------
extern "C" void kernel_launch(void* const* d_in, const int* in_sizes, int n_in,
                              void* d_out, int out_size)
{
    const float* nf    = (const float*)d_in[0];
    const float* adj   = (const float*)d_in[1];
    const float* mask  = (const float*)d_in[2];
    const float* Wemb  = (const float*)d_in[3];
    const float* Wmsg  = (const float*)d_in[4];
    const float* bmsg  = (const float*)d_in[5];
    const float* Wagg  = (const float*)d_in[6];
    const float* bagg  = (const float*)d_in[7];
    const float* Wproj = (const float*)d_in[8];
    const float* bproj = (const float*)d_in[9];
    float* out = (float*)d_out;

    float *t, *m;
    uint16_t *ah, *al, *m2h, *m2l, *wh, *wl;
    cudaGetSymbolAddress((void**)&t,   g_t);
    cudaGetSymbolAddress((void**)&m,   g_m);
    cudaGetSymbolAddress((void**)&ah,  g_ah);
    cudaGetSymbolAddress((void**)&al,  g_al);
    cudaGetSymbolAddress((void**)&m2h, g_m2h);
    cudaGetSymbolAddress((void**)&m2l, g_m2l);
    cudaGetSymbolAddress((void**)&wh,  g_wh);
    cudaGetSymbolAddress((void**)&wl,  g_wl);

    cudaFuncSetAttribute(agg_mma, cudaFuncAttributeMaxDynamicSharedMemorySize, AGG_SMEM);
    cudaFuncSetAttribute(chain_kernel<true>,  cudaFuncAttributeMaxDynamicSharedMemorySize, LIN_SMEM);
    cudaFuncSetAttribute(chain_kernel<false>, cudaFuncAttributeMaxDynamicSharedMemorySize, LIN_SMEM);
    cudaFuncSetAttribute(proj_kernel, cudaFuncAttributeMaxDynamicSharedMemorySize, LIN_SMEM);

    dim3 glin(ROWS / 64);          // 512
    dim3 gbig(NN / 128, BATCH);    // 8 x 32

    split_adj<<<(BATCH * NN * NN / 4) / 256, 256>>>((const float4*)adj,
                                                    (uint2*)ah, (uint2*)al);
    split_weights<<<6, 256>>>(Wemb, Wmsg, Wagg, Wproj, wh, wl);

    // layer 0: embed + hyp + msg + m2 fused
    chain_kernel<true><<<glin, 256, LIN_SMEM>>>(nf, wh, wl, 0, 1, 2,
                                                bmsg, m, m2h, m2l);
    agg_mma<<<gbig, 256, AGG_SMEM>>>(ah, al, m2h, m2l, m, bagg, t);

    // layer 1: msg + m2 fused
    chain_kernel<false><<<glin, 256, LIN_SMEM>>>(t, wh, wl, 0, 3, 4,
                                                 bmsg + DD, m, m2h, m2l);
    agg_mma<<<gbig, 256, AGG_SMEM>>>(ah, al, m2h, m2l, m, bagg + DD, t);

    // out = (t @ WprojT + bproj) * mask
    proj_kernel<<<glin, 256, LIN_SMEM>>>(t, wh, wl, bproj, mask, out);
}

// round 7
// speedup vs baseline: 1.8585x; 1.0466x over previous
#include <cuda_runtime.h>
#include <math.h>
#include <stdint.h>

// Problem constants
#define BATCH 32
#define NN    1024
#define DD    128
#define ROWS  (BATCH * NN)   // 32768

// Scratch (device globals — no allocation allowed)
__device__ float g_t[ROWS * DD];
__device__ float g_m[ROWS * DD];
__device__ __align__(16) uint16_t g_ah[(size_t)BATCH * NN * NN];   // adj bf16 hi
__device__ __align__(16) uint16_t g_al[(size_t)BATCH * NN * NN];   // adj bf16 lo
__device__ __align__(16) uint16_t g_m2h[(size_t)BATCH * DD * NN];  // m2^T hi [b][n][k]
__device__ __align__(16) uint16_t g_m2l[(size_t)BATCH * DD * NN];  // m2^T lo
__device__ __align__(16) uint16_t g_wh[6 * DD * DD];               // weights hi [n][k]
__device__ __align__(16) uint16_t g_wl[6 * DD * DD];               // weights lo

// ---------------------------------------------------------------------------
// Helpers
// ---------------------------------------------------------------------------
__device__ __forceinline__ uint32_t smem_u32(const void* p) {
    uint32_t a;
    asm("{ .reg .u64 t; cvta.to.shared.u64 t, %1; cvt.u32.u64 %0, t; }" : "=r"(a) : "l"(p));
    return a;
}
__device__ __forceinline__ uint32_t pack_bf16x2(float v0, float v1) {
    uint32_t r;
    asm("cvt.rn.bf16x2.f32 %0, %1, %2;" : "=r"(r) : "f"(v1), "f"(v0));
    return r;
}
__device__ __forceinline__ void split2(float v0, float v1, uint32_t& h, uint32_t& l) {
    h = pack_bf16x2(v0, v1);
    float r0 = v0 - __uint_as_float(h << 16);
    float r1 = v1 - __uint_as_float(h & 0xffff0000u);
    l = pack_bf16x2(r0, r1);
}
#define CP16(dst, src) \
    asm volatile("cp.async.cg.shared.global [%0], [%1], 16;" :: "r"(dst), "l"(src) : "memory")
#define CP_COMMIT() asm volatile("cp.async.commit_group;" ::: "memory")
#define CPWAIT(n)   asm volatile("cp.async.wait_group %0;" :: "n"(n) : "memory")

#define LDSM4(r0, r1, r2, r3, addr) \
    asm volatile("ldmatrix.sync.aligned.m8n8.x4.shared.b16 {%0,%1,%2,%3}, [%4];" \
        : "=r"(r0), "=r"(r1), "=r"(r2), "=r"(r3) : "r"(addr))

__device__ __forceinline__ void mma_bf16(float d[4], const uint32_t a[4],
                                         uint32_t b0, uint32_t b1) {
    asm volatile(
        "mma.sync.aligned.m16n8k16.row.col.f32.bf16.bf16.f32 "
        "{%0,%1,%2,%3}, {%4,%5,%6,%7}, {%8,%9}, {%0,%1,%2,%3};"
        : "+f"(d[0]), "+f"(d[1]), "+f"(d[2]), "+f"(d[3])
        : "r"(a[0]), "r"(a[1]), "r"(a[2]), "r"(a[3]), "r"(b0), "r"(b1));
}

// Composite per-row scale: logmap0(proj(expmap0(h))) = s(||h||) * h
__device__ __forceinline__ float hyp_scale(float n) {
    const float EPS  = 1e-7f;
    const float MAXN = 1.0f - 1e-5f;
    float n1 = fmaxf(n, EPS);
    float r  = tanhf(n1) / n1;
    float xn = r * n;
    float n2 = fmaxf(xn, EPS);
    float s2 = (n2 > MAXN) ? (MAXN / n2) : 1.0f;
    float x2 = s2 * xn;
    float n3 = fmaxf(x2, EPS);
    float z  = fminf(n3, 1.0f - EPS);
    float lg = atanhf(z) / n3;
    return r * s2 * lg;
}

// ---------------------------------------------------------------------------
// Warp-tile MMA block over merged hi/lo smem tiles — ldmatrix fragment loads.
//   A-frag: ldmatrix.x4 per (mi, hi/lo). B-frag: one x4 gives hi AND lo.
//   Bit-identical data path to scalar loads; 4x fewer shared ops.
// ---------------------------------------------------------------------------
template<int PITCH, int LOOFF, int NKS, int MI>
__device__ __forceinline__ void mma_blk(uint32_t Ab, uint32_t Bb,
                                        int wma, int wnb, int lane,
                                        float (&d)[MI][4][4]) {
    const int lg = lane >> 3;            // 8-lane group 0..3
    const int lr = lane & 7;
    // A x4 tile order: (m0-7,k0) (m8-15,k0) (m0-7,k+16B) (m8-15,k+16B)
    const uint32_t aBase = Ab + (uint32_t)((wma * (MI * 16) + (lg & 1) * 8 + lr) * PITCH
                                           + (lg >> 1) * 16);
    // B x4 tile order: (n0-7 hi,k0) (hi,k+16B) (lo,k0) (lo,k+16B)
    const uint32_t bBase = Bb + (uint32_t)((wnb * 32 + lr) * PITCH + (lg & 1) * 16
                                           + ((lg >> 1) ? LOOFF : 0));
    #pragma unroll
    for (int ks = 0; ks < NKS; ks++) {
        const uint32_t kb = (uint32_t)ks * 32;
        uint32_t bh[4][2], bl[4][2];
        #pragma unroll
        for (int ni = 0; ni < 4; ni++)
            LDSM4(bh[ni][0], bh[ni][1], bl[ni][0], bl[ni][1],
                  bBase + ni * 8 * PITCH + kb);
        #pragma unroll
        for (int mi = 0; mi < MI; mi++) {
            uint32_t ah[4], al[4];
            LDSM4(ah[0], ah[1], ah[2], ah[3], aBase + mi * 16 * PITCH + kb);
            LDSM4(al[0], al[1], al[2], al[3], aBase + mi * 16 * PITCH + kb + LOOFF);
            #pragma unroll
            for (int ni = 0; ni < 4; ni++) {
                mma_bf16(d[mi][ni], ah, bh[ni][0], bh[ni][1]);
                mma_bf16(d[mi][ni], ah, bl[ni][0], bl[ni][1]);
                mma_bf16(d[mi][ni], al, bh[ni][0], bh[ni][1]);
            }
        }
    }
}

// ---------------------------------------------------------------------------
// One-time adjacency split: fp32 -> bf16 hi/lo
// ---------------------------------------------------------------------------
__global__ void __launch_bounds__(256) split_adj(const float4* __restrict__ a,
                                                 uint2* __restrict__ h,
                                                 uint2* __restrict__ l) {
    int i = blockIdx.x * 256 + threadIdx.x;
    float4 v = a[i];
    uint32_t h0, l0, h1, l1;
    split2(v.x, v.y, h0, l0);
    split2(v.z, v.w, h1, l1);
    h[i] = make_uint2(h0, h1);
    l[i] = make_uint2(l0, l1);
}

// ---------------------------------------------------------------------------
// One-time weight split into [n][k] bf16 hi/lo. mats: 0=emb,1=msg0,2=agg0,
// 3=msg1,4=agg1,5=proj. emb/proj stored [n][k] already; msg/agg are [k][n].
// ---------------------------------------------------------------------------
__global__ void __launch_bounds__(256) split_weights(
    const float* __restrict__ Wemb, const float* __restrict__ Wmsg,
    const float* __restrict__ Wagg, const float* __restrict__ Wproj,
    uint16_t* __restrict__ WH, uint16_t* __restrict__ WL)
{
    int mat = blockIdx.x;
    const float* src;
    bool trans;
    switch (mat) {
        case 0:  src = Wemb;            trans = false; break;
        case 1:  src = Wmsg;            trans = true;  break;
        case 2:  src = Wagg;            trans = true;  break;
        case 3:  src = Wmsg + DD * DD;  trans = true;  break;
        case 4:  src = Wagg + DD * DD;  trans = true;  break;
        default: src = Wproj;           trans = false; break;
    }
    for (int idx = threadIdx.x; idx < DD * DD; idx += 256) {
        int n = idx >> 7, k = idx & 127;
        float v = trans ? src[k * DD + n] : src[idx];
        uint32_t p = pack_bf16x2(v, 0.f);
        uint16_t hh = (uint16_t)(p & 0xffffu);
        float r = v - __uint_as_float((uint32_t)hh << 16);
        uint32_t pl = pack_bf16x2(r, 0.f);
        WH[mat * DD * DD + idx] = hh;
        WL[mat * DD * DD + idx] = (uint16_t)(pl & 0xffffu);
    }
}

// ---------------------------------------------------------------------------
// Chain / proj smem layout: merged hi||lo rows, pitch 528 (bank = 4r+c).
// ---------------------------------------------------------------------------
#define PW 528
#define XBYTES (64 * PW)
#define WBYTES (128 * PW)
#define LIN_SMEM (XBYTES + WBYTES)    // 101376 -> 2 CTAs/SM

// LDG 64x128 fp32 rows (stride 128) -> split bf16 hi/lo into X tile
__device__ __forceinline__ void ldgsplit_X64(const float* __restrict__ g,
                                             char* X, int tid) {
    int row = tid >> 2;
    int c0  = (tid & 3) * 32;
    const float* gp = g + (size_t)row * DD + c0;
    char* ph = X + row * PW + c0 * 2;
    char* pl = ph + 256;
    #pragma unroll
    for (int i = 0; i < 8; i++) {
        float4 v = *(const float4*)(gp + i * 4);
        uint32_t h0, l0, h1, l1;
        split2(v.x, v.y, h0, l0);
        split2(v.z, v.w, h1, l1);
        *(uint2*)(ph + i * 8) = make_uint2(h0, h1);
        *(uint2*)(pl + i * 8) = make_uint2(l0, l1);
    }
}

// cp.async a pre-split weight matrix (mat) into W tile
__device__ __forceinline__ void cpw(const uint16_t* __restrict__ WHg,
                                    const uint16_t* __restrict__ WLg,
                                    int mat, uint32_t wbase, int tid) {
    int n = tid >> 1, half = tid & 1;
    const char* src = (const char*)((half ? WLg : WHg) + (size_t)mat * DD * DD + n * DD);
    uint32_t dst = wbase + (uint32_t)(n * PW + half * 256);
    #pragma unroll
    for (int q = 0; q < 16; q++)
        CP16(dst + q * 16, src + q * 16);
}

// ---------------------------------------------------------------------------
// Fused chain kernel (64-row tiles, 512 CTAs, 2 CTA/SM)
// ---------------------------------------------------------------------------
template<bool FIRST>
__global__ void __launch_bounds__(256, 2) chain_kernel(
    const float* __restrict__ X,
    const uint16_t* __restrict__ WHg, const uint16_t* __restrict__ WLg,
    int emb_mat, int w1_mat, int w2_mat,
    const float* __restrict__ bias1,
    float* __restrict__ Mout,
    uint16_t* __restrict__ M2H, uint16_t* __restrict__ M2L)
{
    extern __shared__ char smem[];
    const uint32_t sX = smem_u32(smem);
    const uint32_t sW = sX + XBYTES;
    char* Xp = smem;

    const int tid = threadIdx.x, lane = tid & 31, wid = tid >> 5;
    const int wm = wid & 1, wn = wid >> 1;      // GEMM0/1: M=64,N=128
    const int wm2 = wid & 3, wn2 = wid >> 2;    // GEMM2:   M=128,N=64
    const int row0 = blockIdx.x * 64;
    const int bb = row0 >> 10;
    const int rb = row0 & 1023;

    float d[2][4][4];

    if (FIRST) {
        cpw(WHg, WLg, emb_mat, sW, tid);
        CP_COMMIT();
        ldgsplit_X64(X + (size_t)row0 * DD, Xp, tid);
        CPWAIT(0);
        __syncthreads();

        #pragma unroll
        for (int i = 0; i < 2; i++)
            #pragma unroll
            for (int j = 0; j < 4; j++)
                #pragma unroll
                for (int q = 0; q < 4; q++) d[i][j][q] = 0.f;
        mma_blk<PW, 256, 8, 2>(sX, sW, wm, wn, lane, d);
        __syncthreads();                         // X & W reads done

        cpw(WHg, WLg, w1_mat, sW, tid);          // prefetch W1
        CP_COMMIT();

        // stage h f32 into X region (pitch 132 floats)
        float* stg = (float*)Xp;
        #pragma unroll
        for (int mi = 0; mi < 2; mi++) {
            int R = wm * 32 + mi * 16 + (lane >> 2);
            #pragma unroll
            for (int ni = 0; ni < 4; ni++) {
                int C = wn * 32 + ni * 8 + (lane & 3) * 2;
                stg[R * 132 + C]           = d[mi][ni][0];
                stg[R * 132 + C + 1]       = d[mi][ni][1];
                stg[(R + 8) * 132 + C]     = d[mi][ni][2];
                stg[(R + 8) * 132 + C + 1] = d[mi][ni][3];
            }
        }
        __syncthreads();

        // hyp rows (8 rows per warp), resplit into X tile in place
        #pragma unroll
        for (int i = 0; i < 8; i++) {
            int rr = wid * 8 + i;
            float4 v = *(float4*)&stg[rr * 132 + lane * 4];
            float ss = v.x * v.x + v.y * v.y + v.z * v.z + v.w * v.w;
            #pragma unroll
            for (int o = 16; o > 0; o >>= 1)
                ss += __shfl_xor_sync(0xffffffffu, ss, o);
            float s = hyp_scale(sqrtf(ss));
            v.x *= s; v.y *= s; v.z *= s; v.w *= s;
            __syncwarp();
            uint32_t h0, l0, h1, l1;
            split2(v.x, v.y, h0, l0);
            split2(v.z, v.w, h1, l1);
            *(uint2*)(Xp + rr * PW + lane * 8)       = make_uint2(h0, h1);
            *(uint2*)(Xp + rr * PW + 256 + lane * 8) = make_uint2(l0, l1);
        }
        CPWAIT(0);
        __syncthreads();
    } else {
        cpw(WHg, WLg, w1_mat, sW, tid);
        CP_COMMIT();
        ldgsplit_X64(X + (size_t)row0 * DD, Xp, tid);
        CPWAIT(0);
        __syncthreads();
    }

    // GEMM1: m = t @ W1 + b1
    #pragma unroll
    for (int i = 0; i < 2; i++)
        #pragma unroll
        for (int j = 0; j < 4; j++)
            #pragma unroll
            for (int q = 0; q < 4; q++) d[i][j][q] = 0.f;
    mma_blk<PW, 256, 8, 2>(sX, sW, wm, wn, lane, d);
    __syncthreads();                             // X & W reads done

    cpw(WHg, WLg, w2_mat, sW, tid);              // prefetch W2
    CP_COMMIT();

    // write m (gmem fp32) + resplit m into X tile
    #pragma unroll
    for (int mi = 0; mi < 2; mi++) {
        int R = wm * 32 + mi * 16 + (lane >> 2);
        #pragma unroll
        for (int ni = 0; ni < 4; ni++) {
            int C = wn * 32 + ni * 8 + (lane & 3) * 2;
            float b0 = bias1[C], b1 = bias1[C + 1];
            float v0 = d[mi][ni][0] + b0, v1 = d[mi][ni][1] + b1;
            float v2 = d[mi][ni][2] + b0, v3 = d[mi][ni][3] + b1;
            *(float2*)&Mout[(size_t)(row0 + R) * DD + C]     = make_float2(v0, v1);
            *(float2*)&Mout[(size_t)(row0 + R + 8) * DD + C] = make_float2(v2, v3);
            uint32_t h, l;
            split2(v0, v1, h, l);
            *(uint32_t*)(Xp + R * PW + C * 2)       = h;
            *(uint32_t*)(Xp + R * PW + 256 + C * 2) = l;
            split2(v2, v3, h, l);
            *(uint32_t*)(Xp + (R + 8) * PW + C * 2)       = h;
            *(uint32_t*)(Xp + (R + 8) * PW + 256 + C * 2) = l;
        }
    }
    CPWAIT(0);
    __syncthreads();

    // GEMM2: m2T[n][r] = sum_k W2n[n][k] * m[r][k]
    float e[2][4][4];
    #pragma unroll
    for (int i = 0; i < 2; i++)
        #pragma unroll
        for (int j = 0; j < 4; j++)
            #pragma unroll
            for (int q = 0; q < 4; q++) e[i][j][q] = 0.f;
    mma_blk<PW, 256, 8, 2>(sW, sX, wm2, wn2, lane, e);

    #pragma unroll
    for (int mi = 0; mi < 2; mi++) {
        int Rn = wm2 * 32 + mi * 16 + (lane >> 2);
        #pragma unroll
        for (int ni = 0; ni < 4; ni++) {
            int Cr = wn2 * 32 + ni * 8 + (lane & 3) * 2;
            uint32_t h, l;
            split2(e[mi][ni][0], e[mi][ni][1], h, l);
            size_t o = (((size_t)(bb * DD + Rn)) << 10) + rb + Cr;
            *(uint32_t*)(M2H + o) = h;
            *(uint32_t*)(M2L + o) = l;
            split2(e[mi][ni][2], e[mi][ni][3], h, l);
            size_t o2 = (((size_t)(bb * DD + Rn + 8)) << 10) + rb + Cr;
            *(uint32_t*)(M2H + o2) = h;
            *(uint32_t*)(M2L + o2) = l;
        }
    }
}

// ---------------------------------------------------------------------------
// Final projection: out = (t @ WprojT + bp) * mask
// ---------------------------------------------------------------------------
__global__ void __launch_bounds__(256, 2) proj_kernel(
    const float* __restrict__ X,
    const uint16_t* __restrict__ WHg, const uint16_t* __restrict__ WLg,
    const float* __restrict__ bp, const float* __restrict__ mask,
    float* __restrict__ out)
{
    extern __shared__ char smem[];
    const uint32_t sX = smem_u32(smem);
    const uint32_t sW = sX + XBYTES;
    const int tid = threadIdx.x, lane = tid & 31, wid = tid >> 5;
    const int wm = wid & 1, wn = wid >> 1;
    const int row0 = blockIdx.x * 64;

    cpw(WHg, WLg, 5, sW, tid);
    CP_COMMIT();
    ldgsplit_X64(X + (size_t)row0 * DD, smem, tid);
    CPWAIT(0);
    __syncthreads();

    float d[2][4][4];
    #pragma unroll
    for (int i = 0; i < 2; i++)
        #pragma unroll
        for (int j = 0; j < 4; j++)
            #pragma unroll
            for (int q = 0; q < 4; q++) d[i][j][q] = 0.f;
    mma_blk<PW, 256, 8, 2>(sX, sW, wm, wn, lane, d);

    #pragma unroll
    for (int mi = 0; mi < 2; mi++) {
        int R = wm * 32 + mi * 16 + (lane >> 2);
        float mk0 = mask[row0 + R];
        float mk1 = mask[row0 + R + 8];
        #pragma unroll
        for (int ni = 0; ni < 4; ni++) {
            int C = wn * 32 + ni * 8 + (lane & 3) * 2;
            float b0 = bp[C], b1 = bp[C + 1];
            *(float2*)&out[(size_t)(row0 + R) * DD + C] =
                make_float2((d[mi][ni][0] + b0) * mk0, (d[mi][ni][1] + b1) * mk0);
            *(float2*)&out[(size_t)(row0 + R + 8) * DD + C] =
                make_float2((d[mi][ni][2] + b0) * mk1, (d[mi][ni][3] + b1) * mk1);
        }
    }
}

// ---------------------------------------------------------------------------
// Big GEMM: 3-stage cp.async pipeline, merged hi||lo tiles (pitch 144).
// Ordering per chunk: wait(c) -> syncthreads -> issue(c+2) -> mma(c).
// ---------------------------------------------------------------------------
#define PAG    144
#define TILEA  18432                   // 128 * 144
#define STG_SZ (2 * TILEA)             // A + B per stage
#define AGG_SMEM (3 * STG_SZ)          // 110592 -> 2 CTAs/SM

__global__ void __launch_bounds__(256, 2) agg_mma(
    const uint16_t* __restrict__ AH, const uint16_t* __restrict__ AL,
    const uint16_t* __restrict__ BH, const uint16_t* __restrict__ BL,
    const float* __restrict__ M, const float* __restrict__ bagg,
    float* __restrict__ T)
{
    extern __shared__ char smem[];
    const uint32_t sb = smem_u32(smem);
    const int tid  = threadIdx.x;
    const int lane = tid & 31;
    const int wid  = tid >> 5;
    const int b    = blockIdx.y;
    const int row0 = blockIdx.x * 128;
    const int wm   = wid & 1;
    const int wn   = wid >> 1;

    const char* gAh = (const char*)(AH + (size_t)(b * NN + row0) * NN);
    const char* gAl = (const char*)(AL + (size_t)(b * NN + row0) * NN);
    const char* gBh = (const char*)(BH + (size_t)b * DD * NN);
    const char* gBl = (const char*)(BL + (size_t)b * DD * NN);

    const int r_ld = tid >> 2;          // 0..63
    const int q16  = (tid & 3) * 16;    // 16B chunk in 64B half-row

    float d[4][4][4];
    #pragma unroll
    for (int i = 0; i < 4; i++)
        #pragma unroll
        for (int j = 0; j < 4; j++)
            #pragma unroll
            for (int qq = 0; qq < 4; qq++) d[i][j][qq] = 0.f;

    auto issue = [&](int c, int s) {
        uint32_t base = sb + (uint32_t)s * STG_SZ;
        #pragma unroll
        for (int j = 0; j < 2; j++) {
            int r = r_ld + j * 64;
            uint32_t drow = (uint32_t)(r * PAG) + q16;
            size_t   soff = (size_t)r * 2048 + (size_t)c * 64 + q16;
            CP16(base + drow,              gAh + soff);
            CP16(base + drow + 64,         gAl + soff);
            CP16(base + TILEA + drow,      gBh + soff);
            CP16(base + TILEA + drow + 64, gBl + soff);
        }
        CP_COMMIT();
    };

    issue(0, 0);
    issue(1, 1);

    for (int c = 0; c < 32; c++) {
        // wait for chunk c data, then publish + retire prior readers
        if (c < 31) { CPWAIT(1); } else { CPWAIT(0); }
        __syncthreads();
        // safe: stage (c+2)%3 == (c-1)%3 has no remaining readers
        if (c + 2 < 32) issue(c + 2, (c + 2) % 3);
        uint32_t base = sb + (uint32_t)(c % 3) * STG_SZ;
        mma_blk<PAG, 64, 2, 4>(base, base + TILEA, wm, wn, lane, d);
    }
    __syncthreads();                    // drain readers of last stage

    // stage D to smem (f32, pitch 132)
    float* stg = (float*)smem;
    #pragma unroll
    for (int mi = 0; mi < 4; mi++) {
        int R = wm * 64 + mi * 16 + (lane >> 2);
        #pragma unroll
        for (int ni = 0; ni < 4; ni++) {
            int C = wn * 32 + ni * 8 + (lane & 3) * 2;
            *(float2*)&stg[R * 132 + C]       = make_float2(d[mi][ni][0], d[mi][ni][1]);
            *(float2*)&stg[(R + 8) * 132 + C] = make_float2(d[mi][ni][2], d[mi][ni][3]);
        }
    }
    __syncthreads();

    const float* Mb = M + ((size_t)b * NN + row0) * DD;
    float*       Tb = T + ((size_t)b * NN + row0) * DD;
    float4 bg = *(const float4*)&bagg[lane * 4];
    #pragma unroll
    for (int i = 0; i < 16; i++) {
        int rr = wid * 16 + i;
        float4 raw = *(const float4*)&stg[rr * 132 + lane * 4];
        float4 mm  = *(const float4*)&Mb[(size_t)rr * DD + lane * 4];
        float v0 = fmaxf(raw.x + mm.x + bg.x, 0.f);
        float v1 = fmaxf(raw.y + mm.y + bg.y, 0.f);
        float v2 = fmaxf(raw.z + mm.z + bg.z, 0.f);
        float v3 = fmaxf(raw.w + mm.w + bg.w, 0.f);
        float ss = v0*v0 + v1*v1 + v2*v2 + v3*v3;
        #pragma unroll
        for (int o = 16; o > 0; o >>= 1)
            ss += __shfl_xor_sync(0xffffffffu, ss, o);
        float s = hyp_scale(sqrtf(ss));
        *(float4*)&Tb[(size_t)rr * DD + lane * 4] =
            make_float4(v0 * s, v1 * s, v2 * s, v3 * s);
    }
}

// ---------------------------------------------------------------------------
// Host launch
// ---------------------------------------------------------------------------
extern "C" void kernel_launch(void* const* d_in, const int* in_sizes, int n_in,
                              void* d_out, int out_size)
{
    const float* nf    = (const float*)d_in[0];
    const float* adj   = (const float*)d_in[1];
    const float* mask  = (const float*)d_in[2];
    const float* Wemb  = (const float*)d_in[3];
    const float* Wmsg  = (const float*)d_in[4];
    const float* bmsg  = (const float*)d_in[5];
    const float* Wagg  = (const float*)d_in[6];
    const float* bagg  = (const float*)d_in[7];
    const float* Wproj = (const float*)d_in[8];
    const float* bproj = (const float*)d_in[9];
    float* out = (float*)d_out;

    float *t, *m;
    uint16_t *ah, *al, *m2h, *m2l, *wh, *wl;
    cudaGetSymbolAddress((void**)&t,   g_t);
    cudaGetSymbolAddress((void**)&m,   g_m);
    cudaGetSymbolAddress((void**)&ah,  g_ah);
    cudaGetSymbolAddress((void**)&al,  g_al);
    cudaGetSymbolAddress((void**)&m2h, g_m2h);
    cudaGetSymbolAddress((void**)&m2l, g_m2l);
    cudaGetSymbolAddress((void**)&wh,  g_wh);
    cudaGetSymbolAddress((void**)&wl,  g_wl);

    cudaFuncSetAttribute(agg_mma, cudaFuncAttributeMaxDynamicSharedMemorySize, AGG_SMEM);
    cudaFuncSetAttribute(chain_kernel<true>,  cudaFuncAttributeMaxDynamicSharedMemorySize, LIN_SMEM);
    cudaFuncSetAttribute(chain_kernel<false>, cudaFuncAttributeMaxDynamicSharedMemorySize, LIN_SMEM);
    cudaFuncSetAttribute(proj_kernel, cudaFuncAttributeMaxDynamicSharedMemorySize, LIN_SMEM);

    dim3 glin(ROWS / 64);          // 512
    dim3 gbig(NN / 128, BATCH);    // 8 x 32

    split_adj<<<(BATCH * NN * NN / 4) / 256, 256>>>((const float4*)adj,
                                                    (uint2*)ah, (uint2*)al);
    split_weights<<<6, 256>>>(Wemb, Wmsg, Wagg, Wproj, wh, wl);

    // layer 0: embed + hyp + msg + m2 fused
    chain_kernel<true><<<glin, 256, LIN_SMEM>>>(nf, wh, wl, 0, 1, 2,
                                                bmsg, m, m2h, m2l);
    agg_mma<<<gbig, 256, AGG_SMEM>>>(ah, al, m2h, m2l, m, bagg, t);

    // layer 1: msg + m2 fused
    chain_kernel<false><<<glin, 256, LIN_SMEM>>>(t, wh, wl, 0, 3, 4,
                                                 bmsg + DD, m, m2h, m2l);
    agg_mma<<<gbig, 256, AGG_SMEM>>>(ah, al, m2h, m2l, m, bagg + DD, t);

    // out = (t @ WprojT + bproj) * mask
    proj_kernel<<<glin, 256, LIN_SMEM>>>(t, wh, wl, bproj, mask, out);
}

// round 8
// speedup vs baseline: 1.9326x; 1.0399x over previous
#include <cuda_runtime.h>
#include <math.h>
#include <stdint.h>

// Problem constants
#define BATCH 32
#define NN    1024
#define DD    128
#define ROWS  (BATCH * NN)   // 32768

// Scratch (device globals — no allocation allowed)
__device__ float g_t[ROWS * DD];
__device__ float g_m[ROWS * DD];
__device__ __align__(16) uint16_t g_ah[(size_t)BATCH * NN * NN];   // adj bf16 hi
__device__ __align__(16) uint16_t g_m2h[(size_t)BATCH * DD * NN];  // m2^T hi [b][n][k]
__device__ __align__(16) uint16_t g_m2l[(size_t)BATCH * DD * NN];  // m2^T lo
__device__ __align__(16) uint16_t g_wh[6 * DD * DD];               // weights hi [n][k]
__device__ __align__(16) uint16_t g_wl[6 * DD * DD];               // weights lo

// ---------------------------------------------------------------------------
// Helpers
// ---------------------------------------------------------------------------
__device__ __forceinline__ uint32_t smem_u32(const void* p) {
    uint32_t a;
    asm("{ .reg .u64 t; cvta.to.shared.u64 t, %1; cvt.u32.u64 %0, t; }" : "=r"(a) : "l"(p));
    return a;
}
__device__ __forceinline__ uint32_t pack_bf16x2(float v0, float v1) {
    uint32_t r;
    asm("cvt.rn.bf16x2.f32 %0, %1, %2;" : "=r"(r) : "f"(v1), "f"(v0));
    return r;
}
__device__ __forceinline__ void split2(float v0, float v1, uint32_t& h, uint32_t& l) {
    h = pack_bf16x2(v0, v1);
    float r0 = v0 - __uint_as_float(h << 16);
    float r1 = v1 - __uint_as_float(h & 0xffff0000u);
    l = pack_bf16x2(r0, r1);
}
#define CP16(dst, src) \
    asm volatile("cp.async.cg.shared.global [%0], [%1], 16;" :: "r"(dst), "l"(src) : "memory")
#define CP_COMMIT() asm volatile("cp.async.commit_group;" ::: "memory")
#define CPWAIT(n)   asm volatile("cp.async.wait_group %0;" :: "n"(n) : "memory")

#define LDSM4(r0, r1, r2, r3, addr) \
    asm volatile("ldmatrix.sync.aligned.m8n8.x4.shared.b16 {%0,%1,%2,%3}, [%4];" \
        : "=r"(r0), "=r"(r1), "=r"(r2), "=r"(r3) : "r"(addr))

__device__ __forceinline__ void mma_bf16(float d[4], const uint32_t a[4],
                                         uint32_t b0, uint32_t b1) {
    asm volatile(
        "mma.sync.aligned.m16n8k16.row.col.f32.bf16.bf16.f32 "
        "{%0,%1,%2,%3}, {%4,%5,%6,%7}, {%8,%9}, {%0,%1,%2,%3};"
        : "+f"(d[0]), "+f"(d[1]), "+f"(d[2]), "+f"(d[3])
        : "r"(a[0]), "r"(a[1]), "r"(a[2]), "r"(a[3]), "r"(b0), "r"(b1));
}

// Composite per-row scale: logmap0(proj(expmap0(h))) = s(||h||) * h
__device__ __forceinline__ float hyp_scale(float n) {
    const float EPS  = 1e-7f;
    const float MAXN = 1.0f - 1e-5f;
    float n1 = fmaxf(n, EPS);
    float r  = tanhf(n1) / n1;
    float xn = r * n;
    float n2 = fmaxf(xn, EPS);
    float s2 = (n2 > MAXN) ? (MAXN / n2) : 1.0f;
    float x2 = s2 * xn;
    float n3 = fmaxf(x2, EPS);
    float z  = fminf(n3, 1.0f - EPS);
    float lg = atanhf(z) / n3;
    return r * s2 * lg;
}

// ---------------------------------------------------------------------------
// 3-product warp-tile MMA over merged hi/lo smem tiles (chain/proj kernels).
// ---------------------------------------------------------------------------
template<int PITCH, int LOOFF, int NKS, int MI>
__device__ __forceinline__ void mma_blk(uint32_t Ab, uint32_t Bb,
                                        int wma, int wnb, int lane,
                                        float (&d)[MI][4][4]) {
    const int lg = lane >> 3;
    const int lr = lane & 7;
    const uint32_t aBase = Ab + (uint32_t)((wma * (MI * 16) + (lg & 1) * 8 + lr) * PITCH
                                           + (lg >> 1) * 16);
    const uint32_t bBase = Bb + (uint32_t)((wnb * 32 + lr) * PITCH + (lg & 1) * 16
                                           + ((lg >> 1) ? LOOFF : 0));
    #pragma unroll
    for (int ks = 0; ks < NKS; ks++) {
        const uint32_t kb = (uint32_t)ks * 32;
        uint32_t bh[4][2], bl[4][2];
        #pragma unroll
        for (int ni = 0; ni < 4; ni++)
            LDSM4(bh[ni][0], bh[ni][1], bl[ni][0], bl[ni][1],
                  bBase + ni * 8 * PITCH + kb);
        #pragma unroll
        for (int mi = 0; mi < MI; mi++) {
            uint32_t ah[4], al[4];
            LDSM4(ah[0], ah[1], ah[2], ah[3], aBase + mi * 16 * PITCH + kb);
            LDSM4(al[0], al[1], al[2], al[3], aBase + mi * 16 * PITCH + kb + LOOFF);
            #pragma unroll
            for (int ni = 0; ni < 4; ni++) {
                mma_bf16(d[mi][ni], ah, bh[ni][0], bh[ni][1]);
                mma_bf16(d[mi][ni], ah, bl[ni][0], bl[ni][1]);
                mma_bf16(d[mi][ni], al, bh[ni][0], bh[ni][1]);
            }
        }
    }
}

// ---------------------------------------------------------------------------
// One-time adjacency split: fp32 -> bf16 HI ONLY (A in [0,1): residual term
// dropped in agg; error analysis R8)
// ---------------------------------------------------------------------------
__global__ void __launch_bounds__(256) split_adj(const float4* __restrict__ a,
                                                 uint2* __restrict__ h) {
    int i = blockIdx.x * 256 + threadIdx.x;
    float4 v = a[i];
    h[i] = make_uint2(pack_bf16x2(v.x, v.y), pack_bf16x2(v.z, v.w));
}

// ---------------------------------------------------------------------------
// One-time weight split into [n][k] bf16 hi/lo. mats: 0=emb,1=msg0,2=agg0,
// 3=msg1,4=agg1,5=proj. emb/proj stored [n][k] already; msg/agg are [k][n].
// ---------------------------------------------------------------------------
__global__ void __launch_bounds__(256) split_weights(
    const float* __restrict__ Wemb, const float* __restrict__ Wmsg,
    const float* __restrict__ Wagg, const float* __restrict__ Wproj,
    uint16_t* __restrict__ WH, uint16_t* __restrict__ WL)
{
    int mat = blockIdx.x;
    const float* src;
    bool trans;
    switch (mat) {
        case 0:  src = Wemb;            trans = false; break;
        case 1:  src = Wmsg;            trans = true;  break;
        case 2:  src = Wagg;            trans = true;  break;
        case 3:  src = Wmsg + DD * DD;  trans = true;  break;
        case 4:  src = Wagg + DD * DD;  trans = true;  break;
        default: src = Wproj;           trans = false; break;
    }
    for (int idx = threadIdx.x; idx < DD * DD; idx += 256) {
        int n = idx >> 7, k = idx & 127;
        float v = trans ? src[k * DD + n] : src[idx];
        uint32_t p = pack_bf16x2(v, 0.f);
        uint16_t hh = (uint16_t)(p & 0xffffu);
        float r = v - __uint_as_float((uint32_t)hh << 16);
        uint32_t pl = pack_bf16x2(r, 0.f);
        WH[mat * DD * DD + idx] = hh;
        WL[mat * DD * DD + idx] = (uint16_t)(pl & 0xffffu);
    }
}

// ---------------------------------------------------------------------------
// Chain / proj smem layout: merged hi||lo rows, pitch 528 (bank = 4r+c).
// ---------------------------------------------------------------------------
#define PW 528
#define XBYTES (64 * PW)
#define WBYTES (128 * PW)
#define LIN_SMEM (XBYTES + WBYTES)    // 101376 -> 2 CTAs/SM

__device__ __forceinline__ void ldgsplit_X64(const float* __restrict__ g,
                                             char* X, int tid) {
    int row = tid >> 2;
    int c0  = (tid & 3) * 32;
    const float* gp = g + (size_t)row * DD + c0;
    char* ph = X + row * PW + c0 * 2;
    char* pl = ph + 256;
    #pragma unroll
    for (int i = 0; i < 8; i++) {
        float4 v = *(const float4*)(gp + i * 4);
        uint32_t h0, l0, h1, l1;
        split2(v.x, v.y, h0, l0);
        split2(v.z, v.w, h1, l1);
        *(uint2*)(ph + i * 8) = make_uint2(h0, h1);
        *(uint2*)(pl + i * 8) = make_uint2(l0, l1);
    }
}

__device__ __forceinline__ void cpw(const uint16_t* __restrict__ WHg,
                                    const uint16_t* __restrict__ WLg,
                                    int mat, uint32_t wbase, int tid) {
    int n = tid >> 1, half = tid & 1;
    const char* src = (const char*)((half ? WLg : WHg) + (size_t)mat * DD * DD + n * DD);
    uint32_t dst = wbase + (uint32_t)(n * PW + half * 256);
    #pragma unroll
    for (int q = 0; q < 16; q++)
        CP16(dst + q * 16, src + q * 16);
}

// ---------------------------------------------------------------------------
// Fused chain kernel (64-row tiles, 512 CTAs, 2 CTA/SM) — unchanged from R7
// ---------------------------------------------------------------------------
template<bool FIRST>
__global__ void __launch_bounds__(256, 2) chain_kernel(
    const float* __restrict__ X,
    const uint16_t* __restrict__ WHg, const uint16_t* __restrict__ WLg,
    int emb_mat, int w1_mat, int w2_mat,
    const float* __restrict__ bias1,
    float* __restrict__ Mout,
    uint16_t* __restrict__ M2H, uint16_t* __restrict__ M2L)
{
    extern __shared__ char smem[];
    const uint32_t sX = smem_u32(smem);
    const uint32_t sW = sX + XBYTES;
    char* Xp = smem;

    const int tid = threadIdx.x, lane = tid & 31, wid = tid >> 5;
    const int wm = wid & 1, wn = wid >> 1;
    const int wm2 = wid & 3, wn2 = wid >> 2;
    const int row0 = blockIdx.x * 64;
    const int bb = row0 >> 10;
    const int rb = row0 & 1023;

    float d[2][4][4];

    if (FIRST) {
        cpw(WHg, WLg, emb_mat, sW, tid);
        CP_COMMIT();
        ldgsplit_X64(X + (size_t)row0 * DD, Xp, tid);
        CPWAIT(0);
        __syncthreads();

        #pragma unroll
        for (int i = 0; i < 2; i++)
            #pragma unroll
            for (int j = 0; j < 4; j++)
                #pragma unroll
                for (int q = 0; q < 4; q++) d[i][j][q] = 0.f;
        mma_blk<PW, 256, 8, 2>(sX, sW, wm, wn, lane, d);
        __syncthreads();

        cpw(WHg, WLg, w1_mat, sW, tid);
        CP_COMMIT();

        float* stg = (float*)Xp;
        #pragma unroll
        for (int mi = 0; mi < 2; mi++) {
            int R = wm * 32 + mi * 16 + (lane >> 2);
            #pragma unroll
            for (int ni = 0; ni < 4; ni++) {
                int C = wn * 32 + ni * 8 + (lane & 3) * 2;
                stg[R * 132 + C]           = d[mi][ni][0];
                stg[R * 132 + C + 1]       = d[mi][ni][1];
                stg[(R + 8) * 132 + C]     = d[mi][ni][2];
                stg[(R + 8) * 132 + C + 1] = d[mi][ni][3];
            }
        }
        __syncthreads();

        #pragma unroll
        for (int i = 0; i < 8; i++) {
            int rr = wid * 8 + i;
            float4 v = *(float4*)&stg[rr * 132 + lane * 4];
            float ss = v.x * v.x + v.y * v.y + v.z * v.z + v.w * v.w;
            #pragma unroll
            for (int o = 16; o > 0; o >>= 1)
                ss += __shfl_xor_sync(0xffffffffu, ss, o);
            float s = hyp_scale(sqrtf(ss));
            v.x *= s; v.y *= s; v.z *= s; v.w *= s;
            __syncwarp();
            uint32_t h0, l0, h1, l1;
            split2(v.x, v.y, h0, l0);
            split2(v.z, v.w, h1, l1);
            *(uint2*)(Xp + rr * PW + lane * 8)       = make_uint2(h0, h1);
            *(uint2*)(Xp + rr * PW + 256 + lane * 8) = make_uint2(l0, l1);
        }
        CPWAIT(0);
        __syncthreads();
    } else {
        cpw(WHg, WLg, w1_mat, sW, tid);
        CP_COMMIT();
        ldgsplit_X64(X + (size_t)row0 * DD, Xp, tid);
        CPWAIT(0);
        __syncthreads();
    }

    // GEMM1: m = t @ W1 + b1
    #pragma unroll
    for (int i = 0; i < 2; i++)
        #pragma unroll
        for (int j = 0; j < 4; j++)
            #pragma unroll
            for (int q = 0; q < 4; q++) d[i][j][q] = 0.f;
    mma_blk<PW, 256, 8, 2>(sX, sW, wm, wn, lane, d);
    __syncthreads();

    cpw(WHg, WLg, w2_mat, sW, tid);
    CP_COMMIT();

    #pragma unroll
    for (int mi = 0; mi < 2; mi++) {
        int R = wm * 32 + mi * 16 + (lane >> 2);
        #pragma unroll
        for (int ni = 0; ni < 4; ni++) {
            int C = wn * 32 + ni * 8 + (lane & 3) * 2;
            float b0 = bias1[C], b1 = bias1[C + 1];
            float v0 = d[mi][ni][0] + b0, v1 = d[mi][ni][1] + b1;
            float v2 = d[mi][ni][2] + b0, v3 = d[mi][ni][3] + b1;
            *(float2*)&Mout[(size_t)(row0 + R) * DD + C]     = make_float2(v0, v1);
            *(float2*)&Mout[(size_t)(row0 + R + 8) * DD + C] = make_float2(v2, v3);
            uint32_t h, l;
            split2(v0, v1, h, l);
            *(uint32_t*)(Xp + R * PW + C * 2)       = h;
            *(uint32_t*)(Xp + R * PW + 256 + C * 2) = l;
            split2(v2, v3, h, l);
            *(uint32_t*)(Xp + (R + 8) * PW + C * 2)       = h;
            *(uint32_t*)(Xp + (R + 8) * PW + 256 + C * 2) = l;
        }
    }
    CPWAIT(0);
    __syncthreads();

    // GEMM2: m2T[n][r] = sum_k W2n[n][k] * m[r][k]
    float e[2][4][4];
    #pragma unroll
    for (int i = 0; i < 2; i++)
        #pragma unroll
        for (int j = 0; j < 4; j++)
            #pragma unroll
            for (int q = 0; q < 4; q++) e[i][j][q] = 0.f;
    mma_blk<PW, 256, 8, 2>(sW, sX, wm2, wn2, lane, e);

    #pragma unroll
    for (int mi = 0; mi < 2; mi++) {
        int Rn = wm2 * 32 + mi * 16 + (lane >> 2);
        #pragma unroll
        for (int ni = 0; ni < 4; ni++) {
            int Cr = wn2 * 32 + ni * 8 + (lane & 3) * 2;
            uint32_t h, l;
            split2(e[mi][ni][0], e[mi][ni][1], h, l);
            size_t o = (((size_t)(bb * DD + Rn)) << 10) + rb + Cr;
            *(uint32_t*)(M2H + o) = h;
            *(uint32_t*)(M2L + o) = l;
            split2(e[mi][ni][2], e[mi][ni][3], h, l);
            size_t o2 = (((size_t)(bb * DD + Rn + 8)) << 10) + rb + Cr;
            *(uint32_t*)(M2H + o2) = h;
            *(uint32_t*)(M2L + o2) = l;
        }
    }
}

// ---------------------------------------------------------------------------
// Final projection: out = (t @ WprojT + bp) * mask — unchanged from R7
// ---------------------------------------------------------------------------
__global__ void __launch_bounds__(256, 2) proj_kernel(
    const float* __restrict__ X,
    const uint16_t* __restrict__ WHg, const uint16_t* __restrict__ WLg,
    const float* __restrict__ bp, const float* __restrict__ mask,
    float* __restrict__ out)
{
    extern __shared__ char smem[];
    const uint32_t sX = smem_u32(smem);
    const uint32_t sW = sX + XBYTES;
    const int tid = threadIdx.x, lane = tid & 31, wid = tid >> 5;
    const int wm = wid & 1, wn = wid >> 1;
    const int row0 = blockIdx.x * 64;

    cpw(WHg, WLg, 5, sW, tid);
    CP_COMMIT();
    ldgsplit_X64(X + (size_t)row0 * DD, smem, tid);
    CPWAIT(0);
    __syncthreads();

    float d[2][4][4];
    #pragma unroll
    for (int i = 0; i < 2; i++)
        #pragma unroll
        for (int j = 0; j < 4; j++)
            #pragma unroll
            for (int q = 0; q < 4; q++) d[i][j][q] = 0.f;
    mma_blk<PW, 256, 8, 2>(sX, sW, wm, wn, lane, d);

    #pragma unroll
    for (int mi = 0; mi < 2; mi++) {
        int R = wm * 32 + mi * 16 + (lane >> 2);
        float mk0 = mask[row0 + R];
        float mk1 = mask[row0 + R + 8];
        #pragma unroll
        for (int ni = 0; ni < 4; ni++) {
            int C = wn * 32 + ni * 8 + (lane & 3) * 2;
            float b0 = bp[C], b1 = bp[C + 1];
            *(float2*)&out[(size_t)(row0 + R) * DD + C] =
                make_float2((d[mi][ni][0] + b0) * mk0, (d[mi][ni][1] + b1) * mk0);
            *(float2*)&out[(size_t)(row0 + R + 8) * DD + C] =
                make_float2((d[mi][ni][2] + b0) * mk1, (d[mi][ni][3] + b1) * mk1);
        }
    }
}

// ---------------------------------------------------------------------------
// Big GEMM: 2-product (A-hi only), 4-stage cp.async pipeline, depth-3 prefetch.
//   A tile: 128 x 32k bf16 hi, pitch 80 (16B-aligned, conflict-free ldmatrix)
//   B tile: 128 x (32k hi || 32k lo), pitch 144
// Ordering per chunk: wait(c) -> syncthreads -> issue(c+3) -> mma(c).
// ---------------------------------------------------------------------------
#define PAG_A   80
#define PAG_B   144
#define TILE_A  (128 * PAG_A)          // 10240
#define TILE_B  (128 * PAG_B)          // 18432
#define STG_SZ  (TILE_A + TILE_B)      // 28672
#define NSTG    4
#define AGG_SMEM (NSTG * STG_SZ)       // 114688 -> 2 CTAs/SM

__global__ void __launch_bounds__(256, 2) agg_mma(
    const uint16_t* __restrict__ AH,
    const uint16_t* __restrict__ BH, const uint16_t* __restrict__ BL,
    const float* __restrict__ M, const float* __restrict__ bagg,
    float* __restrict__ T)
{
    extern __shared__ char smem[];
    const uint32_t sb = smem_u32(smem);
    const int tid  = threadIdx.x;
    const int lane = tid & 31;
    const int wid  = tid >> 5;
    const int b    = blockIdx.y;
    const int row0 = blockIdx.x * 128;
    const int wm   = wid & 1;
    const int wn   = wid >> 1;

    const char* gAh = (const char*)(AH + (size_t)(b * NN + row0) * NN);
    const char* gBh = (const char*)(BH + (size_t)b * DD * NN);
    const char* gBl = (const char*)(BL + (size_t)b * DD * NN);

    const int rr_ld = tid >> 1;         // 0..127
    const int half  = tid & 1;

    float d[4][4][4];
    #pragma unroll
    for (int i = 0; i < 4; i++)
        #pragma unroll
        for (int j = 0; j < 4; j++)
            #pragma unroll
            for (int q = 0; q < 4; q++) d[i][j][q] = 0.f;

    auto issue = [&](int c, int s) {
        uint32_t base = sb + (uint32_t)s * STG_SZ;
        // A hi: row rr_ld, 32B half
        uint32_t dA = base + (uint32_t)(rr_ld * PAG_A + half * 32);
        const char* sA = gAh + (size_t)rr_ld * 2048 + (size_t)c * 64 + half * 32;
        CP16(dA,      sA);
        CP16(dA + 16, sA + 16);
        // B: row rr_ld, half 0 = hi (offset 0), half 1 = lo (offset 64)
        uint32_t dB = base + TILE_A + (uint32_t)(rr_ld * PAG_B + half * 64);
        const char* sB = (half ? gBl : gBh) + (size_t)rr_ld * 2048 + (size_t)c * 64;
        CP16(dB,      sB);
        CP16(dB + 16, sB + 16);
        CP16(dB + 32, sB + 32);
        CP16(dB + 48, sB + 48);
        CP_COMMIT();
    };

    issue(0, 0);
    issue(1, 1);
    issue(2, 2);

    const int lg = lane >> 3, lr = lane & 7;
    const uint32_t aOff = (uint32_t)((wm * 64 + (lg & 1) * 8 + lr) * PAG_A
                                     + (lg >> 1) * 16);
    const uint32_t bOff = (uint32_t)(TILE_A + (wn * 32 + lr) * PAG_B
                                     + (lg & 1) * 16 + ((lg >> 1) ? 64 : 0));

    for (int c = 0; c < 32; c++) {
        if (c < 30)       { CPWAIT(2); }
        else if (c == 30) { CPWAIT(1); }
        else              { CPWAIT(0); }
        __syncthreads();
        // safe: stage (c+3)%4 == (c-1)%4 has no remaining readers
        if (c + 3 < 32) issue(c + 3, (c + 3) & 3);

        uint32_t base = sb + (uint32_t)(c & 3) * STG_SZ;
        #pragma unroll
        for (int ks = 0; ks < 2; ks++) {
            const uint32_t kb = (uint32_t)ks * 32;
            uint32_t bh[4][2], bl[4][2];
            #pragma unroll
            for (int ni = 0; ni < 4; ni++)
                LDSM4(bh[ni][0], bh[ni][1], bl[ni][0], bl[ni][1],
                      base + bOff + ni * 8 * PAG_B + kb);
            #pragma unroll
            for (int mi = 0; mi < 4; mi++) {
                uint32_t ah[4];
                LDSM4(ah[0], ah[1], ah[2], ah[3],
                      base + aOff + mi * 16 * PAG_A + kb);
                #pragma unroll
                for (int ni = 0; ni < 4; ni++) {
                    mma_bf16(d[mi][ni], ah, bh[ni][0], bh[ni][1]);
                    mma_bf16(d[mi][ni], ah, bl[ni][0], bl[ni][1]);
                }
            }
        }
    }
    __syncthreads();                    // drain readers of last stage

    // stage D to smem (f32, pitch 132)
    float* stg = (float*)smem;
    #pragma unroll
    for (int mi = 0; mi < 4; mi++) {
        int R = wm * 64 + mi * 16 + (lane >> 2);
        #pragma unroll
        for (int ni = 0; ni < 4; ni++) {
            int C = wn * 32 + ni * 8 + (lane & 3) * 2;
            *(float2*)&stg[R * 132 + C]       = make_float2(d[mi][ni][0], d[mi][ni][1]);
            *(float2*)&stg[(R + 8) * 132 + C] = make_float2(d[mi][ni][2], d[mi][ni][3]);
        }
    }
    __syncthreads();

    const float* Mb = M + ((size_t)b * NN + row0) * DD;
    float*       Tb = T + ((size_t)b * NN + row0) * DD;
    float4 bg = *(const float4*)&bagg[lane * 4];
    #pragma unroll
    for (int i = 0; i < 16; i++) {
        int rr = wid * 16 + i;
        float4 raw = *(const float4*)&stg[rr * 132 + lane * 4];
        float4 mm  = *(const float4*)&Mb[(size_t)rr * DD + lane * 4];
        float v0 = fmaxf(raw.x + mm.x + bg.x, 0.f);
        float v1 = fmaxf(raw.y + mm.y + bg.y, 0.f);
        float v2 = fmaxf(raw.z + mm.z + bg.z, 0.f);
        float v3 = fmaxf(raw.w + mm.w + bg.w, 0.f);
        float ss = v0*v0 + v1*v1 + v2*v2 + v3*v3;
        #pragma unroll
        for (int o = 16; o > 0; o >>= 1)
            ss += __shfl_xor_sync(0xffffffffu, ss, o);
        float s = hyp_scale(sqrtf(ss));
        *(float4*)&Tb[(size_t)rr * DD + lane * 4] =
            make_float4(v0 * s, v1 * s, v2 * s, v3 * s);
    }
}

// ---------------------------------------------------------------------------
// Host launch
// ---------------------------------------------------------------------------
extern "C" void kernel_launch(void* const* d_in, const int* in_sizes, int n_in,
                              void* d_out, int out_size)
{
    const float* nf    = (const float*)d_in[0];
    const float* adj   = (const float*)d_in[1];
    const float* mask  = (const float*)d_in[2];
    const float* Wemb  = (const float*)d_in[3];
    const float* Wmsg  = (const float*)d_in[4];
    const float* bmsg  = (const float*)d_in[5];
    const float* Wagg  = (const float*)d_in[6];
    const float* bagg  = (const float*)d_in[7];
    const float* Wproj = (const float*)d_in[8];
    const float* bproj = (const float*)d_in[9];
    float* out = (float*)d_out;

    float *t, *m;
    uint16_t *ah, *m2h, *m2l, *wh, *wl;
    cudaGetSymbolAddress((void**)&t,   g_t);
    cudaGetSymbolAddress((void**)&m,   g_m);
    cudaGetSymbolAddress((void**)&ah,  g_ah);
    cudaGetSymbolAddress((void**)&m2h, g_m2h);
    cudaGetSymbolAddress((void**)&m2l, g_m2l);
    cudaGetSymbolAddress((void**)&wh,  g_wh);
    cudaGetSymbolAddress((void**)&wl,  g_wl);

    cudaFuncSetAttribute(agg_mma, cudaFuncAttributeMaxDynamicSharedMemorySize, AGG_SMEM);
    cudaFuncSetAttribute(chain_kernel<true>,  cudaFuncAttributeMaxDynamicSharedMemorySize, LIN_SMEM);
    cudaFuncSetAttribute(chain_kernel<false>, cudaFuncAttributeMaxDynamicSharedMemorySize, LIN_SMEM);
    cudaFuncSetAttribute(proj_kernel, cudaFuncAttributeMaxDynamicSharedMemorySize, LIN_SMEM);

    dim3 glin(ROWS / 64);          // 512
    dim3 gbig(NN / 128, BATCH);    // 8 x 32

    split_adj<<<(BATCH * NN * NN / 4) / 256, 256>>>((const float4*)adj, (uint2*)ah);
    split_weights<<<6, 256>>>(Wemb, Wmsg, Wagg, Wproj, wh, wl);

    // layer 0: embed + hyp + msg + m2 fused
    chain_kernel<true><<<glin, 256, LIN_SMEM>>>(nf, wh, wl, 0, 1, 2,
                                                bmsg, m, m2h, m2l);
    agg_mma<<<gbig, 256, AGG_SMEM>>>(ah, m2h, m2l, m, bagg, t);

    // layer 1: msg + m2 fused
    chain_kernel<false><<<glin, 256, LIN_SMEM>>>(t, wh, wl, 0, 3, 4,
                                                 bmsg + DD, m, m2h, m2l);
    agg_mma<<<gbig, 256, AGG_SMEM>>>(ah, m2h, m2l, m, bagg + DD, t);

    // out = (t @ WprojT + bproj) * mask
    proj_kernel<<<glin, 256, LIN_SMEM>>>(t, wh, wl, bproj, mask, out);
}

// round 9
// speedup vs baseline: 2.0620x; 1.0670x over previous
#include <cuda_runtime.h>
#include <math.h>
#include <stdint.h>

// Problem constants
#define BATCH 32
#define NN    1024
#define DD    128
#define ROWS  (BATCH * NN)   // 32768

// Scratch (device globals — no allocation allowed)
__device__ float g_t[ROWS * DD];
__device__ float g_m[ROWS * DD];
__device__ __align__(16) uint16_t g_ah[(size_t)BATCH * NN * NN];   // adj bf16 hi
__device__ __align__(16) uint16_t g_m2h[(size_t)BATCH * DD * NN];  // m2^T hi [b][n][k]
__device__ __align__(16) uint16_t g_m2l[(size_t)BATCH * DD * NN];  // m2^T lo
__device__ __align__(16) uint16_t g_wh[6 * DD * DD];               // weights hi [n][k]
__device__ __align__(16) uint16_t g_wl[6 * DD * DD];               // weights lo

// ---------------------------------------------------------------------------
// Helpers
// ---------------------------------------------------------------------------
__device__ __forceinline__ uint32_t smem_u32(const void* p) {
    uint32_t a;
    asm("{ .reg .u64 t; cvta.to.shared.u64 t, %1; cvt.u32.u64 %0, t; }" : "=r"(a) : "l"(p));
    return a;
}
__device__ __forceinline__ uint32_t pack_bf16x2(float v0, float v1) {
    uint32_t r;
    asm("cvt.rn.bf16x2.f32 %0, %1, %2;" : "=r"(r) : "f"(v1), "f"(v0));
    return r;
}
__device__ __forceinline__ void split2(float v0, float v1, uint32_t& h, uint32_t& l) {
    h = pack_bf16x2(v0, v1);
    float r0 = v0 - __uint_as_float(h << 16);
    float r1 = v1 - __uint_as_float(h & 0xffff0000u);
    l = pack_bf16x2(r0, r1);
}
#define CP16(dst, src) \
    asm volatile("cp.async.cg.shared.global [%0], [%1], 16;" :: "r"(dst), "l"(src) : "memory")
#define CP_COMMIT() asm volatile("cp.async.commit_group;" ::: "memory")
#define CPWAIT(n)   asm volatile("cp.async.wait_group %0;" :: "n"(n) : "memory")

#define LDSM4(r0, r1, r2, r3, addr) \
    asm volatile("ldmatrix.sync.aligned.m8n8.x4.shared.b16 {%0,%1,%2,%3}, [%4];" \
        : "=r"(r0), "=r"(r1), "=r"(r2), "=r"(r3) : "r"(addr))

__device__ __forceinline__ void mma_bf16(float d[4], const uint32_t a[4],
                                         uint32_t b0, uint32_t b1) {
    asm volatile(
        "mma.sync.aligned.m16n8k16.row.col.f32.bf16.bf16.f32 "
        "{%0,%1,%2,%3}, {%4,%5,%6,%7}, {%8,%9}, {%0,%1,%2,%3};"
        : "+f"(d[0]), "+f"(d[1]), "+f"(d[2]), "+f"(d[3])
        : "r"(a[0]), "r"(a[1]), "r"(a[2]), "r"(a[3]), "r"(b0), "r"(b1));
}

// Composite per-row scale: logmap0(proj(expmap0(h))) = s(||h||) * h
__device__ __forceinline__ float hyp_scale(float n) {
    const float EPS  = 1e-7f;
    const float MAXN = 1.0f - 1e-5f;
    float n1 = fmaxf(n, EPS);
    float r  = tanhf(n1) / n1;
    float xn = r * n;
    float n2 = fmaxf(xn, EPS);
    float s2 = (n2 > MAXN) ? (MAXN / n2) : 1.0f;
    float x2 = s2 * xn;
    float n3 = fmaxf(x2, EPS);
    float z  = fminf(n3, 1.0f - EPS);
    float lg = atanhf(z) / n3;
    return r * s2 * lg;
}

// ---------------------------------------------------------------------------
// 3-product warp-tile MMA over merged hi/lo smem tiles (chain/proj kernels).
// ---------------------------------------------------------------------------
template<int PITCH, int LOOFF, int NKS, int MI>
__device__ __forceinline__ void mma_blk(uint32_t Ab, uint32_t Bb,
                                        int wma, int wnb, int lane,
                                        float (&d)[MI][4][4]) {
    const int lg = lane >> 3;
    const int lr = lane & 7;
    const uint32_t aBase = Ab + (uint32_t)((wma * (MI * 16) + (lg & 1) * 8 + lr) * PITCH
                                           + (lg >> 1) * 16);
    const uint32_t bBase = Bb + (uint32_t)((wnb * 32 + lr) * PITCH + (lg & 1) * 16
                                           + ((lg >> 1) ? LOOFF : 0));
    #pragma unroll
    for (int ks = 0; ks < NKS; ks++) {
        const uint32_t kb = (uint32_t)ks * 32;
        uint32_t bh[4][2], bl[4][2];
        #pragma unroll
        for (int ni = 0; ni < 4; ni++)
            LDSM4(bh[ni][0], bh[ni][1], bl[ni][0], bl[ni][1],
                  bBase + ni * 8 * PITCH + kb);
        #pragma unroll
        for (int mi = 0; mi < MI; mi++) {
            uint32_t ah[4], al[4];
            LDSM4(ah[0], ah[1], ah[2], ah[3], aBase + mi * 16 * PITCH + kb);
            LDSM4(al[0], al[1], al[2], al[3], aBase + mi * 16 * PITCH + kb + LOOFF);
            #pragma unroll
            for (int ni = 0; ni < 4; ni++) {
                mma_bf16(d[mi][ni], ah, bh[ni][0], bh[ni][1]);
                mma_bf16(d[mi][ni], ah, bl[ni][0], bl[ni][1]);
                mma_bf16(d[mi][ni], al, bh[ni][0], bh[ni][1]);
            }
        }
    }
}

// ---------------------------------------------------------------------------
// One-time adjacency split: fp32 -> bf16 HI ONLY
// ---------------------------------------------------------------------------
__global__ void __launch_bounds__(256) split_adj(const float4* __restrict__ a,
                                                 uint2* __restrict__ h) {
    int i = blockIdx.x * 256 + threadIdx.x;
    float4 v = a[i];
    h[i] = make_uint2(pack_bf16x2(v.x, v.y), pack_bf16x2(v.z, v.w));
}

// ---------------------------------------------------------------------------
// One-time weight split into [n][k] bf16 hi/lo.
// ---------------------------------------------------------------------------
__global__ void __launch_bounds__(256) split_weights(
    const float* __restrict__ Wemb, const float* __restrict__ Wmsg,
    const float* __restrict__ Wagg, const float* __restrict__ Wproj,
    uint16_t* __restrict__ WH, uint16_t* __restrict__ WL)
{
    int mat = blockIdx.x;
    const float* src;
    bool trans;
    switch (mat) {
        case 0:  src = Wemb;            trans = false; break;
        case 1:  src = Wmsg;            trans = true;  break;
        case 2:  src = Wagg;            trans = true;  break;
        case 3:  src = Wmsg + DD * DD;  trans = true;  break;
        case 4:  src = Wagg + DD * DD;  trans = true;  break;
        default: src = Wproj;           trans = false; break;
    }
    for (int idx = threadIdx.x; idx < DD * DD; idx += 256) {
        int n = idx >> 7, k = idx & 127;
        float v = trans ? src[k * DD + n] : src[idx];
        uint32_t p = pack_bf16x2(v, 0.f);
        uint16_t hh = (uint16_t)(p & 0xffffu);
        float r = v - __uint_as_float((uint32_t)hh << 16);
        uint32_t pl = pack_bf16x2(r, 0.f);
        WH[mat * DD * DD + idx] = hh;
        WL[mat * DD * DD + idx] = (uint16_t)(pl & 0xffffu);
    }
}

// ---------------------------------------------------------------------------
// Chain / proj smem layout: merged hi||lo rows, pitch 528.
// ---------------------------------------------------------------------------
#define PW 528
#define XBYTES (64 * PW)
#define WBYTES (128 * PW)
#define LIN_SMEM (XBYTES + WBYTES)    // 101376 -> 2 CTAs/SM

__device__ __forceinline__ void ldgsplit_X64(const float* __restrict__ g,
                                             char* X, int tid) {
    int row = tid >> 2;
    int c0  = (tid & 3) * 32;
    const float* gp = g + (size_t)row * DD + c0;
    char* ph = X + row * PW + c0 * 2;
    char* pl = ph + 256;
    #pragma unroll
    for (int i = 0; i < 8; i++) {
        float4 v = *(const float4*)(gp + i * 4);
        uint32_t h0, l0, h1, l1;
        split2(v.x, v.y, h0, l0);
        split2(v.z, v.w, h1, l1);
        *(uint2*)(ph + i * 8) = make_uint2(h0, h1);
        *(uint2*)(pl + i * 8) = make_uint2(l0, l1);
    }
}

__device__ __forceinline__ void cpw(const uint16_t* __restrict__ WHg,
                                    const uint16_t* __restrict__ WLg,
                                    int mat, uint32_t wbase, int tid) {
    int n = tid >> 1, half = tid & 1;
    const char* src = (const char*)((half ? WLg : WHg) + (size_t)mat * DD * DD + n * DD);
    uint32_t dst = wbase + (uint32_t)(n * PW + half * 256);
    #pragma unroll
    for (int q = 0; q < 16; q++)
        CP16(dst + q * 16, src + q * 16);
}

// ---------------------------------------------------------------------------
// Fused chain kernel (64-row tiles, 512 CTAs, 2 CTA/SM)
// ---------------------------------------------------------------------------
template<bool FIRST>
__global__ void __launch_bounds__(256, 2) chain_kernel(
    const float* __restrict__ X,
    const uint16_t* __restrict__ WHg, const uint16_t* __restrict__ WLg,
    int emb_mat, int w1_mat, int w2_mat,
    const float* __restrict__ bias1,
    float* __restrict__ Mout,
    uint16_t* __restrict__ M2H, uint16_t* __restrict__ M2L)
{
    extern __shared__ char smem[];
    const uint32_t sX = smem_u32(smem);
    const uint32_t sW = sX + XBYTES;
    char* Xp = smem;

    const int tid = threadIdx.x, lane = tid & 31, wid = tid >> 5;
    const int wm = wid & 1, wn = wid >> 1;
    const int wm2 = wid & 3, wn2 = wid >> 2;
    const int row0 = blockIdx.x * 64;
    const int bb = row0 >> 10;
    const int rb = row0 & 1023;

    float d[2][4][4];

    if (FIRST) {
        cpw(WHg, WLg, emb_mat, sW, tid);
        CP_COMMIT();
        ldgsplit_X64(X + (size_t)row0 * DD, Xp, tid);
        CPWAIT(0);
        __syncthreads();

        #pragma unroll
        for (int i = 0; i < 2; i++)
            #pragma unroll
            for (int j = 0; j < 4; j++)
                #pragma unroll
                for (int q = 0; q < 4; q++) d[i][j][q] = 0.f;
        mma_blk<PW, 256, 8, 2>(sX, sW, wm, wn, lane, d);
        __syncthreads();

        cpw(WHg, WLg, w1_mat, sW, tid);
        CP_COMMIT();

        float* stg = (float*)Xp;
        #pragma unroll
        for (int mi = 0; mi < 2; mi++) {
            int R = wm * 32 + mi * 16 + (lane >> 2);
            #pragma unroll
            for (int ni = 0; ni < 4; ni++) {
                int C = wn * 32 + ni * 8 + (lane & 3) * 2;
                stg[R * 132 + C]           = d[mi][ni][0];
                stg[R * 132 + C + 1]       = d[mi][ni][1];
                stg[(R + 8) * 132 + C]     = d[mi][ni][2];
                stg[(R + 8) * 132 + C + 1] = d[mi][ni][3];
            }
        }
        __syncthreads();

        #pragma unroll
        for (int i = 0; i < 8; i++) {
            int rr = wid * 8 + i;
            float4 v = *(float4*)&stg[rr * 132 + lane * 4];
            float ss = v.x * v.x + v.y * v.y + v.z * v.z + v.w * v.w;
            #pragma unroll
            for (int o = 16; o > 0; o >>= 1)
                ss += __shfl_xor_sync(0xffffffffu, ss, o);
            float s = hyp_scale(sqrtf(ss));
            v.x *= s; v.y *= s; v.z *= s; v.w *= s;
            __syncwarp();
            uint32_t h0, l0, h1, l1;
            split2(v.x, v.y, h0, l0);
            split2(v.z, v.w, h1, l1);
            *(uint2*)(Xp + rr * PW + lane * 8)       = make_uint2(h0, h1);
            *(uint2*)(Xp + rr * PW + 256 + lane * 8) = make_uint2(l0, l1);
        }
        CPWAIT(0);
        __syncthreads();
    } else {
        cpw(WHg, WLg, w1_mat, sW, tid);
        CP_COMMIT();
        ldgsplit_X64(X + (size_t)row0 * DD, Xp, tid);
        CPWAIT(0);
        __syncthreads();
    }

    // GEMM1: m = t @ W1 + b1
    #pragma unroll
    for (int i = 0; i < 2; i++)
        #pragma unroll
        for (int j = 0; j < 4; j++)
            #pragma unroll
            for (int q = 0; q < 4; q++) d[i][j][q] = 0.f;
    mma_blk<PW, 256, 8, 2>(sX, sW, wm, wn, lane, d);
    __syncthreads();

    cpw(WHg, WLg, w2_mat, sW, tid);
    CP_COMMIT();

    #pragma unroll
    for (int mi = 0; mi < 2; mi++) {
        int R = wm * 32 + mi * 16 + (lane >> 2);
        #pragma unroll
        for (int ni = 0; ni < 4; ni++) {
            int C = wn * 32 + ni * 8 + (lane & 3) * 2;
            float b0 = bias1[C], b1 = bias1[C + 1];
            float v0 = d[mi][ni][0] + b0, v1 = d[mi][ni][1] + b1;
            float v2 = d[mi][ni][2] + b0, v3 = d[mi][ni][3] + b1;
            *(float2*)&Mout[(size_t)(row0 + R) * DD + C]     = make_float2(v0, v1);
            *(float2*)&Mout[(size_t)(row0 + R + 8) * DD + C] = make_float2(v2, v3);
            uint32_t h, l;
            split2(v0, v1, h, l);
            *(uint32_t*)(Xp + R * PW + C * 2)       = h;
            *(uint32_t*)(Xp + R * PW + 256 + C * 2) = l;
            split2(v2, v3, h, l);
            *(uint32_t*)(Xp + (R + 8) * PW + C * 2)       = h;
            *(uint32_t*)(Xp + (R + 8) * PW + 256 + C * 2) = l;
        }
    }
    CPWAIT(0);
    __syncthreads();

    // GEMM2: m2T[n][r] = sum_k W2n[n][k] * m[r][k]
    float e[2][4][4];
    #pragma unroll
    for (int i = 0; i < 2; i++)
        #pragma unroll
        for (int j = 0; j < 4; j++)
            #pragma unroll
            for (int q = 0; q < 4; q++) e[i][j][q] = 0.f;
    mma_blk<PW, 256, 8, 2>(sW, sX, wm2, wn2, lane, e);

    #pragma unroll
    for (int mi = 0; mi < 2; mi++) {
        int Rn = wm2 * 32 + mi * 16 + (lane >> 2);
        #pragma unroll
        for (int ni = 0; ni < 4; ni++) {
            int Cr = wn2 * 32 + ni * 8 + (lane & 3) * 2;
            uint32_t h, l;
            split2(e[mi][ni][0], e[mi][ni][1], h, l);
            size_t o = (((size_t)(bb * DD + Rn)) << 10) + rb + Cr;
            *(uint32_t*)(M2H + o) = h;
            *(uint32_t*)(M2L + o) = l;
            split2(e[mi][ni][2], e[mi][ni][3], h, l);
            size_t o2 = (((size_t)(bb * DD + Rn + 8)) << 10) + rb + Cr;
            *(uint32_t*)(M2H + o2) = h;
            *(uint32_t*)(M2L + o2) = l;
        }
    }
}

// ---------------------------------------------------------------------------
// Final projection: out = (t @ WprojT + bp) * mask
// ---------------------------------------------------------------------------
__global__ void __launch_bounds__(256, 2) proj_kernel(
    const float* __restrict__ X,
    const uint16_t* __restrict__ WHg, const uint16_t* __restrict__ WLg,
    const float* __restrict__ bp, const float* __restrict__ mask,
    float* __restrict__ out)
{
    extern __shared__ char smem[];
    const uint32_t sX = smem_u32(smem);
    const uint32_t sW = sX + XBYTES;
    const int tid = threadIdx.x, lane = tid & 31, wid = tid >> 5;
    const int wm = wid & 1, wn = wid >> 1;
    const int row0 = blockIdx.x * 64;

    cpw(WHg, WLg, 5, sW, tid);
    CP_COMMIT();
    ldgsplit_X64(X + (size_t)row0 * DD, smem, tid);
    CPWAIT(0);
    __syncthreads();

    float d[2][4][4];
    #pragma unroll
    for (int i = 0; i < 2; i++)
        #pragma unroll
        for (int j = 0; j < 4; j++)
            #pragma unroll
            for (int q = 0; q < 4; q++) d[i][j][q] = 0.f;
    mma_blk<PW, 256, 8, 2>(sX, sW, wm, wn, lane, d);

    #pragma unroll
    for (int mi = 0; mi < 2; mi++) {
        int R = wm * 32 + mi * 16 + (lane >> 2);
        float mk0 = mask[row0 + R];
        float mk1 = mask[row0 + R + 8];
        #pragma unroll
        for (int ni = 0; ni < 4; ni++) {
            int C = wn * 32 + ni * 8 + (lane & 3) * 2;
            float b0 = bp[C], b1 = bp[C + 1];
            *(float2*)&out[(size_t)(row0 + R) * DD + C] =
                make_float2((d[mi][ni][0] + b0) * mk0, (d[mi][ni][1] + b1) * mk0);
            *(float2*)&out[(size_t)(row0 + R + 8) * DD + C] =
                make_float2((d[mi][ni][2] + b0) * mk1, (d[mi][ni][3] + b1) * mk1);
        }
    }
}

// ---------------------------------------------------------------------------
// Big GEMM: BM=256, 512 threads, 1 CTA/SM. cp.async-issue-optimized:
// per chunk per CTA = 2048 x 16B ops (A 16KB + B 16KB) for 256 output rows.
// 4-stage pipeline, depth-3 prefetch, wait -> barrier -> issue(c+3) -> mma(c).
// ---------------------------------------------------------------------------
#define BMA     256
#define PAG_A   80
#define PAG_B   144
#define TILE_A  (BMA * PAG_A)          // 20480
#define TILE_B  (128 * PAG_B)          // 18432
#define STG_SZ  (TILE_A + TILE_B)      // 38912
#define NSTG    4
#define AGG_SMEM (NSTG * STG_SZ)       // 155648 (also covers 256x132 f32 epi)

__global__ void __launch_bounds__(512, 1) agg_mma(
    const uint16_t* __restrict__ AH,
    const uint16_t* __restrict__ BH, const uint16_t* __restrict__ BL,
    const float* __restrict__ M, const float* __restrict__ bagg,
    float* __restrict__ T)
{
    extern __shared__ char smem[];
    const uint32_t sb = smem_u32(smem);
    const int tid  = threadIdx.x;
    const int lane = tid & 31;
    const int wid  = tid >> 5;          // 0..15
    const int b    = blockIdx.y;
    const int row0 = blockIdx.x * BMA;
    const int wm   = wid & 3;           // 4 m groups x 64 rows
    const int wn   = wid >> 2;          // 4 n groups x 32 cols

    const char* gAh = (const char*)(AH + (size_t)(b * NN + row0) * NN);
    const char* gBh = (const char*)(BH + (size_t)b * DD * NN);
    const char* gBl = (const char*)(BL + (size_t)b * DD * NN);

    // load assignment (512 threads, 4 CP16 each = 2048 ops/chunk)
    const int arow  = tid >> 1;         // 0..255
    const int ahalf = tid & 1;          // 32B half of 64B A row-chunk
    const int brow  = tid & 127;        // 0..127
    const int bpart = tid >> 7;         // 0..3: 0,1 = hi halves; 2,3 = lo halves

    float d[4][4][4];
    #pragma unroll
    for (int i = 0; i < 4; i++)
        #pragma unroll
        for (int j = 0; j < 4; j++)
            #pragma unroll
            for (int q = 0; q < 4; q++) d[i][j][q] = 0.f;

    auto issue = [&](int c, int s) {
        uint32_t base = sb + (uint32_t)s * STG_SZ;
        // A hi
        uint32_t dA = base + (uint32_t)(arow * PAG_A + ahalf * 32);
        const char* sA = gAh + (size_t)arow * 2048 + (size_t)c * 64 + ahalf * 32;
        CP16(dA,      sA);
        CP16(dA + 16, sA + 16);
        // B hi (parts 0,1) / lo (parts 2,3)
        int sub = bpart & 1;
        const char* gB = (bpart < 2) ? gBh : gBl;
        uint32_t dB = base + TILE_A
                    + (uint32_t)(brow * PAG_B + (bpart < 2 ? 0 : 64) + sub * 32);
        const char* sB = gB + (size_t)brow * 2048 + (size_t)c * 64 + sub * 32;
        CP16(dB,      sB);
        CP16(dB + 16, sB + 16);
        CP_COMMIT();
    };

    issue(0, 0);
    issue(1, 1);
    issue(2, 2);

    const int lg = lane >> 3, lr = lane & 7;
    const uint32_t aOff = (uint32_t)((wm * 64 + (lg & 1) * 8 + lr) * PAG_A
                                     + (lg >> 1) * 16);
    const uint32_t bOff = (uint32_t)(TILE_A + (wn * 32 + lr) * PAG_B
                                     + (lg & 1) * 16 + ((lg >> 1) ? 64 : 0));

    for (int c = 0; c < 32; c++) {
        if (c < 30)       { CPWAIT(2); }
        else if (c == 30) { CPWAIT(1); }
        else              { CPWAIT(0); }
        __syncthreads();
        // safe: stage (c+3)&3 == (c-1)&3 has no remaining readers
        if (c + 3 < 32) issue(c + 3, (c + 3) & 3);

        uint32_t base = sb + (uint32_t)(c & 3) * STG_SZ;
        #pragma unroll
        for (int ks = 0; ks < 2; ks++) {
            const uint32_t kb = (uint32_t)ks * 32;
            uint32_t bh[4][2], bl[4][2];
            #pragma unroll
            for (int ni = 0; ni < 4; ni++)
                LDSM4(bh[ni][0], bh[ni][1], bl[ni][0], bl[ni][1],
                      base + bOff + ni * 8 * PAG_B + kb);
            #pragma unroll
            for (int mi = 0; mi < 4; mi++) {
                uint32_t ah[4];
                LDSM4(ah[0], ah[1], ah[2], ah[3],
                      base + aOff + mi * 16 * PAG_A + kb);
                #pragma unroll
                for (int ni = 0; ni < 4; ni++) {
                    mma_bf16(d[mi][ni], ah, bh[ni][0], bh[ni][1]);
                    mma_bf16(d[mi][ni], ah, bl[ni][0], bl[ni][1]);
                }
            }
        }
    }
    __syncthreads();                    // drain readers of last stage

    // stage D to smem (f32, pitch 132, 256 rows = 135168 B <= AGG_SMEM)
    float* stg = (float*)smem;
    #pragma unroll
    for (int mi = 0; mi < 4; mi++) {
        int R = wm * 64 + mi * 16 + (lane >> 2);
        #pragma unroll
        for (int ni = 0; ni < 4; ni++) {
            int C = wn * 32 + ni * 8 + (lane & 3) * 2;
            *(float2*)&stg[R * 132 + C]       = make_float2(d[mi][ni][0], d[mi][ni][1]);
            *(float2*)&stg[(R + 8) * 132 + C] = make_float2(d[mi][ni][2], d[mi][ni][3]);
        }
    }
    __syncthreads();

    const float* Mb = M + ((size_t)b * NN + row0) * DD;
    float*       Tb = T + ((size_t)b * NN + row0) * DD;
    float4 bg = *(const float4*)&bagg[lane * 4];
    #pragma unroll
    for (int i = 0; i < 16; i++) {
        int rr = wid * 16 + i;
        float4 raw = *(const float4*)&stg[rr * 132 + lane * 4];
        float4 mm  = *(const float4*)&Mb[(size_t)rr * DD + lane * 4];
        float v0 = fmaxf(raw.x + mm.x + bg.x, 0.f);
        float v1 = fmaxf(raw.y + mm.y + bg.y, 0.f);
        float v2 = fmaxf(raw.z + mm.z + bg.z, 0.f);
        float v3 = fmaxf(raw.w + mm.w + bg.w, 0.f);
        float ss = v0*v0 + v1*v1 + v2*v2 + v3*v3;
        #pragma unroll
        for (int o = 16; o > 0; o >>= 1)
            ss += __shfl_xor_sync(0xffffffffu, ss, o);
        float s = hyp_scale(sqrtf(ss));
        *(float4*)&Tb[(size_t)rr * DD + lane * 4] =
            make_float4(v0 * s, v1 * s, v2 * s, v3 * s);
    }
}

// ---------------------------------------------------------------------------
// Host launch
// ---------------------------------------------------------------------------
extern "C" void kernel_launch(void* const* d_in, const int* in_sizes, int n_in,
                              void* d_out, int out_size)
{
    const float* nf    = (const float*)d_in[0];
    const float* adj   = (const float*)d_in[1];
    const float* mask  = (const float*)d_in[2];
    const float* Wemb  = (const float*)d_in[3];
    const float* Wmsg  = (const float*)d_in[4];
    const float* bmsg  = (const float*)d_in[5];
    const float* Wagg  = (const float*)d_in[6];
    const float* bagg  = (const float*)d_in[7];
    const float* Wproj = (const float*)d_in[8];
    const float* bproj = (const float*)d_in[9];
    float* out = (float*)d_out;

    float *t, *m;
    uint16_t *ah, *m2h, *m2l, *wh, *wl;
    cudaGetSymbolAddress((void**)&t,   g_t);
    cudaGetSymbolAddress((void**)&m,   g_m);
    cudaGetSymbolAddress((void**)&ah,  g_ah);
    cudaGetSymbolAddress((void**)&m2h, g_m2h);
    cudaGetSymbolAddress((void**)&m2l, g_m2l);
    cudaGetSymbolAddress((void**)&wh,  g_wh);
    cudaGetSymbolAddress((void**)&wl,  g_wl);

    cudaFuncSetAttribute(agg_mma, cudaFuncAttributeMaxDynamicSharedMemorySize, AGG_SMEM);
    cudaFuncSetAttribute(chain_kernel<true>,  cudaFuncAttributeMaxDynamicSharedMemorySize, LIN_SMEM);
    cudaFuncSetAttribute(chain_kernel<false>, cudaFuncAttributeMaxDynamicSharedMemorySize, LIN_SMEM);
    cudaFuncSetAttribute(proj_kernel, cudaFuncAttributeMaxDynamicSharedMemorySize, LIN_SMEM);

    dim3 glin(ROWS / 64);          // 512
    dim3 gbig(NN / BMA, BATCH);    // 4 x 32 = 128

    split_adj<<<(BATCH * NN * NN / 4) / 256, 256>>>((const float4*)adj, (uint2*)ah);
    split_weights<<<6, 256>>>(Wemb, Wmsg, Wagg, Wproj, wh, wl);

    // layer 0: embed + hyp + msg + m2 fused
    chain_kernel<true><<<glin, 256, LIN_SMEM>>>(nf, wh, wl, 0, 1, 2,
                                                bmsg, m, m2h, m2l);
    agg_mma<<<gbig, 512, AGG_SMEM>>>(ah, m2h, m2l, m, bagg, t);

    // layer 1: msg + m2 fused
    chain_kernel<false><<<glin, 256, LIN_SMEM>>>(t, wh, wl, 0, 3, 4,
                                                 bmsg + DD, m, m2h, m2l);
    agg_mma<<<gbig, 512, AGG_SMEM>>>(ah, m2h, m2l, m, bagg + DD, t);

    // out = (t @ WprojT + bproj) * mask
    proj_kernel<<<glin, 256, LIN_SMEM>>>(t, wh, wl, bproj, mask, out);
}

// round 10
// speedup vs baseline: 2.3813x; 1.1549x over previous
#include <cuda_runtime.h>
#include <math.h>
#include <stdint.h>

// Problem constants
#define BATCH 32
#define NN    1024
#define DD    128
#define ROWS  (BATCH * NN)   // 32768

// Scratch (device globals — no allocation allowed)
__device__ float g_t[ROWS * DD];
__device__ float g_m[ROWS * DD];
// A-hi, chunk-tiled: [b][mt(4)][c(32)] -> 16KB block: r(256) x 64B, unit swizzle u^((r>>1)&3)
__device__ __align__(16) uint8_t g_aht[(size_t)BATCH * 4 * 32 * 16384];   // 64MB
// m2^T, chunk-tiled: [b][c(32)] -> 16KB block: n(128) x 128B (hi u0-3 || lo u4-7), swizzle unit3^(n&7)
__device__ __align__(16) uint8_t g_m2t[(size_t)BATCH * 32 * 16384];       // 16MB
__device__ __align__(16) uint16_t g_wh[6 * DD * DD];               // weights hi [n][k]
__device__ __align__(16) uint16_t g_wl[6 * DD * DD];               // weights lo

// ---------------------------------------------------------------------------
// Helpers
// ---------------------------------------------------------------------------
__device__ __forceinline__ uint32_t smem_u32(const void* p) {
    uint32_t a;
    asm("{ .reg .u64 t; cvta.to.shared.u64 t, %1; cvt.u32.u64 %0, t; }" : "=r"(a) : "l"(p));
    return a;
}
__device__ __forceinline__ uint32_t pack_bf16x2(float v0, float v1) {
    uint32_t r;
    asm("cvt.rn.bf16x2.f32 %0, %1, %2;" : "=r"(r) : "f"(v1), "f"(v0));
    return r;
}
__device__ __forceinline__ void split2(float v0, float v1, uint32_t& h, uint32_t& l) {
    h = pack_bf16x2(v0, v1);
    float r0 = v0 - __uint_as_float(h << 16);
    float r1 = v1 - __uint_as_float(h & 0xffff0000u);
    l = pack_bf16x2(r0, r1);
}
#define CP16(dst, src) \
    asm volatile("cp.async.cg.shared.global [%0], [%1], 16;" :: "r"(dst), "l"(src) : "memory")
#define CP_COMMIT() asm volatile("cp.async.commit_group;" ::: "memory")
#define CPWAIT(n)   asm volatile("cp.async.wait_group %0;" :: "n"(n) : "memory")

#define LDSM4(r0, r1, r2, r3, addr) \
    asm volatile("ldmatrix.sync.aligned.m8n8.x4.shared.b16 {%0,%1,%2,%3}, [%4];" \
        : "=r"(r0), "=r"(r1), "=r"(r2), "=r"(r3) : "r"(addr))

// 1D bulk async copy gmem->smem with mbarrier completion (sm_90 base feature)
#define BULK(dst, src, sz, mb) \
    asm volatile("cp.async.bulk.shared::cta.global.mbarrier::complete_tx::bytes [%0], [%1], %2, [%3];" \
        :: "r"(dst), "l"(src), "r"(sz), "r"(mb) : "memory")

#define MBAR_INIT(a, c) asm volatile("mbarrier.init.shared.b64 [%0], %1;" :: "r"(a), "r"(c) : "memory")
#define MBAR_EXPECT_TX(a, b) asm volatile("mbarrier.arrive.expect_tx.shared.b64 _, [%0], %1;" :: "r"(a), "r"(b) : "memory")
#define FENCE_ASYNC() asm volatile("fence.proxy.async.shared::cta;" ::: "memory")

#define MBAR_WAIT(a, ph) do { \
    uint32_t _m = (a), _p = (uint32_t)(ph), _d; \
    asm volatile("{ .reg .pred p; mbarrier.try_wait.parity.acquire.cta.shared::cta.b64 p, [%1], %2; selp.b32 %0, 1, 0, p; }" \
        : "=r"(_d) : "r"(_m), "r"(_p) : "memory"); \
    if (!_d) { \
        asm volatile("{ .reg .pred P1; WL_%=: mbarrier.try_wait.parity.acquire.cta.shared::cta.b64 P1, [%0], %1, 0x989680; @P1 bra.uni WD_%=; bra.uni WL_%=; WD_%=: }" \
            :: "r"(_m), "r"(_p) : "memory"); \
    } } while (0)

__device__ __forceinline__ void mma_bf16(float d[4], const uint32_t a[4],
                                         uint32_t b0, uint32_t b1) {
    asm volatile(
        "mma.sync.aligned.m16n8k16.row.col.f32.bf16.bf16.f32 "
        "{%0,%1,%2,%3}, {%4,%5,%6,%7}, {%8,%9}, {%0,%1,%2,%3};"
        : "+f"(d[0]), "+f"(d[1]), "+f"(d[2]), "+f"(d[3])
        : "r"(a[0]), "r"(a[1]), "r"(a[2]), "r"(a[3]), "r"(b0), "r"(b1));
}

// Composite per-row scale: logmap0(proj(expmap0(h))) = s(||h||) * h
__device__ __forceinline__ float hyp_scale(float n) {
    const float EPS  = 1e-7f;
    const float MAXN = 1.0f - 1e-5f;
    float n1 = fmaxf(n, EPS);
    float r  = tanhf(n1) / n1;
    float xn = r * n;
    float n2 = fmaxf(xn, EPS);
    float s2 = (n2 > MAXN) ? (MAXN / n2) : 1.0f;
    float x2 = s2 * xn;
    float n3 = fmaxf(x2, EPS);
    float z  = fminf(n3, 1.0f - EPS);
    float lg = atanhf(z) / n3;
    return r * s2 * lg;
}

// ---------------------------------------------------------------------------
// 3-product warp-tile MMA over merged hi/lo smem tiles (chain/proj kernels).
// ---------------------------------------------------------------------------
template<int PITCH, int LOOFF, int NKS, int MI>
__device__ __forceinline__ void mma_blk(uint32_t Ab, uint32_t Bb,
                                        int wma, int wnb, int lane,
                                        float (&d)[MI][4][4]) {
    const int lg = lane >> 3;
    const int lr = lane & 7;
    const uint32_t aBase = Ab + (uint32_t)((wma * (MI * 16) + (lg & 1) * 8 + lr) * PITCH
                                           + (lg >> 1) * 16);
    const uint32_t bBase = Bb + (uint32_t)((wnb * 32 + lr) * PITCH + (lg & 1) * 16
                                           + ((lg >> 1) ? LOOFF : 0));
    #pragma unroll
    for (int ks = 0; ks < NKS; ks++) {
        const uint32_t kb = (uint32_t)ks * 32;
        uint32_t bh[4][2], bl[4][2];
        #pragma unroll
        for (int ni = 0; ni < 4; ni++)
            LDSM4(bh[ni][0], bh[ni][1], bl[ni][0], bl[ni][1],
                  bBase + ni * 8 * PITCH + kb);
        #pragma unroll
        for (int mi = 0; mi < MI; mi++) {
            uint32_t ah[4], al[4];
            LDSM4(ah[0], ah[1], ah[2], ah[3], aBase + mi * 16 * PITCH + kb);
            LDSM4(al[0], al[1], al[2], al[3], aBase + mi * 16 * PITCH + kb + LOOFF);
            #pragma unroll
            for (int ni = 0; ni < 4; ni++) {
                mma_bf16(d[mi][ni], ah, bh[ni][0], bh[ni][1]);
                mma_bf16(d[mi][ni], ah, bl[ni][0], bl[ni][1]);
                mma_bf16(d[mi][ni], al, bh[ni][0], bh[ni][1]);
            }
        }
    }
}

// ---------------------------------------------------------------------------
// One-time adjacency split -> chunk-tiled, swizzled bf16-hi blocks.
// One thread per 16B output unit (8 k values).
// ---------------------------------------------------------------------------
__global__ void __launch_bounds__(256) split_adj(const float* __restrict__ a,
                                                 uint8_t* __restrict__ out) {
    int t = blockIdx.x * 256 + threadIdx.x;     // 0 .. 4M-1
    int u32i = t & 127;           // k/8
    int rowg = (t >> 7) & 1023;
    int b    = t >> 17;
    const float* src = a + ((size_t)b * NN + rowg) * NN + u32i * 8;
    float4 v0 = *(const float4*)src;
    float4 v1 = *(const float4*)(src + 4);
    uint4 w = make_uint4(pack_bf16x2(v0.x, v0.y), pack_bf16x2(v0.z, v0.w),
                         pack_bf16x2(v1.x, v1.y), pack_bf16x2(v1.z, v1.w));
    int mt = rowg >> 8, r = rowg & 255, c = u32i >> 2, u = u32i & 3;
    size_t dst = (((((size_t)(b * 4 + mt)) * 32 + c) * 256 + r) * 4
                  + (u ^ ((r >> 1) & 3))) * 16;
    *(uint4*)(out + dst) = w;
}

// ---------------------------------------------------------------------------
// One-time weight split into [n][k] bf16 hi/lo.
// ---------------------------------------------------------------------------
__global__ void __launch_bounds__(256) split_weights(
    const float* __restrict__ Wemb, const float* __restrict__ Wmsg,
    const float* __restrict__ Wagg, const float* __restrict__ Wproj,
    uint16_t* __restrict__ WH, uint16_t* __restrict__ WL)
{
    int mat = blockIdx.x;
    const float* src;
    bool trans;
    switch (mat) {
        case 0:  src = Wemb;            trans = false; break;
        case 1:  src = Wmsg;            trans = true;  break;
        case 2:  src = Wagg;            trans = true;  break;
        case 3:  src = Wmsg + DD * DD;  trans = true;  break;
        case 4:  src = Wagg + DD * DD;  trans = true;  break;
        default: src = Wproj;           trans = false; break;
    }
    for (int idx = threadIdx.x; idx < DD * DD; idx += 256) {
        int n = idx >> 7, k = idx & 127;
        float v = trans ? src[k * DD + n] : src[idx];
        uint32_t p = pack_bf16x2(v, 0.f);
        uint16_t hh = (uint16_t)(p & 0xffffu);
        float r = v - __uint_as_float((uint32_t)hh << 16);
        uint32_t pl = pack_bf16x2(r, 0.f);
        WH[mat * DD * DD + idx] = hh;
        WL[mat * DD * DD + idx] = (uint16_t)(pl & 0xffffu);
    }
}

// ---------------------------------------------------------------------------
// Chain / proj smem layout: merged hi||lo rows, pitch 528.
// ---------------------------------------------------------------------------
#define PW 528
#define XBYTES (64 * PW)
#define WBYTES (128 * PW)
#define LIN_SMEM (XBYTES + WBYTES)    // 101376 -> 2 CTAs/SM

__device__ __forceinline__ void ldgsplit_X64(const float* __restrict__ g,
                                             char* X, int tid) {
    int row = tid >> 2;
    int c0  = (tid & 3) * 32;
    const float* gp = g + (size_t)row * DD + c0;
    char* ph = X + row * PW + c0 * 2;
    char* pl = ph + 256;
    #pragma unroll
    for (int i = 0; i < 8; i++) {
        float4 v = *(const float4*)(gp + i * 4);
        uint32_t h0, l0, h1, l1;
        split2(v.x, v.y, h0, l0);
        split2(v.z, v.w, h1, l1);
        *(uint2*)(ph + i * 8) = make_uint2(h0, h1);
        *(uint2*)(pl + i * 8) = make_uint2(l0, l1);
    }
}

__device__ __forceinline__ void cpw(const uint16_t* __restrict__ WHg,
                                    const uint16_t* __restrict__ WLg,
                                    int mat, uint32_t wbase, int tid) {
    int n = tid >> 1, half = tid & 1;
    const char* src = (const char*)((half ? WLg : WHg) + (size_t)mat * DD * DD + n * DD);
    uint32_t dst = wbase + (uint32_t)(n * PW + half * 256);
    #pragma unroll
    for (int q = 0; q < 16; q++)
        CP16(dst + q * 16, src + q * 16);
}

// m2^T tiled store: value pair (h,l) for (b, n, k..k+1)
__device__ __forceinline__ void store_m2(uint8_t* __restrict__ M2, int b, int n,
                                         int k, uint32_t h, uint32_t l) {
    int c  = k >> 5;
    int u2 = (k >> 3) & 3;
    uint8_t* p = M2 + (((size_t)(b * 32 + c)) * 128 + n) * 128;
    int w = (k & 7) * 2;
    *(uint32_t*)(p + ((u2 ^ (n & 7)) * 16) + w)       = h;
    *(uint32_t*)(p + (((4 + u2) ^ (n & 7)) * 16) + w) = l;
}

// ---------------------------------------------------------------------------
// Fused chain kernel (64-row tiles, 512 CTAs, 2 CTA/SM)
// ---------------------------------------------------------------------------
template<bool FIRST>
__global__ void __launch_bounds__(256, 2) chain_kernel(
    const float* __restrict__ X,
    const uint16_t* __restrict__ WHg, const uint16_t* __restrict__ WLg,
    int emb_mat, int w1_mat, int w2_mat,
    const float* __restrict__ bias1,
    float* __restrict__ Mout,
    uint8_t* __restrict__ M2)
{
    extern __shared__ char smem[];
    const uint32_t sX = smem_u32(smem);
    const uint32_t sW = sX + XBYTES;
    char* Xp = smem;

    const int tid = threadIdx.x, lane = tid & 31, wid = tid >> 5;
    const int wm = wid & 1, wn = wid >> 1;
    const int wm2 = wid & 3, wn2 = wid >> 2;
    const int row0 = blockIdx.x * 64;
    const int bb = row0 >> 10;
    const int rb = row0 & 1023;

    float d[2][4][4];

    if (FIRST) {
        cpw(WHg, WLg, emb_mat, sW, tid);
        CP_COMMIT();
        ldgsplit_X64(X + (size_t)row0 * DD, Xp, tid);
        CPWAIT(0);
        __syncthreads();

        #pragma unroll
        for (int i = 0; i < 2; i++)
            #pragma unroll
            for (int j = 0; j < 4; j++)
                #pragma unroll
                for (int q = 0; q < 4; q++) d[i][j][q] = 0.f;
        mma_blk<PW, 256, 8, 2>(sX, sW, wm, wn, lane, d);
        __syncthreads();

        cpw(WHg, WLg, w1_mat, sW, tid);
        CP_COMMIT();

        float* stg = (float*)Xp;
        #pragma unroll
        for (int mi = 0; mi < 2; mi++) {
            int R = wm * 32 + mi * 16 + (lane >> 2);
            #pragma unroll
            for (int ni = 0; ni < 4; ni++) {
                int C = wn * 32 + ni * 8 + (lane & 3) * 2;
                stg[R * 132 + C]           = d[mi][ni][0];
                stg[R * 132 + C + 1]       = d[mi][ni][1];
                stg[(R + 8) * 132 + C]     = d[mi][ni][2];
                stg[(R + 8) * 132 + C + 1] = d[mi][ni][3];
            }
        }
        __syncthreads();

        #pragma unroll
        for (int i = 0; i < 8; i++) {
            int rr = wid * 8 + i;
            float4 v = *(float4*)&stg[rr * 132 + lane * 4];
            float ss = v.x * v.x + v.y * v.y + v.z * v.z + v.w * v.w;
            #pragma unroll
            for (int o = 16; o > 0; o >>= 1)
                ss += __shfl_xor_sync(0xffffffffu, ss, o);
            float s = hyp_scale(sqrtf(ss));
            v.x *= s; v.y *= s; v.z *= s; v.w *= s;
            __syncwarp();
            uint32_t h0, l0, h1, l1;
            split2(v.x, v.y, h0, l0);
            split2(v.z, v.w, h1, l1);
            *(uint2*)(Xp + rr * PW + lane * 8)       = make_uint2(h0, h1);
            *(uint2*)(Xp + rr * PW + 256 + lane * 8) = make_uint2(l0, l1);
        }
        CPWAIT(0);
        __syncthreads();
    } else {
        cpw(WHg, WLg, w1_mat, sW, tid);
        CP_COMMIT();
        ldgsplit_X64(X + (size_t)row0 * DD, Xp, tid);
        CPWAIT(0);
        __syncthreads();
    }

    // GEMM1: m = t @ W1 + b1
    #pragma unroll
    for (int i = 0; i < 2; i++)
        #pragma unroll
        for (int j = 0; j < 4; j++)
            #pragma unroll
            for (int q = 0; q < 4; q++) d[i][j][q] = 0.f;
    mma_blk<PW, 256, 8, 2>(sX, sW, wm, wn, lane, d);
    __syncthreads();

    cpw(WHg, WLg, w2_mat, sW, tid);
    CP_COMMIT();

    #pragma unroll
    for (int mi = 0; mi < 2; mi++) {
        int R = wm * 32 + mi * 16 + (lane >> 2);
        #pragma unroll
        for (int ni = 0; ni < 4; ni++) {
            int C = wn * 32 + ni * 8 + (lane & 3) * 2;
            float b0 = bias1[C], b1 = bias1[C + 1];
            float v0 = d[mi][ni][0] + b0, v1 = d[mi][ni][1] + b1;
            float v2 = d[mi][ni][2] + b0, v3 = d[mi][ni][3] + b1;
            *(float2*)&Mout[(size_t)(row0 + R) * DD + C]     = make_float2(v0, v1);
            *(float2*)&Mout[(size_t)(row0 + R + 8) * DD + C] = make_float2(v2, v3);
            uint32_t h, l;
            split2(v0, v1, h, l);
            *(uint32_t*)(Xp + R * PW + C * 2)       = h;
            *(uint32_t*)(Xp + R * PW + 256 + C * 2) = l;
            split2(v2, v3, h, l);
            *(uint32_t*)(Xp + (R + 8) * PW + C * 2)       = h;
            *(uint32_t*)(Xp + (R + 8) * PW + 256 + C * 2) = l;
        }
    }
    CPWAIT(0);
    __syncthreads();

    // GEMM2: m2T[n][r] = sum_k W2n[n][k] * m[r][k]
    float e[2][4][4];
    #pragma unroll
    for (int i = 0; i < 2; i++)
        #pragma unroll
        for (int j = 0; j < 4; j++)
            #pragma unroll
            for (int q = 0; q < 4; q++) e[i][j][q] = 0.f;
    mma_blk<PW, 256, 8, 2>(sW, sX, wm2, wn2, lane, e);

    #pragma unroll
    for (int mi = 0; mi < 2; mi++) {
        int Rn = wm2 * 32 + mi * 16 + (lane >> 2);
        #pragma unroll
        for (int ni = 0; ni < 4; ni++) {
            int Cr = wn2 * 32 + ni * 8 + (lane & 3) * 2;
            uint32_t h, l;
            split2(e[mi][ni][0], e[mi][ni][1], h, l);
            store_m2(M2, bb, Rn, rb + Cr, h, l);
            split2(e[mi][ni][2], e[mi][ni][3], h, l);
            store_m2(M2, bb, Rn + 8, rb + Cr, h, l);
        }
    }
}

// ---------------------------------------------------------------------------
// Final projection: out = (t @ WprojT + bp) * mask
// ---------------------------------------------------------------------------
__global__ void __launch_bounds__(256, 2) proj_kernel(
    const float* __restrict__ X,
    const uint16_t* __restrict__ WHg, const uint16_t* __restrict__ WLg,
    const float* __restrict__ bp, const float* __restrict__ mask,
    float* __restrict__ out)
{
    extern __shared__ char smem[];
    const uint32_t sX = smem_u32(smem);
    const uint32_t sW = sX + XBYTES;
    const int tid = threadIdx.x, lane = tid & 31, wid = tid >> 5;
    const int wm = wid & 1, wn = wid >> 1;
    const int row0 = blockIdx.x * 64;

    cpw(WHg, WLg, 5, sW, tid);
    CP_COMMIT();
    ldgsplit_X64(X + (size_t)row0 * DD, smem, tid);
    CPWAIT(0);
    __syncthreads();

    float d[2][4][4];
    #pragma unroll
    for (int i = 0; i < 2; i++)
        #pragma unroll
        for (int j = 0; j < 4; j++)
            #pragma unroll
            for (int q = 0; q < 4; q++) d[i][j][q] = 0.f;
    mma_blk<PW, 256, 8, 2>(sX, sW, wm, wn, lane, d);

    #pragma unroll
    for (int mi = 0; mi < 2; mi++) {
        int R = wm * 32 + mi * 16 + (lane >> 2);
        float mk0 = mask[row0 + R];
        float mk1 = mask[row0 + R + 8];
        #pragma unroll
        for (int ni = 0; ni < 4; ni++) {
            int C = wn * 32 + ni * 8 + (lane & 3) * 2;
            float b0 = bp[C], b1 = bp[C + 1];
            *(float2*)&out[(size_t)(row0 + R) * DD + C] =
                make_float2((d[mi][ni][0] + b0) * mk0, (d[mi][ni][1] + b1) * mk0);
            *(float2*)&out[(size_t)(row0 + R + 8) * DD + C] =
                make_float2((d[mi][ni][2] + b0) * mk1, (d[mi][ni][3] + b1) * mk1);
        }
    }
}

// ---------------------------------------------------------------------------
// Big GEMM: BM=256, 512 threads, 1 CTA/SM, cp.async.bulk (2 instr/chunk).
//   Stage = A block 16KB (256 x 64B swizzled) + B block 16KB (128 x 128B).
//   4-stage mbarrier pipeline: wait(c) -> barrier -> issue(c+3) -> mma(c).
// ---------------------------------------------------------------------------
#define BMA     256
#define STG     32768
#define MBAR_OFF (4 * STG)             // 131072
#define AGG_SMEM 135168                // covers 256x132 f32 epilogue staging

__global__ void __launch_bounds__(512, 1) agg_mma(
    const uint8_t* __restrict__ AT, const uint8_t* __restrict__ BT,
    const float* __restrict__ M, const float* __restrict__ bagg,
    float* __restrict__ T)
{
    extern __shared__ char smem[];
    const uint32_t sb = smem_u32(smem);
    const uint32_t mb = sb + MBAR_OFF;
    const int tid  = threadIdx.x;
    const int lane = tid & 31;
    const int wid  = tid >> 5;          // 0..15
    const int b    = blockIdx.y;
    const int mt   = blockIdx.x;        // 256-row tile index
    const int row0 = mt * BMA;
    const int wm   = wid & 3;           // 4 m groups x 64 rows
    const int wn   = wid >> 2;          // 4 n groups x 32 cols

    const uint8_t* gA = AT + ((size_t)(b * 4 + mt) * 32) * 16384;
    const uint8_t* gB = BT + ((size_t)b * 32) * 16384;

    if (tid == 0) {
        #pragma unroll
        for (int s = 0; s < 4; s++) MBAR_INIT(mb + s * 8, 1);
        FENCE_ASYNC();
    }
    __syncthreads();

    auto issue = [&](int c) {
        int s = c & 3;
        MBAR_EXPECT_TX(mb + s * 8, 32768u);
        BULK(sb + (uint32_t)s * STG,         gA + (size_t)c * 16384, 16384u, mb + s * 8);
        BULK(sb + (uint32_t)s * STG + 16384, gB + (size_t)c * 16384, 16384u, mb + s * 8);
    };

    if (tid == 0) { issue(0); issue(1); issue(2); }

    float d[4][4][4];
    #pragma unroll
    for (int i = 0; i < 4; i++)
        #pragma unroll
        for (int j = 0; j < 4; j++)
            #pragma unroll
            for (int q = 0; q < 4; q++) d[i][j][q] = 0.f;

    const int lg = lane >> 3, lr = lane & 7;
    // A fragment: row rbase + mi*16, k-unit (ks*2 + lg>>1) ^ swzA
    const int rbase = wm * 64 + (lg & 1) * 8 + lr;
    const uint32_t swzA = (uint32_t)((rbase >> 1) & 3);
    // B fragment: row nbase + ni*8, unit3 ((lg>>1)*4 + ks*2 + (lg&1)) ^ swzB
    const int nbase = wn * 32 + lr;
    const uint32_t swzB = (uint32_t)(nbase & 7);
    const uint32_t u3base = (uint32_t)((lg >> 1) * 4 + (lg & 1));

    int ph[4] = {0, 0, 0, 0};

    for (int c = 0; c < 32; c++) {
        int s = c & 3;
        MBAR_WAIT(mb + s * 8, ph[s]);
        ph[s] ^= 1;
        __syncthreads();                // publishes data; retires stage (c-1)&3 readers
        if (tid == 0 && c + 3 < 32) issue(c + 3);

        uint32_t aBase = sb + (uint32_t)s * STG;
        uint32_t bBase = aBase + 16384;
        #pragma unroll
        for (int ks = 0; ks < 2; ks++) {
            uint32_t bh[4][2], bl[4][2];
            const uint32_t ub = ((u3base + ks * 2) ^ swzB) * 16;
            #pragma unroll
            for (int ni = 0; ni < 4; ni++)
                LDSM4(bh[ni][0], bh[ni][1], bl[ni][0], bl[ni][1],
                      bBase + (uint32_t)(nbase + ni * 8) * 128 + ub);
            const uint32_t ua = (((uint32_t)(ks * 2 + (lg >> 1))) ^ swzA) * 16;
            #pragma unroll
            for (int mi = 0; mi < 4; mi++) {
                uint32_t ah[4];
                LDSM4(ah[0], ah[1], ah[2], ah[3],
                      aBase + (uint32_t)(rbase + mi * 16) * 64 + ua);
                #pragma unroll
                for (int ni = 0; ni < 4; ni++) {
                    mma_bf16(d[mi][ni], ah, bh[ni][0], bh[ni][1]);
                    mma_bf16(d[mi][ni], ah, bl[ni][0], bl[ni][1]);
                }
            }
        }
    }
    __syncthreads();                    // drain readers of last stage

    // stage D to smem (f32, pitch 132, 256 rows)
    float* stg = (float*)smem;
    #pragma unroll
    for (int mi = 0; mi < 4; mi++) {
        int R = wm * 64 + mi * 16 + (lane >> 2);
        #pragma unroll
        for (int ni = 0; ni < 4; ni++) {
            int C = wn * 32 + ni * 8 + (lane & 3) * 2;
            *(float2*)&stg[R * 132 + C]       = make_float2(d[mi][ni][0], d[mi][ni][1]);
            *(float2*)&stg[(R + 8) * 132 + C] = make_float2(d[mi][ni][2], d[mi][ni][3]);
        }
    }
    __syncthreads();

    const float* Mb = M + ((size_t)b * NN + row0) * DD;
    float*       Tb = T + ((size_t)b * NN + row0) * DD;
    float4 bg = *(const float4*)&bagg[lane * 4];
    #pragma unroll
    for (int i = 0; i < 16; i++) {
        int rr = wid * 16 + i;
        float4 raw = *(const float4*)&stg[rr * 132 + lane * 4];
        float4 mm  = *(const float4*)&Mb[(size_t)rr * DD + lane * 4];
        float v0 = fmaxf(raw.x + mm.x + bg.x, 0.f);
        float v1 = fmaxf(raw.y + mm.y + bg.y, 0.f);
        float v2 = fmaxf(raw.z + mm.z + bg.z, 0.f);
        float v3 = fmaxf(raw.w + mm.w + bg.w, 0.f);
        float ss = v0*v0 + v1*v1 + v2*v2 + v3*v3;
        #pragma unroll
        for (int o = 16; o > 0; o >>= 1)
            ss += __shfl_xor_sync(0xffffffffu, ss, o);
        float s = hyp_scale(sqrtf(ss));
        *(float4*)&Tb[(size_t)rr * DD + lane * 4] =
            make_float4(v0 * s, v1 * s, v2 * s, v3 * s);
    }
}

// ---------------------------------------------------------------------------
// Host launch
// ---------------------------------------------------------------------------
extern "C" void kernel_launch(void* const* d_in, const int* in_sizes, int n_in,
                              void* d_out, int out_size)
{
    const float* nf    = (const float*)d_in[0];
    const float* adj   = (const float*)d_in[1];
    const float* mask  = (const float*)d_in[2];
    const float* Wemb  = (const float*)d_in[3];
    const float* Wmsg  = (const float*)d_in[4];
    const float* bmsg  = (const float*)d_in[5];
    const float* Wagg  = (const float*)d_in[6];
    const float* bagg  = (const float*)d_in[7];
    const float* Wproj = (const float*)d_in[8];
    const float* bproj = (const float*)d_in[9];
    float* out = (float*)d_out;

    float *t, *m;
    uint8_t *aht, *m2t;
    uint16_t *wh, *wl;
    cudaGetSymbolAddress((void**)&t,   g_t);
    cudaGetSymbolAddress((void**)&m,   g_m);
    cudaGetSymbolAddress((void**)&aht, g_aht);
    cudaGetSymbolAddress((void**)&m2t, g_m2t);
    cudaGetSymbolAddress((void**)&wh,  g_wh);
    cudaGetSymbolAddress((void**)&wl,  g_wl);

    cudaFuncSetAttribute(agg_mma, cudaFuncAttributeMaxDynamicSharedMemorySize, AGG_SMEM);
    cudaFuncSetAttribute(chain_kernel<true>,  cudaFuncAttributeMaxDynamicSharedMemorySize, LIN_SMEM);
    cudaFuncSetAttribute(chain_kernel<false>, cudaFuncAttributeMaxDynamicSharedMemorySize, LIN_SMEM);
    cudaFuncSetAttribute(proj_kernel, cudaFuncAttributeMaxDynamicSharedMemorySize, LIN_SMEM);

    dim3 glin(ROWS / 64);          // 512
    dim3 gbig(NN / BMA, BATCH);    // 4 x 32 = 128

    split_adj<<<(BATCH * NN * (NN / 8)) / 256, 256>>>(adj, aht);
    split_weights<<<6, 256>>>(Wemb, Wmsg, Wagg, Wproj, wh, wl);

    // layer 0: embed + hyp + msg + m2 fused
    chain_kernel<true><<<glin, 256, LIN_SMEM>>>(nf, wh, wl, 0, 1, 2,
                                                bmsg, m, m2t);
    agg_mma<<<gbig, 512, AGG_SMEM>>>(aht, m2t, m, bagg, t);

    // layer 1: msg + m2 fused
    chain_kernel<false><<<glin, 256, LIN_SMEM>>>(t, wh, wl, 0, 3, 4,
                                                 bmsg + DD, m, m2t);
    agg_mma<<<gbig, 512, AGG_SMEM>>>(aht, m2t, m, bagg + DD, t);

    // out = (t @ WprojT + bproj) * mask
    proj_kernel<<<glin, 256, LIN_SMEM>>>(t, wh, wl, bproj, mask, out);
}

// round 11
// speedup vs baseline: 2.3832x; 1.0008x over previous
#include <cuda_runtime.h>
#include <math.h>
#include <stdint.h>

// Problem constants
#define BATCH 32
#define NN    1024
#define DD    128
#define ROWS  (BATCH * NN)   // 32768

// Scratch (device globals — no allocation allowed)
__device__ float g_t[ROWS * DD];
__device__ float g_m[ROWS * DD];
// A-hi, chunk-tiled: [b][mt(4)][c(32)] -> 16KB block: r(256) x 64B, unit swizzle u^((r>>1)&3)
__device__ __align__(16) uint8_t g_aht[(size_t)BATCH * 4 * 32 * 16384];   // 64MB
// m2^T, chunk-tiled: [b][c(32)] -> 16KB block: n(128) x 128B (hi u0-3 || lo u4-7), swizzle unit3^(n&7)
__device__ __align__(16) uint8_t g_m2t[(size_t)BATCH * 32 * 16384];       // 16MB
__device__ __align__(16) uint16_t g_wh[6 * DD * DD];               // weights hi [n][k]
__device__ __align__(16) uint16_t g_wl[6 * DD * DD];               // weights lo

// ---------------------------------------------------------------------------
// Helpers
// ---------------------------------------------------------------------------
__device__ __forceinline__ uint32_t smem_u32(const void* p) {
    uint32_t a;
    asm("{ .reg .u64 t; cvta.to.shared.u64 t, %1; cvt.u32.u64 %0, t; }" : "=r"(a) : "l"(p));
    return a;
}
__device__ __forceinline__ uint32_t pack_bf16x2(float v0, float v1) {
    uint32_t r;
    asm("cvt.rn.bf16x2.f32 %0, %1, %2;" : "=r"(r) : "f"(v1), "f"(v0));
    return r;
}
__device__ __forceinline__ void split2(float v0, float v1, uint32_t& h, uint32_t& l) {
    h = pack_bf16x2(v0, v1);
    float r0 = v0 - __uint_as_float(h << 16);
    float r1 = v1 - __uint_as_float(h & 0xffff0000u);
    l = pack_bf16x2(r0, r1);
}
#define CP16(dst, src) \
    asm volatile("cp.async.cg.shared.global [%0], [%1], 16;" :: "r"(dst), "l"(src) : "memory")
#define CP_COMMIT() asm volatile("cp.async.commit_group;" ::: "memory")
#define CPWAIT(n)   asm volatile("cp.async.wait_group %0;" :: "n"(n) : "memory")

#define LDSM4(r0, r1, r2, r3, addr) \
    asm volatile("ldmatrix.sync.aligned.m8n8.x4.shared.b16 {%0,%1,%2,%3}, [%4];" \
        : "=r"(r0), "=r"(r1), "=r"(r2), "=r"(r3) : "r"(addr))

// 1D bulk async copy gmem->smem with mbarrier completion (sm_90 base feature)
#define BULK(dst, src, sz, mb) \
    asm volatile("cp.async.bulk.shared::cta.global.mbarrier::complete_tx::bytes [%0], [%1], %2, [%3];" \
        :: "r"(dst), "l"(src), "r"(sz), "r"(mb) : "memory")

#define MBAR_INIT(a, c) asm volatile("mbarrier.init.shared.b64 [%0], %1;" :: "r"(a), "r"(c) : "memory")
#define MBAR_EXPECT_TX(a, b) asm volatile("mbarrier.arrive.expect_tx.shared.b64 _, [%0], %1;" :: "r"(a), "r"(b) : "memory")
#define MBAR_ARRIVE(a) asm volatile("mbarrier.arrive.shared.b64 _, [%0];" :: "r"(a) : "memory")
#define FENCE_ASYNC() asm volatile("fence.proxy.async.shared::cta;" ::: "memory")

#define MBAR_WAIT(a, ph) do { \
    uint32_t _m = (a), _p = (uint32_t)(ph), _d; \
    asm volatile("{ .reg .pred p; mbarrier.try_wait.parity.acquire.cta.shared::cta.b64 p, [%1], %2; selp.b32 %0, 1, 0, p; }" \
        : "=r"(_d) : "r"(_m), "r"(_p) : "memory"); \
    if (!_d) { \
        asm volatile("{ .reg .pred P1; WL_%=: mbarrier.try_wait.parity.acquire.cta.shared::cta.b64 P1, [%0], %1, 0x989680; @P1 bra.uni WD_%=; bra.uni WL_%=; WD_%=: }" \
            :: "r"(_m), "r"(_p) : "memory"); \
    } } while (0)

__device__ __forceinline__ void mma_bf16(float d[4], const uint32_t a[4],
                                         uint32_t b0, uint32_t b1) {
    asm volatile(
        "mma.sync.aligned.m16n8k16.row.col.f32.bf16.bf16.f32 "
        "{%0,%1,%2,%3}, {%4,%5,%6,%7}, {%8,%9}, {%0,%1,%2,%3};"
        : "+f"(d[0]), "+f"(d[1]), "+f"(d[2]), "+f"(d[3])
        : "r"(a[0]), "r"(a[1]), "r"(a[2]), "r"(a[3]), "r"(b0), "r"(b1));
}

// Composite per-row scale: logmap0(proj(expmap0(h))) = s(||h||) * h
__device__ __forceinline__ float hyp_scale(float n) {
    const float EPS  = 1e-7f;
    const float MAXN = 1.0f - 1e-5f;
    float n1 = fmaxf(n, EPS);
    float r  = tanhf(n1) / n1;
    float xn = r * n;
    float n2 = fmaxf(xn, EPS);
    float s2 = (n2 > MAXN) ? (MAXN / n2) : 1.0f;
    float x2 = s2 * xn;
    float n3 = fmaxf(x2, EPS);
    float z  = fminf(n3, 1.0f - EPS);
    float lg = atanhf(z) / n3;
    return r * s2 * lg;
}

// ---------------------------------------------------------------------------
// 3-product warp-tile MMA over merged hi/lo smem tiles (chain/proj kernels).
// ---------------------------------------------------------------------------
template<int PITCH, int LOOFF, int NKS, int MI>
__device__ __forceinline__ void mma_blk(uint32_t Ab, uint32_t Bb,
                                        int wma, int wnb, int lane,
                                        float (&d)[MI][4][4]) {
    const int lg = lane >> 3;
    const int lr = lane & 7;
    const uint32_t aBase = Ab + (uint32_t)((wma * (MI * 16) + (lg & 1) * 8 + lr) * PITCH
                                           + (lg >> 1) * 16);
    const uint32_t bBase = Bb + (uint32_t)((wnb * 32 + lr) * PITCH + (lg & 1) * 16
                                           + ((lg >> 1) ? LOOFF : 0));
    #pragma unroll
    for (int ks = 0; ks < NKS; ks++) {
        const uint32_t kb = (uint32_t)ks * 32;
        uint32_t bh[4][2], bl[4][2];
        #pragma unroll
        for (int ni = 0; ni < 4; ni++)
            LDSM4(bh[ni][0], bh[ni][1], bl[ni][0], bl[ni][1],
                  bBase + ni * 8 * PITCH + kb);
        #pragma unroll
        for (int mi = 0; mi < MI; mi++) {
            uint32_t ah[4], al[4];
            LDSM4(ah[0], ah[1], ah[2], ah[3], aBase + mi * 16 * PITCH + kb);
            LDSM4(al[0], al[1], al[2], al[3], aBase + mi * 16 * PITCH + kb + LOOFF);
            #pragma unroll
            for (int ni = 0; ni < 4; ni++) {
                mma_bf16(d[mi][ni], ah, bh[ni][0], bh[ni][1]);
                mma_bf16(d[mi][ni], ah, bl[ni][0], bl[ni][1]);
                mma_bf16(d[mi][ni], al, bh[ni][0], bh[ni][1]);
            }
        }
    }
}

// ---------------------------------------------------------------------------
// One-time adjacency split -> chunk-tiled, swizzled bf16-hi blocks.
// ---------------------------------------------------------------------------
__global__ void __launch_bounds__(256) split_adj(const float* __restrict__ a,
                                                 uint8_t* __restrict__ out) {
    int t = blockIdx.x * 256 + threadIdx.x;     // 0 .. 4M-1
    int u32i = t & 127;           // k/8
    int rowg = (t >> 7) & 1023;
    int b    = t >> 17;
    const float* src = a + ((size_t)b * NN + rowg) * NN + u32i * 8;
    float4 v0 = *(const float4*)src;
    float4 v1 = *(const float4*)(src + 4);
    uint4 w = make_uint4(pack_bf16x2(v0.x, v0.y), pack_bf16x2(v0.z, v0.w),
                         pack_bf16x2(v1.x, v1.y), pack_bf16x2(v1.z, v1.w));
    int mt = rowg >> 8, r = rowg & 255, c = u32i >> 2, u = u32i & 3;
    size_t dst = (((((size_t)(b * 4 + mt)) * 32 + c) * 256 + r) * 4
                  + (u ^ ((r >> 1) & 3))) * 16;
    *(uint4*)(out + dst) = w;
}

// ---------------------------------------------------------------------------
// One-time weight split into [n][k] bf16 hi/lo.
// ---------------------------------------------------------------------------
__global__ void __launch_bounds__(256) split_weights(
    const float* __restrict__ Wemb, const float* __restrict__ Wmsg,
    const float* __restrict__ Wagg, const float* __restrict__ Wproj,
    uint16_t* __restrict__ WH, uint16_t* __restrict__ WL)
{
    int mat = blockIdx.x;
    const float* src;
    bool trans;
    switch (mat) {
        case 0:  src = Wemb;            trans = false; break;
        case 1:  src = Wmsg;            trans = true;  break;
        case 2:  src = Wagg;            trans = true;  break;
        case 3:  src = Wmsg + DD * DD;  trans = true;  break;
        case 4:  src = Wagg + DD * DD;  trans = true;  break;
        default: src = Wproj;           trans = false; break;
    }
    for (int idx = threadIdx.x; idx < DD * DD; idx += 256) {
        int n = idx >> 7, k = idx & 127;
        float v = trans ? src[k * DD + n] : src[idx];
        uint32_t p = pack_bf16x2(v, 0.f);
        uint16_t hh = (uint16_t)(p & 0xffffu);
        float r = v - __uint_as_float((uint32_t)hh << 16);
        uint32_t pl = pack_bf16x2(r, 0.f);
        WH[mat * DD * DD + idx] = hh;
        WL[mat * DD * DD + idx] = (uint16_t)(pl & 0xffffu);
    }
}

// ---------------------------------------------------------------------------
// Chain / proj smem layout: merged hi||lo rows, pitch 528.
// ---------------------------------------------------------------------------
#define PW 528
#define XBYTES (64 * PW)
#define WBYTES (128 * PW)
#define LIN_SMEM (XBYTES + WBYTES)    // 101376 -> 2 CTAs/SM

__device__ __forceinline__ void ldgsplit_X64(const float* __restrict__ g,
                                             char* X, int tid) {
    int row = tid >> 2;
    int c0  = (tid & 3) * 32;
    const float* gp = g + (size_t)row * DD + c0;
    char* ph = X + row * PW + c0 * 2;
    char* pl = ph + 256;
    #pragma unroll
    for (int i = 0; i < 8; i++) {
        float4 v = *(const float4*)(gp + i * 4);
        uint32_t h0, l0, h1, l1;
        split2(v.x, v.y, h0, l0);
        split2(v.z, v.w, h1, l1);
        *(uint2*)(ph + i * 8) = make_uint2(h0, h1);
        *(uint2*)(pl + i * 8) = make_uint2(l0, l1);
    }
}

__device__ __forceinline__ void cpw(const uint16_t* __restrict__ WHg,
                                    const uint16_t* __restrict__ WLg,
                                    int mat, uint32_t wbase, int tid) {
    int n = tid >> 1, half = tid & 1;
    const char* src = (const char*)((half ? WLg : WHg) + (size_t)mat * DD * DD + n * DD);
    uint32_t dst = wbase + (uint32_t)(n * PW + half * 256);
    #pragma unroll
    for (int q = 0; q < 16; q++)
        CP16(dst + q * 16, src + q * 16);
}

// m2^T tiled store: value pair (h,l) for (b, n, k..k+1)
__device__ __forceinline__ void store_m2(uint8_t* __restrict__ M2, int b, int n,
                                         int k, uint32_t h, uint32_t l) {
    int c  = k >> 5;
    int u2 = (k >> 3) & 3;
    uint8_t* p = M2 + (((size_t)(b * 32 + c)) * 128 + n) * 128;
    int w = (k & 7) * 2;
    *(uint32_t*)(p + ((u2 ^ (n & 7)) * 16) + w)       = h;
    *(uint32_t*)(p + (((4 + u2) ^ (n & 7)) * 16) + w) = l;
}

// ---------------------------------------------------------------------------
// Fused chain kernel (64-row tiles, 512 CTAs, 2 CTA/SM)
// ---------------------------------------------------------------------------
template<bool FIRST>
__global__ void __launch_bounds__(256, 2) chain_kernel(
    const float* __restrict__ X,
    const uint16_t* __restrict__ WHg, const uint16_t* __restrict__ WLg,
    int emb_mat, int w1_mat, int w2_mat,
    const float* __restrict__ bias1,
    float* __restrict__ Mout,
    uint8_t* __restrict__ M2)
{
    extern __shared__ char smem[];
    const uint32_t sX = smem_u32(smem);
    const uint32_t sW = sX + XBYTES;
    char* Xp = smem;

    const int tid = threadIdx.x, lane = tid & 31, wid = tid >> 5;
    const int wm = wid & 1, wn = wid >> 1;
    const int wm2 = wid & 3, wn2 = wid >> 2;
    const int row0 = blockIdx.x * 64;
    const int bb = row0 >> 10;
    const int rb = row0 & 1023;

    float d[2][4][4];

    if (FIRST) {
        cpw(WHg, WLg, emb_mat, sW, tid);
        CP_COMMIT();
        ldgsplit_X64(X + (size_t)row0 * DD, Xp, tid);
        CPWAIT(0);
        __syncthreads();

        #pragma unroll
        for (int i = 0; i < 2; i++)
            #pragma unroll
            for (int j = 0; j < 4; j++)
                #pragma unroll
                for (int q = 0; q < 4; q++) d[i][j][q] = 0.f;
        mma_blk<PW, 256, 8, 2>(sX, sW, wm, wn, lane, d);
        __syncthreads();

        cpw(WHg, WLg, w1_mat, sW, tid);
        CP_COMMIT();

        float* stg = (float*)Xp;
        #pragma unroll
        for (int mi = 0; mi < 2; mi++) {
            int R = wm * 32 + mi * 16 + (lane >> 2);
            #pragma unroll
            for (int ni = 0; ni < 4; ni++) {
                int C = wn * 32 + ni * 8 + (lane & 3) * 2;
                stg[R * 132 + C]           = d[mi][ni][0];
                stg[R * 132 + C + 1]       = d[mi][ni][1];
                stg[(R + 8) * 132 + C]     = d[mi][ni][2];
                stg[(R + 8) * 132 + C + 1] = d[mi][ni][3];
            }
        }
        __syncthreads();

        #pragma unroll
        for (int i = 0; i < 8; i++) {
            int rr = wid * 8 + i;
            float4 v = *(float4*)&stg[rr * 132 + lane * 4];
            float ss = v.x * v.x + v.y * v.y + v.z * v.z + v.w * v.w;
            #pragma unroll
            for (int o = 16; o > 0; o >>= 1)
                ss += __shfl_xor_sync(0xffffffffu, ss, o);
            float s = hyp_scale(sqrtf(ss));
            v.x *= s; v.y *= s; v.z *= s; v.w *= s;
            __syncwarp();
            uint32_t h0, l0, h1, l1;
            split2(v.x, v.y, h0, l0);
            split2(v.z, v.w, h1, l1);
            *(uint2*)(Xp + rr * PW + lane * 8)       = make_uint2(h0, h1);
            *(uint2*)(Xp + rr * PW + 256 + lane * 8) = make_uint2(l0, l1);
        }
        CPWAIT(0);
        __syncthreads();
    } else {
        cpw(WHg, WLg, w1_mat, sW, tid);
        CP_COMMIT();
        ldgsplit_X64(X + (size_t)row0 * DD, Xp, tid);
        CPWAIT(0);
        __syncthreads();
    }

    // GEMM1: m = t @ W1 + b1
    #pragma unroll
    for (int i = 0; i < 2; i++)
        #pragma unroll
        for (int j = 0; j < 4; j++)
            #pragma unroll
            for (int q = 0; q < 4; q++) d[i][j][q] = 0.f;
    mma_blk<PW, 256, 8, 2>(sX, sW, wm, wn, lane, d);
    __syncthreads();

    cpw(WHg, WLg, w2_mat, sW, tid);
    CP_COMMIT();

    #pragma unroll
    for (int mi = 0; mi < 2; mi++) {
        int R = wm * 32 + mi * 16 + (lane >> 2);
        #pragma unroll
        for (int ni = 0; ni < 4; ni++) {
            int C = wn * 32 + ni * 8 + (lane & 3) * 2;
            float b0 = bias1[C], b1 = bias1[C + 1];
            float v0 = d[mi][ni][0] + b0, v1 = d[mi][ni][1] + b1;
            float v2 = d[mi][ni][2] + b0, v3 = d[mi][ni][3] + b1;
            *(float2*)&Mout[(size_t)(row0 + R) * DD + C]     = make_float2(v0, v1);
            *(float2*)&Mout[(size_t)(row0 + R + 8) * DD + C] = make_float2(v2, v3);
            uint32_t h, l;
            split2(v0, v1, h, l);
            *(uint32_t*)(Xp + R * PW + C * 2)       = h;
            *(uint32_t*)(Xp + R * PW + 256 + C * 2) = l;
            split2(v2, v3, h, l);
            *(uint32_t*)(Xp + (R + 8) * PW + C * 2)       = h;
            *(uint32_t*)(Xp + (R + 8) * PW + 256 + C * 2) = l;
        }
    }
    CPWAIT(0);
    __syncthreads();

    // GEMM2: m2T[n][r] = sum_k W2n[n][k] * m[r][k]
    float e[2][4][4];
    #pragma unroll
    for (int i = 0; i < 2; i++)
        #pragma unroll
        for (int j = 0; j < 4; j++)
            #pragma unroll
            for (int q = 0; q < 4; q++) e[i][j][q] = 0.f;
    mma_blk<PW, 256, 8, 2>(sW, sX, wm2, wn2, lane, e);

    #pragma unroll
    for (int mi = 0; mi < 2; mi++) {
        int Rn = wm2 * 32 + mi * 16 + (lane >> 2);
        #pragma unroll
        for (int ni = 0; ni < 4; ni++) {
            int Cr = wn2 * 32 + ni * 8 + (lane & 3) * 2;
            uint32_t h, l;
            split2(e[mi][ni][0], e[mi][ni][1], h, l);
            store_m2(M2, bb, Rn, rb + Cr, h, l);
            split2(e[mi][ni][2], e[mi][ni][3], h, l);
            store_m2(M2, bb, Rn + 8, rb + Cr, h, l);
        }
    }
}

// ---------------------------------------------------------------------------
// Final projection: out = (t @ WprojT + bp) * mask
// ---------------------------------------------------------------------------
__global__ void __launch_bounds__(256, 2) proj_kernel(
    const float* __restrict__ X,
    const uint16_t* __restrict__ WHg, const uint16_t* __restrict__ WLg,
    const float* __restrict__ bp, const float* __restrict__ mask,
    float* __restrict__ out)
{
    extern __shared__ char smem[];
    const uint32_t sX = smem_u32(smem);
    const uint32_t sW = sX + XBYTES;
    const int tid = threadIdx.x, lane = tid & 31, wid = tid >> 5;
    const int wm = wid & 1, wn = wid >> 1;
    const int row0 = blockIdx.x * 64;

    cpw(WHg, WLg, 5, sW, tid);
    CP_COMMIT();
    ldgsplit_X64(X + (size_t)row0 * DD, smem, tid);
    CPWAIT(0);
    __syncthreads();

    float d[2][4][4];
    #pragma unroll
    for (int i = 0; i < 2; i++)
        #pragma unroll
        for (int j = 0; j < 4; j++)
            #pragma unroll
            for (int q = 0; q < 4; q++) d[i][j][q] = 0.f;
    mma_blk<PW, 256, 8, 2>(sX, sW, wm, wn, lane, d);

    #pragma unroll
    for (int mi = 0; mi < 2; mi++) {
        int R = wm * 32 + mi * 16 + (lane >> 2);
        float mk0 = mask[row0 + R];
        float mk1 = mask[row0 + R + 8];
        #pragma unroll
        for (int ni = 0; ni < 4; ni++) {
            int C = wn * 32 + ni * 8 + (lane & 3) * 2;
            float b0 = bp[C], b1 = bp[C + 1];
            *(float2*)&out[(size_t)(row0 + R) * DD + C] =
                make_float2((d[mi][ni][0] + b0) * mk0, (d[mi][ni][1] + b1) * mk0);
            *(float2*)&out[(size_t)(row0 + R + 8) * DD + C] =
                make_float2((d[mi][ni][2] + b0) * mk1, (d[mi][ni][3] + b1) * mk1);
        }
    }
}

// ---------------------------------------------------------------------------
// Big GEMM: BM=256, 512 threads, 1 CTA/SM, cp.async.bulk, 6-stage
// full/empty mbarrier pipeline (no per-chunk __syncthreads — warps free-run).
//   full[s]  (count 1):  completed by bulk complete_tx
//   empty[s] (count 16): each warp's lane 0 arrives after consuming
//   producer = warp 0 lane 0, issue depth 4 (slack 2 chunks vs slowest warp)
// ---------------------------------------------------------------------------
#define BMA     256
#define STG     32768
#define NSTG    6
#define MBAR_OFF (NSTG * STG)          // 196608
#define AGG_SMEM (MBAR_OFF + 128)      // 196736 (epi 256x132 f32 = 135168 fits)

__global__ void __launch_bounds__(512, 1) agg_mma(
    const uint8_t* __restrict__ AT, const uint8_t* __restrict__ BT,
    const float* __restrict__ M, const float* __restrict__ bagg,
    float* __restrict__ T)
{
    extern __shared__ char smem[];
    const uint32_t sb = smem_u32(smem);
    const uint32_t mb_full  = sb + MBAR_OFF;            // 6 x 8B
    const uint32_t mb_empty = sb + MBAR_OFF + 48;       // 6 x 8B
    const int tid  = threadIdx.x;
    const int lane = tid & 31;
    const int wid  = tid >> 5;          // 0..15
    const int b    = blockIdx.y;
    const int mt   = blockIdx.x;
    const int row0 = mt * BMA;
    const int wm   = wid & 3;
    const int wn   = wid >> 2;

    const uint8_t* gA = AT + ((size_t)(b * 4 + mt) * 32) * 16384;
    const uint8_t* gB = BT + ((size_t)b * 32) * 16384;

    if (tid == 0) {
        #pragma unroll
        for (int s = 0; s < NSTG; s++) {
            MBAR_INIT(mb_full + s * 8, 1);
            MBAR_INIT(mb_empty + s * 8, 16);
        }
        FENCE_ASYNC();
    }
    __syncthreads();

    auto issue = [&](int c) {
        int s = c % NSTG;
        MBAR_EXPECT_TX(mb_full + s * 8, 32768u);
        BULK(sb + (uint32_t)s * STG,         gA + (size_t)c * 16384, 16384u, mb_full + s * 8);
        BULK(sb + (uint32_t)s * STG + 16384, gB + (size_t)c * 16384, 16384u, mb_full + s * 8);
    };

    if (tid == 0) { issue(0); issue(1); issue(2); issue(3); }

    float d[4][4][4];
    #pragma unroll
    for (int i = 0; i < 4; i++)
        #pragma unroll
        for (int j = 0; j < 4; j++)
            #pragma unroll
            for (int q = 0; q < 4; q++) d[i][j][q] = 0.f;

    const int lg = lane >> 3, lr = lane & 7;
    const int rbase = wm * 64 + (lg & 1) * 8 + lr;
    const uint32_t swzA = (uint32_t)((rbase >> 1) & 3);
    const int nbase = wn * 32 + lr;
    const uint32_t swzB = (uint32_t)(nbase & 7);
    const uint32_t u3base = (uint32_t)((lg >> 1) * 4 + (lg & 1));

    int phf[NSTG] = {0, 0, 0, 0, 0, 0};   // consumer full phases (per warp)
    int phe[NSTG] = {0, 0, 0, 0, 0, 0};   // producer empty phases (warp0 lane0)

    for (int c = 0; c < 32; c++) {
        int s = c % NSTG;

        // producer: refill stage (c+4)%6 — requires all warps past chunk c-2
        if (tid == 0) {
            int cn = c + 4;
            if (cn < 32) {
                int sn = cn % NSTG;
                if (cn >= NSTG) { MBAR_WAIT(mb_empty + sn * 8, phe[sn]); phe[sn] ^= 1; }
                issue(cn);
            }
        }

        MBAR_WAIT(mb_full + s * 8, phf[s]);
        phf[s] ^= 1;

        uint32_t aBase = sb + (uint32_t)s * STG;
        uint32_t bBase = aBase + 16384;
        #pragma unroll
        for (int ks = 0; ks < 2; ks++) {
            uint32_t bh[4][2], bl[4][2];
            const uint32_t ub = ((u3base + ks * 2) ^ swzB) * 16;
            #pragma unroll
            for (int ni = 0; ni < 4; ni++)
                LDSM4(bh[ni][0], bh[ni][1], bl[ni][0], bl[ni][1],
                      bBase + (uint32_t)(nbase + ni * 8) * 128 + ub);
            const uint32_t ua = (((uint32_t)(ks * 2 + (lg >> 1))) ^ swzA) * 16;
            #pragma unroll
            for (int mi = 0; mi < 4; mi++) {
                uint32_t ah[4];
                LDSM4(ah[0], ah[1], ah[2], ah[3],
                      aBase + (uint32_t)(rbase + mi * 16) * 64 + ua);
                #pragma unroll
                for (int ni = 0; ni < 4; ni++) {
                    mma_bf16(d[mi][ni], ah, bh[ni][0], bh[ni][1]);
                    mma_bf16(d[mi][ni], ah, bl[ni][0], bl[ni][1]);
                }
            }
        }

        // warp done with this stage
        if (lane == 0) MBAR_ARRIVE(mb_empty + s * 8);
    }
    __syncthreads();                    // all warps done; safe to reuse smem

    // stage D to smem (f32, pitch 132, 256 rows)
    float* stg = (float*)smem;
    #pragma unroll
    for (int mi = 0; mi < 4; mi++) {
        int R = wm * 64 + mi * 16 + (lane >> 2);
        #pragma unroll
        for (int ni = 0; ni < 4; ni++) {
            int C = wn * 32 + ni * 8 + (lane & 3) * 2;
            *(float2*)&stg[R * 132 + C]       = make_float2(d[mi][ni][0], d[mi][ni][1]);
            *(float2*)&stg[(R + 8) * 132 + C] = make_float2(d[mi][ni][2], d[mi][ni][3]);
        }
    }
    __syncthreads();

    const float* Mb = M + ((size_t)b * NN + row0) * DD;
    float*       Tb = T + ((size_t)b * NN + row0) * DD;
    float4 bg = *(const float4*)&bagg[lane * 4];
    #pragma unroll
    for (int i = 0; i < 16; i++) {
        int rr = wid * 16 + i;
        float4 raw = *(const float4*)&stg[rr * 132 + lane * 4];
        float4 mm  = *(const float4*)&Mb[(size_t)rr * DD + lane * 4];
        float v0 = fmaxf(raw.x + mm.x + bg.x, 0.f);
        float v1 = fmaxf(raw.y + mm.y + bg.y, 0.f);
        float v2 = fmaxf(raw.z + mm.z + bg.z, 0.f);
        float v3 = fmaxf(raw.w + mm.w + bg.w, 0.f);
        float ss = v0*v0 + v1*v1 + v2*v2 + v3*v3;
        #pragma unroll
        for (int o = 16; o > 0; o >>= 1)
            ss += __shfl_xor_sync(0xffffffffu, ss, o);
        float s = hyp_scale(sqrtf(ss));
        *(float4*)&Tb[(size_t)rr * DD + lane * 4] =
            make_float4(v0 * s, v1 * s, v2 * s, v3 * s);
    }
}

// ---------------------------------------------------------------------------
// Host launch
// ---------------------------------------------------------------------------
extern "C" void kernel_launch(void* const* d_in, const int* in_sizes, int n_in,
                              void* d_out, int out_size)
{
    const float* nf    = (const float*)d_in[0];
    const float* adj   = (const float*)d_in[1];
    const float* mask  = (const float*)d_in[2];
    const float* Wemb  = (const float*)d_in[3];
    const float* Wmsg  = (const float*)d_in[4];
    const float* bmsg  = (const float*)d_in[5];
    const float* Wagg  = (const float*)d_in[6];
    const float* bagg  = (const float*)d_in[7];
    const float* Wproj = (const float*)d_in[8];
    const float* bproj = (const float*)d_in[9];
    float* out = (float*)d_out;

    float *t, *m;
    uint8_t *aht, *m2t;
    uint16_t *wh, *wl;
    cudaGetSymbolAddress((void**)&t,   g_t);
    cudaGetSymbolAddress((void**)&m,   g_m);
    cudaGetSymbolAddress((void**)&aht, g_aht);
    cudaGetSymbolAddress((void**)&m2t, g_m2t);
    cudaGetSymbolAddress((void**)&wh,  g_wh);
    cudaGetSymbolAddress((void**)&wl,  g_wl);

    cudaFuncSetAttribute(agg_mma, cudaFuncAttributeMaxDynamicSharedMemorySize, AGG_SMEM);
    cudaFuncSetAttribute(chain_kernel<true>,  cudaFuncAttributeMaxDynamicSharedMemorySize, LIN_SMEM);
    cudaFuncSetAttribute(chain_kernel<false>, cudaFuncAttributeMaxDynamicSharedMemorySize, LIN_SMEM);
    cudaFuncSetAttribute(proj_kernel, cudaFuncAttributeMaxDynamicSharedMemorySize, LIN_SMEM);

    dim3 glin(ROWS / 64);          // 512
    dim3 gbig(NN / BMA, BATCH);    // 4 x 32 = 128

    split_adj<<<(BATCH * NN * (NN / 8)) / 256, 256>>>(adj, aht);
    split_weights<<<6, 256>>>(Wemb, Wmsg, Wagg, Wproj, wh, wl);

    // layer 0: embed + hyp + msg + m2 fused
    chain_kernel<true><<<glin, 256, LIN_SMEM>>>(nf, wh, wl, 0, 1, 2,
                                                bmsg, m, m2t);
    agg_mma<<<gbig, 512, AGG_SMEM>>>(aht, m2t, m, bagg, t);

    // layer 1: msg + m2 fused
    chain_kernel<false><<<glin, 256, LIN_SMEM>>>(t, wh, wl, 0, 3, 4,
                                                 bmsg + DD, m, m2t);
    agg_mma<<<gbig, 512, AGG_SMEM>>>(aht, m2t, m, bagg + DD, t);

    // out = (t @ WprojT + bproj) * mask
    proj_kernel<<<glin, 256, LIN_SMEM>>>(t, wh, wl, bproj, mask, out);
}

// round 12
// speedup vs baseline: 2.4990x; 1.0486x over previous
#include <cuda_runtime.h>
#include <math.h>
#include <stdint.h>

// Problem constants
#define BATCH 32
#define NN    1024
#define DD    128
#define ROWS  (BATCH * NN)   // 32768

// Scratch (device globals — no allocation allowed)
__device__ float g_t[ROWS * DD];
__device__ float g_m[ROWS * DD];
// A-hi, chunk-tiled: [b][mt(4)][c(32)] -> 16KB block: r(256) x 64B, unit swizzle u^((r>>1)&3)
__device__ __align__(16) uint8_t g_aht[(size_t)BATCH * 4 * 32 * 16384];   // 64MB
// m2^T, chunk-tiled: [b][c(32)] -> 16KB block: n(128) x 128B (hi u0-3 || lo u4-7), swizzle unit3^(n&7)
__device__ __align__(16) uint8_t g_m2t[(size_t)BATCH * 32 * 16384];       // 16MB
__device__ __align__(16) uint16_t g_wh[6 * DD * DD];               // weights hi [n][k]
__device__ __align__(16) uint16_t g_wl[6 * DD * DD];               // weights lo

// ---------------------------------------------------------------------------
// Helpers
// ---------------------------------------------------------------------------
__device__ __forceinline__ uint32_t smem_u32(const void* p) {
    uint32_t a;
    asm("{ .reg .u64 t; cvta.to.shared.u64 t, %1; cvt.u32.u64 %0, t; }" : "=r"(a) : "l"(p));
    return a;
}
__device__ __forceinline__ uint32_t pack_bf16x2(float v0, float v1) {
    uint32_t r;
    asm("cvt.rn.bf16x2.f32 %0, %1, %2;" : "=r"(r) : "f"(v1), "f"(v0));
    return r;
}
__device__ __forceinline__ void split2(float v0, float v1, uint32_t& h, uint32_t& l) {
    h = pack_bf16x2(v0, v1);
    float r0 = v0 - __uint_as_float(h << 16);
    float r1 = v1 - __uint_as_float(h & 0xffff0000u);
    l = pack_bf16x2(r0, r1);
}
#define CP16(dst, src) \
    asm volatile("cp.async.cg.shared.global [%0], [%1], 16;" :: "r"(dst), "l"(src) : "memory")
#define CP_COMMIT() asm volatile("cp.async.commit_group;" ::: "memory")
#define CPWAIT(n)   asm volatile("cp.async.wait_group %0;" :: "n"(n) : "memory")

#define LDSM4(r0, r1, r2, r3, addr) \
    asm volatile("ldmatrix.sync.aligned.m8n8.x4.shared.b16 {%0,%1,%2,%3}, [%4];" \
        : "=r"(r0), "=r"(r1), "=r"(r2), "=r"(r3) : "r"(addr))

// 1D bulk async copy gmem->smem with mbarrier completion (sm_90 base feature)
#define BULK(dst, src, sz, mb) \
    asm volatile("cp.async.bulk.shared::cta.global.mbarrier::complete_tx::bytes [%0], [%1], %2, [%3];" \
        :: "r"(dst), "l"(src), "r"(sz), "r"(mb) : "memory")

#define MBAR_INIT(a, c) asm volatile("mbarrier.init.shared.b64 [%0], %1;" :: "r"(a), "r"(c) : "memory")
#define MBAR_EXPECT_TX(a, b) asm volatile("mbarrier.arrive.expect_tx.shared.b64 _, [%0], %1;" :: "r"(a), "r"(b) : "memory")
#define MBAR_ARRIVE(a) asm volatile("mbarrier.arrive.shared.b64 _, [%0];" :: "r"(a) : "memory")
#define FENCE_ASYNC() asm volatile("fence.proxy.async.shared::cta;" ::: "memory")

#define MBAR_WAIT(a, ph) do { \
    uint32_t _m = (a), _p = (uint32_t)(ph), _d; \
    asm volatile("{ .reg .pred p; mbarrier.try_wait.parity.acquire.cta.shared::cta.b64 p, [%1], %2; selp.b32 %0, 1, 0, p; }" \
        : "=r"(_d) : "r"(_m), "r"(_p) : "memory"); \
    if (!_d) { \
        asm volatile("{ .reg .pred P1; WL_%=: mbarrier.try_wait.parity.acquire.cta.shared::cta.b64 P1, [%0], %1, 0x989680; @P1 bra.uni WD_%=; bra.uni WL_%=; WD_%=: }" \
            :: "r"(_m), "r"(_p) : "memory"); \
    } } while (0)

__device__ __forceinline__ void mma_bf16(float d[4], const uint32_t a[4],
                                         uint32_t b0, uint32_t b1) {
    asm volatile(
        "mma.sync.aligned.m16n8k16.row.col.f32.bf16.bf16.f32 "
        "{%0,%1,%2,%3}, {%4,%5,%6,%7}, {%8,%9}, {%0,%1,%2,%3};"
        : "+f"(d[0]), "+f"(d[1]), "+f"(d[2]), "+f"(d[3])
        : "r"(a[0]), "r"(a[1]), "r"(a[2]), "r"(a[3]), "r"(b0), "r"(b1));
}

// Composite per-row scale: logmap0(proj(expmap0(h))) = s(||h||) * h
__device__ __forceinline__ float hyp_scale(float n) {
    const float EPS  = 1e-7f;
    const float MAXN = 1.0f - 1e-5f;
    float n1 = fmaxf(n, EPS);
    float r  = tanhf(n1) / n1;
    float xn = r * n;
    float n2 = fmaxf(xn, EPS);
    float s2 = (n2 > MAXN) ? (MAXN / n2) : 1.0f;
    float x2 = s2 * xn;
    float n3 = fmaxf(x2, EPS);
    float z  = fminf(n3, 1.0f - EPS);
    float lg = atanhf(z) / n3;
    return r * s2 * lg;
}

// ---------------------------------------------------------------------------
// 3-product warp-tile MMA over merged hi/lo smem tiles.
// ---------------------------------------------------------------------------
template<int PITCH, int LOOFF, int NKS, int MI>
__device__ __forceinline__ void mma_blk(uint32_t Ab, uint32_t Bb,
                                        int wma, int wnb, int lane,
                                        float (&d)[MI][4][4]) {
    const int lg = lane >> 3;
    const int lr = lane & 7;
    const uint32_t aBase = Ab + (uint32_t)((wma * (MI * 16) + (lg & 1) * 8 + lr) * PITCH
                                           + (lg >> 1) * 16);
    const uint32_t bBase = Bb + (uint32_t)((wnb * 32 + lr) * PITCH + (lg & 1) * 16
                                           + ((lg >> 1) ? LOOFF : 0));
    #pragma unroll
    for (int ks = 0; ks < NKS; ks++) {
        const uint32_t kb = (uint32_t)ks * 32;
        uint32_t bh[4][2], bl[4][2];
        #pragma unroll
        for (int ni = 0; ni < 4; ni++)
            LDSM4(bh[ni][0], bh[ni][1], bl[ni][0], bl[ni][1],
                  bBase + ni * 8 * PITCH + kb);
        #pragma unroll
        for (int mi = 0; mi < MI; mi++) {
            uint32_t ah[4], al[4];
            LDSM4(ah[0], ah[1], ah[2], ah[3], aBase + mi * 16 * PITCH + kb);
            LDSM4(al[0], al[1], al[2], al[3], aBase + mi * 16 * PITCH + kb + LOOFF);
            #pragma unroll
            for (int ni = 0; ni < 4; ni++) {
                mma_bf16(d[mi][ni], ah, bh[ni][0], bh[ni][1]);
                mma_bf16(d[mi][ni], ah, bl[ni][0], bl[ni][1]);
                mma_bf16(d[mi][ni], al, bh[ni][0], bh[ni][1]);
            }
        }
    }
}

// ---------------------------------------------------------------------------
// One-time adjacency split -> chunk-tiled, swizzled bf16-hi blocks.
// ---------------------------------------------------------------------------
__global__ void __launch_bounds__(256) split_adj(const float* __restrict__ a,
                                                 uint8_t* __restrict__ out) {
    int t = blockIdx.x * 256 + threadIdx.x;     // 0 .. 4M-1
    int u32i = t & 127;           // k/8
    int rowg = (t >> 7) & 1023;
    int b    = t >> 17;
    const float* src = a + ((size_t)b * NN + rowg) * NN + u32i * 8;
    float4 v0 = *(const float4*)src;
    float4 v1 = *(const float4*)(src + 4);
    uint4 w = make_uint4(pack_bf16x2(v0.x, v0.y), pack_bf16x2(v0.z, v0.w),
                         pack_bf16x2(v1.x, v1.y), pack_bf16x2(v1.z, v1.w));
    int mt = rowg >> 8, r = rowg & 255, c = u32i >> 2, u = u32i & 3;
    size_t dst = (((((size_t)(b * 4 + mt)) * 32 + c) * 256 + r) * 4
                  + (u ^ ((r >> 1) & 3))) * 16;
    *(uint4*)(out + dst) = w;
}

// ---------------------------------------------------------------------------
// One-time weight split into [n][k] bf16 hi/lo.
// ---------------------------------------------------------------------------
__global__ void __launch_bounds__(256) split_weights(
    const float* __restrict__ Wemb, const float* __restrict__ Wmsg,
    const float* __restrict__ Wagg, const float* __restrict__ Wproj,
    uint16_t* __restrict__ WH, uint16_t* __restrict__ WL)
{
    int mat = blockIdx.x;
    const float* src;
    bool trans;
    switch (mat) {
        case 0:  src = Wemb;            trans = false; break;
        case 1:  src = Wmsg;            trans = true;  break;
        case 2:  src = Wagg;            trans = true;  break;
        case 3:  src = Wmsg + DD * DD;  trans = true;  break;
        case 4:  src = Wagg + DD * DD;  trans = true;  break;
        default: src = Wproj;           trans = false; break;
    }
    for (int idx = threadIdx.x; idx < DD * DD; idx += 256) {
        int n = idx >> 7, k = idx & 127;
        float v = trans ? src[k * DD + n] : src[idx];
        uint32_t p = pack_bf16x2(v, 0.f);
        uint16_t hh = (uint16_t)(p & 0xffffu);
        float r = v - __uint_as_float((uint32_t)hh << 16);
        uint32_t pl = pack_bf16x2(r, 0.f);
        WH[mat * DD * DD + idx] = hh;
        WL[mat * DD * DD + idx] = (uint16_t)(pl & 0xffffu);
    }
}

// ---------------------------------------------------------------------------
// Chain smem layout: merged hi||lo rows, pitch 528.
// ---------------------------------------------------------------------------
#define PW 528
#define XBYTES (64 * PW)
#define WBYTES (128 * PW)
#define LIN_SMEM (XBYTES + WBYTES)    // 101376 -> 2 CTAs/SM

__device__ __forceinline__ void ldgsplit_X64(const float* __restrict__ g,
                                             char* X, int tid) {
    int row = tid >> 2;
    int c0  = (tid & 3) * 32;
    const float* gp = g + (size_t)row * DD + c0;
    char* ph = X + row * PW + c0 * 2;
    char* pl = ph + 256;
    #pragma unroll
    for (int i = 0; i < 8; i++) {
        float4 v = *(const float4*)(gp + i * 4);
        uint32_t h0, l0, h1, l1;
        split2(v.x, v.y, h0, l0);
        split2(v.z, v.w, h1, l1);
        *(uint2*)(ph + i * 8) = make_uint2(h0, h1);
        *(uint2*)(pl + i * 8) = make_uint2(l0, l1);
    }
}

// cp.async a pre-split weight matrix into a [n][k] tile (256 participating threads)
__device__ __forceinline__ void cpw(const uint16_t* __restrict__ WHg,
                                    const uint16_t* __restrict__ WLg,
                                    int mat, uint32_t wbase, int tid) {
    int n = tid >> 1, half = tid & 1;
    const char* src = (const char*)((half ? WLg : WHg) + (size_t)mat * DD * DD + n * DD);
    uint32_t dst = wbase + (uint32_t)(n * PW + half * 256);
    #pragma unroll
    for (int q = 0; q < 16; q++)
        CP16(dst + q * 16, src + q * 16);
}

// m2^T tiled store: value pair (h,l) for (b, n, k..k+1)
__device__ __forceinline__ void store_m2(uint8_t* __restrict__ M2, int b, int n,
                                         int k, uint32_t h, uint32_t l) {
    int c  = k >> 5;
    int u2 = (k >> 3) & 3;
    uint8_t* p = M2 + (((size_t)(b * 32 + c)) * 128 + n) * 128;
    int w = (k & 7) * 2;
    *(uint32_t*)(p + ((u2 ^ (n & 7)) * 16) + w)       = h;
    *(uint32_t*)(p + (((4 + u2) ^ (n & 7)) * 16) + w) = l;
}

// ---------------------------------------------------------------------------
// Fused chain kernel (64-row tiles, 512 CTAs, 2 CTA/SM)
// ---------------------------------------------------------------------------
template<bool FIRST>
__global__ void __launch_bounds__(256, 2) chain_kernel(
    const float* __restrict__ X,
    const uint16_t* __restrict__ WHg, const uint16_t* __restrict__ WLg,
    int emb_mat, int w1_mat, int w2_mat,
    const float* __restrict__ bias1,
    float* __restrict__ Mout,
    uint8_t* __restrict__ M2)
{
    extern __shared__ char smem[];
    const uint32_t sX = smem_u32(smem);
    const uint32_t sW = sX + XBYTES;
    char* Xp = smem;

    const int tid = threadIdx.x, lane = tid & 31, wid = tid >> 5;
    const int wm = wid & 1, wn = wid >> 1;
    const int wm2 = wid & 3, wn2 = wid >> 2;
    const int row0 = blockIdx.x * 64;
    const int bb = row0 >> 10;
    const int rb = row0 & 1023;

    float d[2][4][4];

    if (FIRST) {
        cpw(WHg, WLg, emb_mat, sW, tid);
        CP_COMMIT();
        ldgsplit_X64(X + (size_t)row0 * DD, Xp, tid);
        CPWAIT(0);
        __syncthreads();

        #pragma unroll
        for (int i = 0; i < 2; i++)
            #pragma unroll
            for (int j = 0; j < 4; j++)
                #pragma unroll
                for (int q = 0; q < 4; q++) d[i][j][q] = 0.f;
        mma_blk<PW, 256, 8, 2>(sX, sW, wm, wn, lane, d);
        __syncthreads();

        cpw(WHg, WLg, w1_mat, sW, tid);
        CP_COMMIT();

        float* stg = (float*)Xp;
        #pragma unroll
        for (int mi = 0; mi < 2; mi++) {
            int R = wm * 32 + mi * 16 + (lane >> 2);
            #pragma unroll
            for (int ni = 0; ni < 4; ni++) {
                int C = wn * 32 + ni * 8 + (lane & 3) * 2;
                stg[R * 132 + C]           = d[mi][ni][0];
                stg[R * 132 + C + 1]       = d[mi][ni][1];
                stg[(R + 8) * 132 + C]     = d[mi][ni][2];
                stg[(R + 8) * 132 + C + 1] = d[mi][ni][3];
            }
        }
        __syncthreads();

        #pragma unroll
        for (int i = 0; i < 8; i++) {
            int rr = wid * 8 + i;
            float4 v = *(float4*)&stg[rr * 132 + lane * 4];
            float ss = v.x * v.x + v.y * v.y + v.z * v.z + v.w * v.w;
            #pragma unroll
            for (int o = 16; o > 0; o >>= 1)
                ss += __shfl_xor_sync(0xffffffffu, ss, o);
            float s = hyp_scale(sqrtf(ss));
            v.x *= s; v.y *= s; v.z *= s; v.w *= s;
            __syncwarp();
            uint32_t h0, l0, h1, l1;
            split2(v.x, v.y, h0, l0);
            split2(v.z, v.w, h1, l1);
            *(uint2*)(Xp + rr * PW + lane * 8)       = make_uint2(h0, h1);
            *(uint2*)(Xp + rr * PW + 256 + lane * 8) = make_uint2(l0, l1);
        }
        CPWAIT(0);
        __syncthreads();
    } else {
        cpw(WHg, WLg, w1_mat, sW, tid);
        CP_COMMIT();
        ldgsplit_X64(X + (size_t)row0 * DD, Xp, tid);
        CPWAIT(0);
        __syncthreads();
    }

    // GEMM1: m = t @ W1 + b1
    #pragma unroll
    for (int i = 0; i < 2; i++)
        #pragma unroll
        for (int j = 0; j < 4; j++)
            #pragma unroll
            for (int q = 0; q < 4; q++) d[i][j][q] = 0.f;
    mma_blk<PW, 256, 8, 2>(sX, sW, wm, wn, lane, d);
    __syncthreads();

    cpw(WHg, WLg, w2_mat, sW, tid);
    CP_COMMIT();

    #pragma unroll
    for (int mi = 0; mi < 2; mi++) {
        int R = wm * 32 + mi * 16 + (lane >> 2);
        #pragma unroll
        for (int ni = 0; ni < 4; ni++) {
            int C = wn * 32 + ni * 8 + (lane & 3) * 2;
            float b0 = bias1[C], b1 = bias1[C + 1];
            float v0 = d[mi][ni][0] + b0, v1 = d[mi][ni][1] + b1;
            float v2 = d[mi][ni][2] + b0, v3 = d[mi][ni][3] + b1;
            *(float2*)&Mout[(size_t)(row0 + R) * DD + C]     = make_float2(v0, v1);
            *(float2*)&Mout[(size_t)(row0 + R + 8) * DD + C] = make_float2(v2, v3);
            uint32_t h, l;
            split2(v0, v1, h, l);
            *(uint32_t*)(Xp + R * PW + C * 2)       = h;
            *(uint32_t*)(Xp + R * PW + 256 + C * 2) = l;
            split2(v2, v3, h, l);
            *(uint32_t*)(Xp + (R + 8) * PW + C * 2)       = h;
            *(uint32_t*)(Xp + (R + 8) * PW + 256 + C * 2) = l;
        }
    }
    CPWAIT(0);
    __syncthreads();

    // GEMM2: m2T[n][r] = sum_k W2n[n][k] * m[r][k]
    float e[2][4][4];
    #pragma unroll
    for (int i = 0; i < 2; i++)
        #pragma unroll
        for (int j = 0; j < 4; j++)
            #pragma unroll
            for (int q = 0; q < 4; q++) e[i][j][q] = 0.f;
    mma_blk<PW, 256, 8, 2>(sW, sX, wm2, wn2, lane, e);

    #pragma unroll
    for (int mi = 0; mi < 2; mi++) {
        int Rn = wm2 * 32 + mi * 16 + (lane >> 2);
        #pragma unroll
        for (int ni = 0; ni < 4; ni++) {
            int Cr = wn2 * 32 + ni * 8 + (lane & 3) * 2;
            uint32_t h, l;
            split2(e[mi][ni][0], e[mi][ni][1], h, l);
            store_m2(M2, bb, Rn, rb + Cr, h, l);
            split2(e[mi][ni][2], e[mi][ni][3], h, l);
            store_m2(M2, bb, Rn + 8, rb + Cr, h, l);
        }
    }
}

// ---------------------------------------------------------------------------
// Big GEMM: BM=256, 512 threads, 1 CTA/SM, cp.async.bulk, KCHUNK=64,
// 3-stage full/empty mbarrier pipeline (16 chunks, prefetch depth 2).
// FUSEP: fuse final projection into the epilogue (t never hits gmem).
// ---------------------------------------------------------------------------
#define BMA      256
#define STG      65536                 // 32KB A + 32KB B per 64-k chunk
#define NSTG     3
#define NCHUNK   16
#define TBYTES   135168                // 256 rows x 528B (fp32 staging / t-bf16 tile)
#define WOFF     TBYTES                // proj weight tile at +135168 (67584 B)
#define MBAR_OFF 202752
#define AGG_SMEM 202880

template<bool FUSEP>
__global__ void __launch_bounds__(512, 1) agg_mma(
    const uint8_t* __restrict__ AT, const uint8_t* __restrict__ BT,
    const float* __restrict__ M, const float* __restrict__ bagg,
    float* __restrict__ T,
    const uint16_t* __restrict__ WHg, const uint16_t* __restrict__ WLg,
    const float* __restrict__ bp, const float* __restrict__ mask,
    float* __restrict__ out)
{
    extern __shared__ char smem[];
    const uint32_t sb = smem_u32(smem);
    const uint32_t mb_full  = sb + MBAR_OFF;            // 3 x 8B
    const uint32_t mb_empty = sb + MBAR_OFF + 24;       // 3 x 8B
    const int tid  = threadIdx.x;
    const int lane = tid & 31;
    const int wid  = tid >> 5;          // 0..15
    const int b    = blockIdx.y;
    const int mt   = blockIdx.x;
    const int row0 = mt * BMA;
    const int wm   = wid & 3;
    const int wn   = wid >> 2;

    const uint8_t* gA = AT + ((size_t)(b * 4 + mt) * 32) * 16384;
    const uint8_t* gB = BT + ((size_t)b * 32) * 16384;

    if (tid == 0) {
        #pragma unroll
        for (int s = 0; s < NSTG; s++) {
            MBAR_INIT(mb_full + s * 8, 1);
            MBAR_INIT(mb_empty + s * 8, 16);
        }
        FENCE_ASYNC();
    }
    __syncthreads();

    auto issue = [&](int c) {
        int s = c % NSTG;
        MBAR_EXPECT_TX(mb_full + s * 8, 65536u);
        BULK(sb + (uint32_t)s * STG,         gA + (size_t)c * 32768, 32768u, mb_full + s * 8);
        BULK(sb + (uint32_t)s * STG + 32768, gB + (size_t)c * 32768, 32768u, mb_full + s * 8);
    };

    if (tid == 0) { issue(0); issue(1); }

    float d[4][4][4];
    #pragma unroll
    for (int i = 0; i < 4; i++)
        #pragma unroll
        for (int j = 0; j < 4; j++)
            #pragma unroll
            for (int q = 0; q < 4; q++) d[i][j][q] = 0.f;

    const int lg = lane >> 3, lr = lane & 7;
    const int rbase = wm * 64 + (lg & 1) * 8 + lr;
    const uint32_t swzA = (uint32_t)((rbase >> 1) & 3);
    const int nbase = wn * 32 + lr;
    const uint32_t swzB = (uint32_t)(nbase & 7);
    const uint32_t u3base = (uint32_t)((lg >> 1) * 4 + (lg & 1));

    int phf[NSTG] = {0, 0, 0};
    int phe[NSTG] = {0, 0, 0};

    for (int c = 0; c < NCHUNK; c++) {
        int s = c % NSTG;

        if (tid == 0) {
            int cn = c + 2;
            if (cn < NCHUNK) {
                int sn = cn % NSTG;
                if (cn >= NSTG) { MBAR_WAIT(mb_empty + sn * 8, phe[sn]); phe[sn] ^= 1; }
                issue(cn);
            }
        }

        MBAR_WAIT(mb_full + s * 8, phf[s]);
        phf[s] ^= 1;

        #pragma unroll
        for (int ks2 = 0; ks2 < 2; ks2++) {
            uint32_t aBase = sb + (uint32_t)s * STG + (uint32_t)ks2 * 16384;
            uint32_t bBase = sb + (uint32_t)s * STG + 32768 + (uint32_t)ks2 * 16384;
            #pragma unroll
            for (int ks = 0; ks < 2; ks++) {
                uint32_t bh[4][2], bl[4][2];
                const uint32_t ub = ((u3base + ks * 2) ^ swzB) * 16;
                #pragma unroll
                for (int ni = 0; ni < 4; ni++)
                    LDSM4(bh[ni][0], bh[ni][1], bl[ni][0], bl[ni][1],
                          bBase + (uint32_t)(nbase + ni * 8) * 128 + ub);
                const uint32_t ua = (((uint32_t)(ks * 2 + (lg >> 1))) ^ swzA) * 16;
                #pragma unroll
                for (int mi = 0; mi < 4; mi++) {
                    uint32_t ah[4];
                    LDSM4(ah[0], ah[1], ah[2], ah[3],
                          aBase + (uint32_t)(rbase + mi * 16) * 64 + ua);
                    #pragma unroll
                    for (int ni = 0; ni < 4; ni++) {
                        mma_bf16(d[mi][ni], ah, bh[ni][0], bh[ni][1]);
                        mma_bf16(d[mi][ni], ah, bl[ni][0], bl[ni][1]);
                    }
                }
            }
        }

        if (lane == 0) MBAR_ARRIVE(mb_empty + s * 8);
    }
    __syncthreads();                    // all warps done; safe to reuse smem

    // stage D to smem (f32, pitch 132 floats = 528 B, 256 rows)
    float* stg = (float*)smem;
    #pragma unroll
    for (int mi = 0; mi < 4; mi++) {
        int R = wm * 64 + mi * 16 + (lane >> 2);
        #pragma unroll
        for (int ni = 0; ni < 4; ni++) {
            int C = wn * 32 + ni * 8 + (lane & 3) * 2;
            *(float2*)&stg[R * 132 + C]       = make_float2(d[mi][ni][0], d[mi][ni][1]);
            *(float2*)&stg[(R + 8) * 132 + C] = make_float2(d[mi][ni][2], d[mi][ni][3]);
        }
    }
    __syncthreads();

    if (FUSEP && tid < 256) cpw(WHg, WLg, 5, sb + WOFF, tid);   // prefetch Wproj
    if (FUSEP) CP_COMMIT();

    const float* Mb = M + ((size_t)b * NN + row0) * DD;
    float4 bg = *(const float4*)&bagg[lane * 4];
    #pragma unroll
    for (int i = 0; i < 16; i++) {
        int rr = wid * 16 + i;
        float4 raw = *(const float4*)&stg[rr * 132 + lane * 4];
        float4 mm  = *(const float4*)&Mb[(size_t)rr * DD + lane * 4];
        float v0 = fmaxf(raw.x + mm.x + bg.x, 0.f);
        float v1 = fmaxf(raw.y + mm.y + bg.y, 0.f);
        float v2 = fmaxf(raw.z + mm.z + bg.z, 0.f);
        float v3 = fmaxf(raw.w + mm.w + bg.w, 0.f);
        float ss = v0*v0 + v1*v1 + v2*v2 + v3*v3;
        #pragma unroll
        for (int o = 16; o > 0; o >>= 1)
            ss += __shfl_xor_sync(0xffffffffu, ss, o);
        float s = hyp_scale(sqrtf(ss));
        v0 *= s; v1 *= s; v2 *= s; v3 *= s;
        if (!FUSEP) {
            float* Tb = T + ((size_t)b * NN + row0) * DD;
            *(float4*)&Tb[(size_t)rr * DD + lane * 4] = make_float4(v0, v1, v2, v3);
        } else {
            // in-place resplit: whole row read by this warp before writes
            __syncwarp();
            uint32_t h0, l0, h1, l1;
            split2(v0, v1, h0, l0);
            split2(v2, v3, h1, l1);
            *(uint2*)(smem + rr * PW + lane * 8)       = make_uint2(h0, h1);
            *(uint2*)(smem + rr * PW + 256 + lane * 8) = make_uint2(l0, l1);
        }
    }

    if (FUSEP) {
        CPWAIT(0);
        __syncthreads();
        // proj GEMM: out = (t @ WprojT + bp) * mask;  A = t tile (256 rows)
        float e[4][4][4];
        #pragma unroll
        for (int i = 0; i < 4; i++)
            #pragma unroll
            for (int j = 0; j < 4; j++)
                #pragma unroll
                for (int q = 0; q < 4; q++) e[i][j][q] = 0.f;
        mma_blk<PW, 256, 8, 4>(sb, sb + WOFF, wm, wn, lane, e);

        #pragma unroll
        for (int mi = 0; mi < 4; mi++) {
            int R = wm * 64 + mi * 16 + (lane >> 2);
            float mk0 = mask[(size_t)b * NN + row0 + R];
            float mk1 = mask[(size_t)b * NN + row0 + R + 8];
            #pragma unroll
            for (int ni = 0; ni < 4; ni++) {
                int C = wn * 32 + ni * 8 + (lane & 3) * 2;
                float b0 = bp[C], b1 = bp[C + 1];
                size_t o0 = ((size_t)b * NN + row0 + R) * DD + C;
                *(float2*)&out[o0] =
                    make_float2((e[mi][ni][0] + b0) * mk0, (e[mi][ni][1] + b1) * mk0);
                *(float2*)&out[o0 + 8 * DD] =
                    make_float2((e[mi][ni][2] + b0) * mk1, (e[mi][ni][3] + b1) * mk1);
            }
        }
    }
}

// ---------------------------------------------------------------------------
// Host launch
// ---------------------------------------------------------------------------
extern "C" void kernel_launch(void* const* d_in, const int* in_sizes, int n_in,
                              void* d_out, int out_size)
{
    const float* nf    = (const float*)d_in[0];
    const float* adj   = (const float*)d_in[1];
    const float* mask  = (const float*)d_in[2];
    const float* Wemb  = (const float*)d_in[3];
    const float* Wmsg  = (const float*)d_in[4];
    const float* bmsg  = (const float*)d_in[5];
    const float* Wagg  = (const float*)d_in[6];
    const float* bagg  = (const float*)d_in[7];
    const float* Wproj = (const float*)d_in[8];
    const float* bproj = (const float*)d_in[9];
    float* out = (float*)d_out;

    float *t, *m;
    uint8_t *aht, *m2t;
    uint16_t *wh, *wl;
    cudaGetSymbolAddress((void**)&t,   g_t);
    cudaGetSymbolAddress((void**)&m,   g_m);
    cudaGetSymbolAddress((void**)&aht, g_aht);
    cudaGetSymbolAddress((void**)&m2t, g_m2t);
    cudaGetSymbolAddress((void**)&wh,  g_wh);
    cudaGetSymbolAddress((void**)&wl,  g_wl);

    cudaFuncSetAttribute(agg_mma<false>, cudaFuncAttributeMaxDynamicSharedMemorySize, AGG_SMEM);
    cudaFuncSetAttribute(agg_mma<true>,  cudaFuncAttributeMaxDynamicSharedMemorySize, AGG_SMEM);
    cudaFuncSetAttribute(chain_kernel<true>,  cudaFuncAttributeMaxDynamicSharedMemorySize, LIN_SMEM);
    cudaFuncSetAttribute(chain_kernel<false>, cudaFuncAttributeMaxDynamicSharedMemorySize, LIN_SMEM);

    dim3 glin(ROWS / 64);          // 512
    dim3 gbig(NN / BMA, BATCH);    // 4 x 32 = 128

    split_adj<<<(BATCH * NN * (NN / 8)) / 256, 256>>>(adj, aht);
    split_weights<<<6, 256>>>(Wemb, Wmsg, Wagg, Wproj, wh, wl);

    // layer 0: embed + hyp + msg + m2 fused
    chain_kernel<true><<<glin, 256, LIN_SMEM>>>(nf, wh, wl, 0, 1, 2,
                                                bmsg, m, m2t);
    agg_mma<false><<<gbig, 512, AGG_SMEM>>>(aht, m2t, m, bagg, t,
                                            nullptr, nullptr, nullptr, nullptr, nullptr);

    // layer 1: msg + m2 fused; agg2 fuses the final projection (t stays in smem)
    chain_kernel<false><<<glin, 256, LIN_SMEM>>>(t, wh, wl, 0, 3, 4,
                                                 bmsg + DD, m, m2t);
    agg_mma<true><<<gbig, 512, AGG_SMEM>>>(aht, m2t, m, bagg + DD, nullptr,
                                           wh, wl, bproj, mask, out);
}